// round 8
// baseline (speedup 1.0000x reference)
#include <cuda_runtime.h>
#include <cuda_bf16.h>
#include <math.h>
#include <stdint.h>

#define B_    2
#define S_    2048
#define E_    4096
#define H_    32
#define KVH_  8
#define D_    128
#define HD_   (H_*D_)      // 4096
#define KVHD_ (KVH_*D_)    // 1024
#define M_    (B_*S_)      // 4096

// ---------------- scratch (no allocations allowed) ----------------
__device__ float g_cos [S_*(D_/2)];
__device__ float g_sin [S_*(D_/2)];

// bf16 hi/lo operands, 8x8-blocked layout: [R/8][C/8][8][8] (128B per block)
__device__ __align__(16) __nv_bfloat16 g_hid_hi [(size_t)M_*E_];
__device__ __align__(16) __nv_bfloat16 g_hid_lo [(size_t)M_*E_];
__device__ __align__(16) __nv_bfloat16 g_wq_hi  [(size_t)HD_*E_];
__device__ __align__(16) __nv_bfloat16 g_wq_lo  [(size_t)HD_*E_];
__device__ __align__(16) __nv_bfloat16 g_wk_hi  [(size_t)KVHD_*E_];
__device__ __align__(16) __nv_bfloat16 g_wk_lo  [(size_t)KVHD_*E_];
__device__ __align__(16) __nv_bfloat16 g_wv_hi  [(size_t)KVHD_*E_];
__device__ __align__(16) __nv_bfloat16 g_wv_lo  [(size_t)KVHD_*E_];
__device__ __align__(16) __nv_bfloat16 g_wo_hi  [(size_t)E_*HD_];
__device__ __align__(16) __nv_bfloat16 g_wo_lo  [(size_t)E_*HD_];
__device__ __align__(16) __nv_bfloat16 g_attn_hi[(size_t)M_*HD_];
__device__ __align__(16) __nv_bfloat16 g_attn_lo[(size_t)M_*HD_];

// pre-blocked attention operands (tile layouts match flash smem exactly)
__device__ __align__(16) __nv_bfloat16 g_qb_hi[(size_t)B_*H_*S_*D_];
__device__ __align__(16) __nv_bfloat16 g_qb_lo[(size_t)B_*H_*S_*D_];
__device__ __align__(16) __nv_bfloat16 g_kb_hi[(size_t)B_*KVH_*S_*D_];
__device__ __align__(16) __nv_bfloat16 g_kb_lo[(size_t)B_*KVH_*S_*D_];
__device__ __align__(16) __nv_bfloat16 g_vb_hi[(size_t)B_*KVH_*S_*D_];
__device__ __align__(16) __nv_bfloat16 g_vb_lo[(size_t)B_*KVH_*S_*D_];

// ---------------- helpers ----------------
__device__ __forceinline__ uint32_t smem_u32(const void* p) {
    uint32_t a;
    asm("{ .reg .u64 t; cvta.to.shared.u64 t, %1; cvt.u32.u64 %0, t; }" : "=r"(a) : "l"(p));
    return a;
}
__device__ __forceinline__ void ldsm_x4(uint32_t* r, uint32_t a) {
    asm volatile("ldmatrix.sync.aligned.m8n8.x4.shared.b16 {%0,%1,%2,%3}, [%4];"
                 : "=r"(r[0]), "=r"(r[1]), "=r"(r[2]), "=r"(r[3]) : "r"(a));
}
__device__ __forceinline__ void mma_bf16(float* c, const uint32_t* a, const uint32_t* b) {
    asm volatile("mma.sync.aligned.m16n8k16.row.col.f32.bf16.bf16.f32 "
                 "{%0,%1,%2,%3}, {%4,%5,%6,%7}, {%8,%9}, {%0,%1,%2,%3};"
                 : "+f"(c[0]), "+f"(c[1]), "+f"(c[2]), "+f"(c[3])
                 : "r"(a[0]), "r"(a[1]), "r"(a[2]), "r"(a[3]), "r"(b[0]), "r"(b[1]));
}
__device__ __forceinline__ void cp16(uint32_t saddr, const void* g) {
    asm volatile("cp.async.cg.shared.global [%0], [%1], 16;" :: "r"(saddr), "l"(g) : "memory");
}
__device__ __forceinline__ uint32_t pack_bf16_split(float x0, float x1,
                                                    uint32_t& lo_out) {
    __nv_bfloat16 h0 = __float2bfloat16_rn(x0);
    __nv_bfloat16 h1 = __float2bfloat16_rn(x1);
    __nv_bfloat16 l0 = __float2bfloat16_rn(x0 - __bfloat162float(h0));
    __nv_bfloat16 l1 = __float2bfloat16_rn(x1 - __bfloat162float(h1));
    __nv_bfloat162 hp = __halves2bfloat162(h0, h1);
    __nv_bfloat162 lp = __halves2bfloat162(l0, l1);
    lo_out = *reinterpret_cast<uint32_t*>(&lp);
    return *reinterpret_cast<uint32_t*>(&hp);
}

// ---------------- RoPE tables ----------------
__global__ void rope_table_kernel() {
    int idx = blockIdx.x * blockDim.x + threadIdx.x;
    if (idx >= S_*(D_/2)) return;
    int t = idx / (D_/2);
    int i = idx % (D_/2);
    double inv = exp(-((double)(2*i) / (double)D_) * log(10000.0));
    double ang = (double)t * inv;
    g_cos[idx] = (float)cos(ang);
    g_sin[idx] = (float)sin(ang);
}

// ---------------- split fp32 [Mr,Kc] -> blocked bf16 hi/lo ----------------
__global__ void split_blocked_kernel(const float* __restrict__ X,
                                     __nv_bfloat16* __restrict__ Hi,
                                     __nv_bfloat16* __restrict__ Lo,
                                     int Mr, int Kc) {
    int idx = blockIdx.x * blockDim.x + threadIdx.x;
    int KB = Kc >> 3;
    if (idx >= Mr * KB) return;
    int row = idx / KB, kb = idx % KB;
    const float* src = X + (size_t)row * Kc + kb * 8;
    float4 v0 = *(const float4*)src;
    float4 v1 = *(const float4*)(src + 4);
    float xs[8] = {v0.x, v0.y, v0.z, v0.w, v1.x, v1.y, v1.z, v1.w};
    uint32_t hw[4], lw[4];
    #pragma unroll
    for (int j = 0; j < 4; j++)
        hw[j] = pack_bf16_split(xs[2*j], xs[2*j+1], lw[j]);
    size_t off = (((size_t)(row >> 3) * KB + kb) << 6) + (size_t)(row & 7) * 8;
    *(uint4*)(Hi + off) = make_uint4(hw[0], hw[1], hw[2], hw[3]);
    *(uint4*)(Lo + off) = make_uint4(lw[0], lw[1], lw[2], lw[3]);
}

// ---------------- transpose+split: W[K,N] fp32 -> blocked BT hi/lo [N,K] ----------------
__global__ void wtrans_split_kernel(const float* __restrict__ W,
                                    __nv_bfloat16* __restrict__ Thi,
                                    __nv_bfloat16* __restrict__ Tlo,
                                    int Kdim, int Ndim) {
    __shared__ float tile[32][33];
    int n0 = blockIdx.x * 32, k0 = blockIdx.y * 32;
    int tx = threadIdx.x, ty = threadIdx.y;  // (32, 8)
    #pragma unroll
    for (int dy = 0; dy < 32; dy += 8)
        tile[ty + dy][tx] = W[(size_t)(k0 + ty + dy) * Ndim + n0 + tx];
    __syncthreads();
    int KB = Kdim >> 3;
    #pragma unroll
    for (int dy = 0; dy < 32; dy += 8) {
        int n = n0 + ty + dy, k = k0 + tx;
        float x = tile[tx][ty + dy];
        __nv_bfloat16 h = __float2bfloat16_rn(x);
        __nv_bfloat16 l = __float2bfloat16_rn(x - __bfloat162float(h));
        size_t off = (((size_t)(n >> 3) * KB + (k >> 3)) << 6) + (size_t)(n & 7) * 8 + (k & 7);
        Thi[off] = h;
        Tlo[off] = l;
    }
}

// ---------------- 3xBF16 mma.sync GEMM (128x128 tile, k-chunk 64) ----------------
// MODE 0: plain fp32 output (+optional bias)
// MODE 1: fused bias + RoPE + split -> g_qb blocked   (N-tile == one Q head)
// MODE 2: fused bias + RoPE + split -> g_kb blocked   (N-tile == one KV head)
// MODE 3: fused bias + transpose + split -> g_vb blocked
template<int MODE>
__global__ __launch_bounds__(256, 1)
void bf16x3_gemm_kernel(const __nv_bfloat16* __restrict__ Ahi, const __nv_bfloat16* __restrict__ Alo,
                        const __nv_bfloat16* __restrict__ Bhi, const __nv_bfloat16* __restrict__ Blo,
                        const float* __restrict__ bias, float* __restrict__ C,
                        const int* __restrict__ pos,
                        __nv_bfloat16* __restrict__ outHi, __nv_bfloat16* __restrict__ outLo,
                        int Mdim, int Ndim, int Kdim) {
    extern __shared__ char smc[];
    const uint32_t sbase = smem_u32(smc);
    const int tid  = threadIdx.x;
    const int warp = tid >> 5, lane = tid & 31;
    const int KB   = Kdim >> 3;
    const int mb0  = blockIdx.y * 16;
    const int nb0  = blockIdx.x * 16;
    const int NC   = Kdim >> 6;

    float acc[4][4][4];
    #pragma unroll
    for (int t = 0; t < 4; t++)
        #pragma unroll
        for (int u = 0; u < 4; u++)
            #pragma unroll
            for (int j = 0; j < 4; j++) acc[t][u][j] = 0.f;

    const char* pAhi = (const char*)Ahi;
    const char* pAlo = (const char*)Alo;
    const char* pBhi = (const char*)Bhi;
    const char* pBlo = (const char*)Blo;

    auto prefetch = [&](int chunk, int st) {
        uint32_t sbuf = sbase + (uint32_t)st * 65536u;
        int kb0 = chunk << 3;
        #pragma unroll
        for (int j = 0; j < 4; j++) {
            int u = tid + j * 256;
            int rb = u >> 6, kb = (u >> 3) & 7, w = u & 7;
            size_t gA = ((size_t)(mb0 + rb) * KB + (kb0 + kb)) * 128u + (size_t)w * 16u;
            size_t gB = ((size_t)(nb0 + rb) * KB + (kb0 + kb)) * 128u + (size_t)w * 16u;
            uint32_t so = (uint32_t)(((rb * 8 + kb) * 8 + w) * 16);
            cp16(sbuf + so,           pAhi + gA);
            cp16(sbuf + 16384u + so,  pAlo + gA);
            cp16(sbuf + 32768u + so,  pBhi + gB);
            cp16(sbuf + 49152u + so,  pBlo + gB);
        }
    };

    const int wmb   = (warp >> 2) * 8;
    const int wnb   = (warp & 3) * 4;
    const int selAm = (lane >> 3) & 1;
    const int selAk = (lane >> 3) >> 1;
    const int selBn = (lane >> 4) & 1;
    const int selBk = (lane >> 3) & 1;
    const int rrow  = lane & 7;

    prefetch(0, 0);
    asm volatile("cp.async.commit_group;" ::: "memory");

    for (int i = 0; i < NC; i++) {
        asm volatile("cp.async.wait_group 0;" ::: "memory");
        __syncthreads();      // also orders: all warps done reading the stage being overwritten
        if (i + 1 < NC) {
            prefetch(i + 1, (i + 1) & 1);
            asm volatile("cp.async.commit_group;" ::: "memory");
        }
        uint32_t sbuf = sbase + (uint32_t)(i & 1) * 65536u;
        #pragma unroll
        for (int ks = 0; ks < 4; ks++) {
            uint32_t ahi[4][4], alo[4][4], bhi[2][4], blo[2][4];
            #pragma unroll
            for (int t = 0; t < 4; t++) {
                int mbb = wmb + 2*t + selAm;
                int kbb = 2*ks + selAk;
                uint32_t off = (uint32_t)((mbb * 8 + kbb) * 128 + rrow * 16);
                ldsm_x4(ahi[t], sbuf + off);
                ldsm_x4(alo[t], sbuf + 16384u + off);
            }
            #pragma unroll
            for (int u2 = 0; u2 < 2; u2++) {
                int nbb = wnb + 2*u2 + selBn;
                int kbb = 2*ks + selBk;
                uint32_t off = (uint32_t)((nbb * 8 + kbb) * 128 + rrow * 16);
                ldsm_x4(bhi[u2], sbuf + 32768u + off);
                ldsm_x4(blo[u2], sbuf + 49152u + off);
            }
            #pragma unroll
            for (int t = 0; t < 4; t++)
                #pragma unroll
                for (int u = 0; u < 4; u++) {
                    const uint32_t* bh = &bhi[u >> 1][(u & 1) * 2];
                    const uint32_t* bl = &blo[u >> 1][(u & 1) * 2];
                    mma_bf16(acc[t][u], ahi[t], bh);
                    mma_bf16(acc[t][u], alo[t], bh);
                    mma_bf16(acc[t][u], ahi[t], bl);
                }
        }
    }

    const int mrow = mb0 * 8 + (warp >> 2) * 64;
    const int ncol = nb0 * 8 + (warp & 3) * 32;
    const int gg = lane >> 2, qq = lane & 3;

    if (MODE == 0) {
        #pragma unroll
        for (int t = 0; t < 4; t++) {
            #pragma unroll
            for (int u = 0; u < 4; u++) {
                int row = mrow + t * 16 + gg;
                int col = ncol + u * 8 + qq * 2;
                float2 b2 = make_float2(0.f, 0.f);
                if (bias) b2 = *(const float2*)(bias + col);
                float2 v0 = make_float2(acc[t][u][0] + b2.x, acc[t][u][1] + b2.y);
                float2 v1 = make_float2(acc[t][u][2] + b2.x, acc[t][u][3] + b2.y);
                *(float2*)(C + (size_t)row * Ndim + col)       = v0;
                *(float2*)(C + (size_t)(row + 8) * Ndim + col) = v1;
            }
        }
        return;
    }

    // ---- fused epilogues: stage acc+bias to smem fp32 [128 rows][132 pitch] ----
    float* st = (float*)smc;
    __syncthreads();   // all warps done with stage smem (ldsm reads) before overwrite
    {
        const int lrow = (warp >> 2) * 64;          // local row base within tile
        const int lcol = (warp & 3) * 32;
        #pragma unroll
        for (int t = 0; t < 4; t++) {
            #pragma unroll
            for (int u = 0; u < 4; u++) {
                int r = lrow + t * 16 + gg;
                int c = lcol + u * 8 + qq * 2;
                float2 b2 = *(const float2*)(bias + nb0 * 8 + c);
                st[r * 132 + c]           = acc[t][u][0] + b2.x;
                st[r * 132 + c + 1]       = acc[t][u][1] + b2.y;
                st[(r + 8) * 132 + c]     = acc[t][u][2] + b2.x;
                st[(r + 8) * 132 + c + 1] = acc[t][u][3] + b2.y;
            }
        }
    }
    __syncthreads();

    if (MODE == 1 || MODE == 2) {
        // RoPE + split; N-tile = one head (h = blockIdx.x)
        const int hh = blockIdx.x;
        #pragma unroll
        for (int j = 0; j < 4; j++) {
            int idx = tid + j * 256;          // 0..1023
            int kbl = idx & 7;                // lower kb (cols i0..i0+7)
            int r   = idx >> 3;               // 0..127
            int token = blockIdx.y * 128 + r;
            int b = token >> 11;
            int s = token & (S_ - 1);
            int p = pos[b * S_ + s];
            int i0 = kbl * 8;
            float y1[8], y2[8];
            #pragma unroll
            for (int jj = 0; jj < 8; jj++) {
                float x1 = st[r * 132 + i0 + jj];
                float x2 = st[r * 132 + 64 + i0 + jj];
                float c  = g_cos[p * 64 + i0 + jj];
                float sn = g_sin[p * 64 + i0 + jj];
                y1[jj] = x1 * c - x2 * sn;
                y2[jj] = x2 * c + x1 * sn;
            }
            uint32_t h1[4], l1[4], h2[4], l2[4];
            #pragma unroll
            for (int jj = 0; jj < 4; jj++) {
                h1[jj] = pack_bf16_split(y1[2*jj], y1[2*jj+1], l1[jj]);
                h2[jj] = pack_bf16_split(y2[2*jj], y2[2*jj+1], l2[jj]);
            }
            size_t dbase;
            if (MODE == 1) {
                int qt = s >> 7, sbw = (s >> 3) & 15;
                dbase = ((((size_t)(b * H_ + hh) * (S_/128) + qt) * 16 + sbw) * 16);
            } else {
                int kt = s >> 6, sbw = (s >> 3) & 7;
                dbase = ((((size_t)(b * KVH_ + hh) * (S_/64) + kt) * 8 + sbw) * 16);
            }
            int rr = s & 7;
            size_t o1 = (dbase + kbl)     * 64 + (size_t)rr * 8;
            size_t o2 = (dbase + kbl + 8) * 64 + (size_t)rr * 8;
            *(uint4*)(outHi + o1) = make_uint4(h1[0], h1[1], h1[2], h1[3]);
            *(uint4*)(outLo + o1) = make_uint4(l1[0], l1[1], l1[2], l1[3]);
            *(uint4*)(outHi + o2) = make_uint4(h2[0], h2[1], h2[2], h2[3]);
            *(uint4*)(outLo + o2) = make_uint4(l2[0], l2[1], l2[2], l2[3]);
        }
    } else {
        // MODE 3: V transpose + split; rows=s (128 = 2 kt-tiles), cols=d (head kvh)
        const int kvh = blockIdx.x;
        const int token0 = blockIdx.y * 128;
        const int b = token0 >> 11;
        const int sbase0 = token0 & (S_ - 1);
        #pragma unroll
        for (int j = 0; j < 8; j++) {
            int idx = tid + j * 256;          // 0..2047
            int dr  = idx & 7;
            int sbw = (idx >> 3) & 7;
            int db  = (idx >> 6) & 15;
            int ktl = idx >> 10;              // 0..1
            int d = db * 8 + dr;
            int sl = ktl * 64 + sbw * 8;      // local s
            uint32_t hw[4], lw[4];
            #pragma unroll
            for (int jj = 0; jj < 4; jj++) {
                float x0 = st[(sl + 2*jj)     * 132 + d];
                float x1 = st[(sl + 2*jj + 1) * 132 + d];
                hw[jj] = pack_bf16_split(x0, x1, lw[jj]);
            }
            int s = sbase0 + sl;
            int kt = s >> 6;
            size_t off = (((((size_t)(b * KVH_ + kvh) * (S_/64) + kt) * 16 + db) * 8 + sbw) * 64)
                       + (size_t)dr * 8;
            *(uint4*)(outHi + off) = make_uint4(hw[0], hw[1], hw[2], hw[3]);
            *(uint4*)(outLo + off) = make_uint4(lw[0], lw[1], lw[2], lw[3]);
        }
    }
}

// ---------------- mma flash attention (causal, GQA 4:1), register softmax ----------------
#define FQHI  0u
#define FQLO  32768u
#define FKHI  65536u
#define FKLO  81920u
#define FVHI  98304u
#define FVLO  114688u
#define FPBH  131072u     // P hi blocked [16 mb][8 kb]
#define FPBL  147456u
#define FMS   163840u     // float[128]
#define FLS   164352u
#define FALS  164864u
#define FPART 165376u     // float[128][2]
#define FTOT  166400u

__global__ __launch_bounds__(256, 1)
void flash_mma_kernel() {
    extern __shared__ char fs[];
    const uint32_t sb = smem_u32(fs);
    float* m_s  = (float*)(fs + FMS);
    float* l_s  = (float*)(fs + FLS);
    float* al_s = (float*)(fs + FALS);
    float* part = (float*)(fs + FPART);

    const int tid  = threadIdx.x;
    const int warp = tid >> 5, lane = tid & 31;
    const int qt = blockIdx.x, h = blockIdx.y, b = blockIdx.z;
    const int q0 = qt * 128;
    const int kvh = h >> 2;
    const float scale = 0.08838834764831845f;

    const int selAm = (lane >> 3) & 1;
    const int selAk = (lane >> 3) >> 1;
    const int selBn = (lane >> 4) & 1;
    const int selBk = (lane >> 3) & 1;
    const int rrow  = lane & 7;
    const int gr = lane >> 2, qq = lane & 3;

    {
        const char* qh = (const char*)(g_qb_hi + (((size_t)(b*H_ + h) * (S_/128) + qt) << 14));
        const char* ql = (const char*)(g_qb_lo + (((size_t)(b*H_ + h) * (S_/128) + qt) << 14));
        #pragma unroll
        for (int j = 0; j < 8; j++) {
            uint32_t u = (uint32_t)(tid + j * 256) * 16u;
            cp16(sb + FQHI + u, qh + u);
            cp16(sb + FQLO + u, ql + u);
        }
        asm volatile("cp.async.commit_group;" ::: "memory");
    }
    if (tid < 128) { m_s[tid] = -1e30f; l_s[tid] = 0.f; }

    const int pwm = (warp >> 2) * 64;
    const int pwn = (warp & 3) * 32;
    float acc[4][4][4];
    #pragma unroll
    for (int t = 0; t < 4; t++)
        #pragma unroll
        for (int u = 0; u < 4; u++)
            #pragma unroll
            for (int j = 0; j < 4; j++) acc[t][u][j] = 0.f;

    const int wm = (warp >> 1) * 32;
    const int wn = (warp & 1) * 32;
    const int wcol = warp & 1;

    const int NK = 2 * qt + 2;
    for (int kt = 0; kt < NK; kt++) {
        const int k0 = kt * 64;
        __syncthreads();

        {
            size_t tb = ((size_t)(b*KVH_ + kvh) * (S_/64) + kt) << 13;
            const char* kh = (const char*)(g_kb_hi + tb);
            const char* kl = (const char*)(g_kb_lo + tb);
            const char* vh = (const char*)(g_vb_hi + tb);
            const char* vl = (const char*)(g_vb_lo + tb);
            #pragma unroll
            for (int j = 0; j < 4; j++) {
                uint32_t u = (uint32_t)(tid + j * 256) * 16u;
                cp16(sb + FKHI + u, kh + u);
                cp16(sb + FKLO + u, kl + u);
                cp16(sb + FVHI + u, vh + u);
                cp16(sb + FVLO + u, vl + u);
            }
            asm volatile("cp.async.commit_group;" ::: "memory");
            asm volatile("cp.async.wait_group 0;" ::: "memory");
        }
        __syncthreads();

        // ---- S = Q @ K^T (3-split) ----
        float sacc[2][4][4];
        #pragma unroll
        for (int t = 0; t < 2; t++)
            #pragma unroll
            for (int u = 0; u < 4; u++)
                #pragma unroll
                for (int j = 0; j < 4; j++) sacc[t][u][j] = 0.f;

        #pragma unroll
        for (int ks = 0; ks < 8; ks++) {
            uint32_t qhi[2][4], qlo[2][4], khi[2][4], klo[2][4];
            #pragma unroll
            for (int t = 0; t < 2; t++) {
                int mbb = (wm >> 3) + 2*t + selAm;
                int kbb = 2*ks + selAk;
                uint32_t off = (uint32_t)((mbb * 16 + kbb) * 128 + rrow * 16);
                ldsm_x4(qhi[t], sb + FQHI + off);
                ldsm_x4(qlo[t], sb + FQLO + off);
            }
            #pragma unroll
            for (int u2 = 0; u2 < 2; u2++) {
                int nbb = (wn >> 3) + 2*u2 + selBn;
                int kbb = 2*ks + selBk;
                uint32_t off = (uint32_t)((nbb * 16 + kbb) * 128 + rrow * 16);
                ldsm_x4(khi[u2], sb + FKHI + off);
                ldsm_x4(klo[u2], sb + FKLO + off);
            }
            #pragma unroll
            for (int t = 0; t < 2; t++)
                #pragma unroll
                for (int u = 0; u < 4; u++) {
                    const uint32_t* kh = &khi[u >> 1][(u & 1) * 2];
                    const uint32_t* kl = &klo[u >> 1][(u & 1) * 2];
                    mma_bf16(sacc[t][u], qhi[t], kh);
                    mma_bf16(sacc[t][u], qlo[t], kh);
                    mma_bf16(sacc[t][u], qhi[t], kl);
                }
        }

        // ---- register softmax: scale + mask + quad row-max ----
        const bool needmask = (kt >= 2 * qt);
        #pragma unroll
        for (int t = 0; t < 2; t++) {
            int r1 = wm + t * 16 + gr;
            float m1 = -1e30f, m2 = -1e30f;
            #pragma unroll
            for (int u = 0; u < 4; u++) {
                int c0 = wn + u * 8 + qq * 2;
                float s0 = sacc[t][u][0] * scale;
                float s1 = sacc[t][u][1] * scale;
                float s2 = sacc[t][u][2] * scale;
                float s3 = sacc[t][u][3] * scale;
                if (needmask) {
                    if (k0 + c0     > q0 + r1)     s0 = -1e30f;
                    if (k0 + c0 + 1 > q0 + r1)     s1 = -1e30f;
                    if (k0 + c0     > q0 + r1 + 8) s2 = -1e30f;
                    if (k0 + c0 + 1 > q0 + r1 + 8) s3 = -1e30f;
                }
                sacc[t][u][0] = s0; sacc[t][u][1] = s1;
                sacc[t][u][2] = s2; sacc[t][u][3] = s3;
                m1 = fmaxf(m1, fmaxf(s0, s1));
                m2 = fmaxf(m2, fmaxf(s2, s3));
            }
            m1 = fmaxf(m1, __shfl_xor_sync(0xffffffffu, m1, 1));
            m1 = fmaxf(m1, __shfl_xor_sync(0xffffffffu, m1, 2));
            m2 = fmaxf(m2, __shfl_xor_sync(0xffffffffu, m2, 1));
            m2 = fmaxf(m2, __shfl_xor_sync(0xffffffffu, m2, 2));
            if (qq == 0) {
                part[r1*2 + wcol]     = m1;
                part[(r1+8)*2 + wcol] = m2;
            }
        }
        __syncthreads();
        if (tid < 128) {
            float mx = fmaxf(part[tid*2], part[tid*2+1]);
            float mo = m_s[tid];
            float mn = fmaxf(mo, mx);
            m_s[tid]  = mn;
            al_s[tid] = __expf(mo - mn);
        }
        __syncthreads();

        // ---- exp in registers + quad row-sum + split P to blocked smem ----
        {
            __nv_bfloat16* ph = (__nv_bfloat16*)(fs + FPBH);
            __nv_bfloat16* pl = (__nv_bfloat16*)(fs + FPBL);
            #pragma unroll
            for (int t = 0; t < 2; t++) {
                int r1 = wm + t * 16 + gr;
                int r2 = r1 + 8;
                float mm1 = m_s[r1], mm2 = m_s[r2];
                float sum1 = 0.f, sum2 = 0.f;
                #pragma unroll
                for (int u = 0; u < 4; u++) {
                    float e0 = __expf(sacc[t][u][0] - mm1);
                    float e1 = __expf(sacc[t][u][1] - mm1);
                    float e2 = __expf(sacc[t][u][2] - mm2);
                    float e3 = __expf(sacc[t][u][3] - mm2);
                    sum1 += e0 + e1;
                    sum2 += e2 + e3;
                    int cb = (wn >> 3) + u;
                    uint32_t lo;
                    uint32_t hi = pack_bf16_split(e0, e1, lo);
                    uint32_t o1 = (uint32_t)((((r1 >> 3) * 8 + cb) << 6) + (r1 & 7) * 8 + qq * 2);
                    *(uint32_t*)(ph + o1) = hi;
                    *(uint32_t*)(pl + o1) = lo;
                    hi = pack_bf16_split(e2, e3, lo);
                    uint32_t o2 = (uint32_t)((((r2 >> 3) * 8 + cb) << 6) + (r2 & 7) * 8 + qq * 2);
                    *(uint32_t*)(ph + o2) = hi;
                    *(uint32_t*)(pl + o2) = lo;
                }
                sum1 += __shfl_xor_sync(0xffffffffu, sum1, 1);
                sum1 += __shfl_xor_sync(0xffffffffu, sum1, 2);
                sum2 += __shfl_xor_sync(0xffffffffu, sum2, 1);
                sum2 += __shfl_xor_sync(0xffffffffu, sum2, 2);
                if (qq == 0) {
                    part[r1*2 + wcol] = sum1;
                    part[r2*2 + wcol] = sum2;
                }
            }
        }
        __syncthreads();
        if (tid < 128) l_s[tid] = l_s[tid] * al_s[tid] + part[tid*2] + part[tid*2+1];

        // ---- rescale PV accumulators ----
        #pragma unroll
        for (int t = 0; t < 4; t++) {
            float a1 = al_s[pwm + t*16 + gr];
            float a2 = al_s[pwm + t*16 + gr + 8];
            #pragma unroll
            for (int u = 0; u < 4; u++) {
                acc[t][u][0] *= a1; acc[t][u][1] *= a1;
                acc[t][u][2] *= a2; acc[t][u][3] *= a2;
            }
        }

        // ---- O += P @ V (3-split) ----
        #pragma unroll
        for (int ks = 0; ks < 4; ks++) {
            uint32_t phiF[4][4], ploF[4][4], vhiF[2][4], vloF[2][4];
            #pragma unroll
            for (int t = 0; t < 4; t++) {
                int mbb = (pwm >> 3) + 2*t + selAm;
                int kbb = 2*ks + selAk;
                uint32_t off = (uint32_t)((mbb * 8 + kbb) * 128 + rrow * 16);
                ldsm_x4(phiF[t], sb + FPBH + off);
                ldsm_x4(ploF[t], sb + FPBL + off);
            }
            #pragma unroll
            for (int u2 = 0; u2 < 2; u2++) {
                int nbb = (pwn >> 3) + 2*u2 + selBn;
                int kbb = 2*ks + selBk;
                uint32_t off = (uint32_t)((nbb * 8 + kbb) * 128 + rrow * 16);
                ldsm_x4(vhiF[u2], sb + FVHI + off);
                ldsm_x4(vloF[u2], sb + FVLO + off);
            }
            #pragma unroll
            for (int t = 0; t < 4; t++)
                #pragma unroll
                for (int u = 0; u < 4; u++) {
                    const uint32_t* vh = &vhiF[u >> 1][(u & 1) * 2];
                    const uint32_t* vl = &vloF[u >> 1][(u & 1) * 2];
                    mma_bf16(acc[t][u], phiF[t], vh);
                    mma_bf16(acc[t][u], ploF[t], vh);
                    mma_bf16(acc[t][u], phiF[t], vl);
                }
        }
    }

    __syncthreads();

    // ---- epilogue: normalize + write blocked bf16 hi/lo ----
    {
        const int KB = HD_ >> 3;
        #pragma unroll
        for (int t = 0; t < 4; t++) {
            int r1 = pwm + t*16 + gr;
            float inv1 = 1.f / l_s[r1];
            float inv2 = 1.f / l_s[r1 + 8];
            int grow1 = b*S_ + q0 + r1;
            int grow2 = grow1 + 8;
            #pragma unroll
            for (int u = 0; u < 4; u++) {
                int col = h * D_ + pwn + u*8 + qq * 2;
                int kb = col >> 3, cw = col & 7;
                uint32_t lo1, lo2;
                uint32_t hi1 = pack_bf16_split(acc[t][u][0]*inv1, acc[t][u][1]*inv1, lo1);
                uint32_t hi2 = pack_bf16_split(acc[t][u][2]*inv2, acc[t][u][3]*inv2, lo2);
                size_t o1 = (((size_t)(grow1 >> 3) * KB + kb) << 6) + (size_t)(grow1 & 7) * 8 + cw;
                size_t o2 = (((size_t)(grow2 >> 3) * KB + kb) << 6) + (size_t)(grow2 & 7) * 8 + cw;
                *(uint32_t*)(g_attn_hi + o1) = hi1;
                *(uint32_t*)(g_attn_lo + o1) = lo1;
                *(uint32_t*)(g_attn_hi + o2) = hi2;
                *(uint32_t*)(g_attn_lo + o2) = lo2;
            }
        }
    }
}

// ---------------- launch ----------------
extern "C" void kernel_launch(void* const* d_in, const int* in_sizes, int n_in,
                              void* d_out, int out_size) {
    const float* hidden = (const float*)d_in[0];
    const int*   pos    = (const int*)  d_in[2];
    const float* Wq     = (const float*)d_in[3];
    const float* bq     = (const float*)d_in[4];
    const float* Wk     = (const float*)d_in[5];
    const float* bk     = (const float*)d_in[6];
    const float* Wv     = (const float*)d_in[7];
    const float* bv     = (const float*)d_in[8];
    const float* Wo     = (const float*)d_in[9];
    float* out = (float*)d_out;

    __nv_bfloat16 *hhi, *hlo, *wqh, *wql, *wkh, *wkl, *wvh, *wvl, *woh, *wol, *ahi, *alo;
    __nv_bfloat16 *qbh, *qbl, *kbh, *kbl2, *vbh, *vbl;
    cudaGetSymbolAddress((void**)&hhi, g_hid_hi);
    cudaGetSymbolAddress((void**)&hlo, g_hid_lo);
    cudaGetSymbolAddress((void**)&wqh, g_wq_hi);
    cudaGetSymbolAddress((void**)&wql, g_wq_lo);
    cudaGetSymbolAddress((void**)&wkh, g_wk_hi);
    cudaGetSymbolAddress((void**)&wkl, g_wk_lo);
    cudaGetSymbolAddress((void**)&wvh, g_wv_hi);
    cudaGetSymbolAddress((void**)&wvl, g_wv_lo);
    cudaGetSymbolAddress((void**)&woh, g_wo_hi);
    cudaGetSymbolAddress((void**)&wol, g_wo_lo);
    cudaGetSymbolAddress((void**)&ahi, g_attn_hi);
    cudaGetSymbolAddress((void**)&alo, g_attn_lo);
    cudaGetSymbolAddress((void**)&qbh, g_qb_hi);
    cudaGetSymbolAddress((void**)&qbl, g_qb_lo);
    cudaGetSymbolAddress((void**)&kbh, g_kb_hi);
    cudaGetSymbolAddress((void**)&kbl2, g_kb_lo);
    cudaGetSymbolAddress((void**)&vbh, g_vb_hi);
    cudaGetSymbolAddress((void**)&vbl, g_vb_lo);

    const size_t gsmem = 131072;
    cudaFuncSetAttribute(bf16x3_gemm_kernel<0>, cudaFuncAttributeMaxDynamicSharedMemorySize, (int)gsmem);
    cudaFuncSetAttribute(bf16x3_gemm_kernel<1>, cudaFuncAttributeMaxDynamicSharedMemorySize, (int)gsmem);
    cudaFuncSetAttribute(bf16x3_gemm_kernel<2>, cudaFuncAttributeMaxDynamicSharedMemorySize, (int)gsmem);
    cudaFuncSetAttribute(bf16x3_gemm_kernel<3>, cudaFuncAttributeMaxDynamicSharedMemorySize, (int)gsmem);
    cudaFuncSetAttribute(flash_mma_kernel, cudaFuncAttributeMaxDynamicSharedMemorySize, (int)FTOT);

    rope_table_kernel<<<(S_*(D_/2) + 255)/256, 256>>>();
    {
        int n = M_ * (E_ >> 3);
        split_blocked_kernel<<<(n + 255)/256, 256>>>(hidden, hhi, hlo, M_, E_);
    }
    wtrans_split_kernel<<<dim3(HD_/32,   E_/32), dim3(32,8)>>>(Wq, wqh, wql, E_,  HD_);
    wtrans_split_kernel<<<dim3(KVHD_/32, E_/32), dim3(32,8)>>>(Wk, wkh, wkl, E_,  KVHD_);
    wtrans_split_kernel<<<dim3(KVHD_/32, E_/32), dim3(32,8)>>>(Wv, wvh, wvl, E_,  KVHD_);

    bf16x3_gemm_kernel<1><<<dim3(HD_/128,   M_/128), 256, gsmem>>>(hhi, hlo, wqh, wql, bq, nullptr, pos, qbh, qbl, M_, HD_,   E_);
    bf16x3_gemm_kernel<2><<<dim3(KVHD_/128, M_/128), 256, gsmem>>>(hhi, hlo, wkh, wkl, bk, nullptr, pos, kbh, kbl2, M_, KVHD_, E_);
    bf16x3_gemm_kernel<3><<<dim3(KVHD_/128, M_/128), 256, gsmem>>>(hhi, hlo, wvh, wvl, bv, nullptr, pos, vbh, vbl, M_, KVHD_, E_);

    flash_mma_kernel<<<dim3(S_/128, H_, B_), 256, FTOT>>>();

    wtrans_split_kernel<<<dim3(E_/32, HD_/32), dim3(32,8)>>>(Wo, woh, wol, HD_, E_);
    bf16x3_gemm_kernel<0><<<dim3(E_/128, M_/128), 256, gsmem>>>(ahi, alo, woh, wol, nullptr, out, nullptr, nullptr, nullptr, M_, E_, HD_);
}

// round 9
// speedup vs baseline: 1.0136x; 1.0136x over previous
#include <cuda_runtime.h>
#include <cuda_bf16.h>
#include <math.h>
#include <stdint.h>

#define B_    2
#define S_    2048
#define E_    4096
#define H_    32
#define KVH_  8
#define D_    128
#define HD_   (H_*D_)      // 4096
#define KVHD_ (KVH_*D_)    // 1024
#define M_    (B_*S_)      // 4096

// ---------------- scratch (no allocations allowed) ----------------
__device__ float g_cos [S_*(D_/2)];
__device__ float g_sin [S_*(D_/2)];

// bf16 hi/lo operands, 8x8-blocked layout: [R/8][C/8][8][8] (128B per block)
__device__ __align__(16) __nv_bfloat16 g_hid_hi [(size_t)M_*E_];
__device__ __align__(16) __nv_bfloat16 g_hid_lo [(size_t)M_*E_];
__device__ __align__(16) __nv_bfloat16 g_wq_hi  [(size_t)HD_*E_];
__device__ __align__(16) __nv_bfloat16 g_wq_lo  [(size_t)HD_*E_];
__device__ __align__(16) __nv_bfloat16 g_wk_hi  [(size_t)KVHD_*E_];
__device__ __align__(16) __nv_bfloat16 g_wk_lo  [(size_t)KVHD_*E_];
__device__ __align__(16) __nv_bfloat16 g_wv_hi  [(size_t)KVHD_*E_];
__device__ __align__(16) __nv_bfloat16 g_wv_lo  [(size_t)KVHD_*E_];
__device__ __align__(16) __nv_bfloat16 g_wo_hi  [(size_t)E_*HD_];
__device__ __align__(16) __nv_bfloat16 g_wo_lo  [(size_t)E_*HD_];
__device__ __align__(16) __nv_bfloat16 g_attn_hi[(size_t)M_*HD_];
__device__ __align__(16) __nv_bfloat16 g_attn_lo[(size_t)M_*HD_];

// pre-blocked attention operands
__device__ __align__(16) __nv_bfloat16 g_qb_hi[(size_t)B_*H_*S_*D_];
__device__ __align__(16) __nv_bfloat16 g_qb_lo[(size_t)B_*H_*S_*D_];
__device__ __align__(16) __nv_bfloat16 g_kb_hi[(size_t)B_*KVH_*S_*D_];
__device__ __align__(16) __nv_bfloat16 g_kb_lo[(size_t)B_*KVH_*S_*D_];
__device__ __align__(16) __nv_bfloat16 g_vb_hi[(size_t)B_*KVH_*S_*D_];
__device__ __align__(16) __nv_bfloat16 g_vb_lo[(size_t)B_*KVH_*S_*D_];

// ---------------- helpers ----------------
__device__ __forceinline__ uint32_t smem_u32(const void* p) {
    uint32_t a;
    asm("{ .reg .u64 t; cvta.to.shared.u64 t, %1; cvt.u32.u64 %0, t; }" : "=r"(a) : "l"(p));
    return a;
}
__device__ __forceinline__ void ldsm_x4(uint32_t* r, uint32_t a) {
    asm volatile("ldmatrix.sync.aligned.m8n8.x4.shared.b16 {%0,%1,%2,%3}, [%4];"
                 : "=r"(r[0]), "=r"(r[1]), "=r"(r[2]), "=r"(r[3]) : "r"(a));
}
__device__ __forceinline__ void mma_bf16(float* c, const uint32_t* a, const uint32_t* b) {
    asm volatile("mma.sync.aligned.m16n8k16.row.col.f32.bf16.bf16.f32 "
                 "{%0,%1,%2,%3}, {%4,%5,%6,%7}, {%8,%9}, {%0,%1,%2,%3};"
                 : "+f"(c[0]), "+f"(c[1]), "+f"(c[2]), "+f"(c[3])
                 : "r"(a[0]), "r"(a[1]), "r"(a[2]), "r"(a[3]), "r"(b[0]), "r"(b[1]));
}
__device__ __forceinline__ void cp16(uint32_t saddr, const void* g) {
    asm volatile("cp.async.cg.shared.global [%0], [%1], 16;" :: "r"(saddr), "l"(g) : "memory");
}
__device__ __forceinline__ uint32_t pack_bf16_split(float x0, float x1,
                                                    uint32_t& lo_out) {
    __nv_bfloat16 h0 = __float2bfloat16_rn(x0);
    __nv_bfloat16 h1 = __float2bfloat16_rn(x1);
    __nv_bfloat16 l0 = __float2bfloat16_rn(x0 - __bfloat162float(h0));
    __nv_bfloat16 l1 = __float2bfloat16_rn(x1 - __bfloat162float(h1));
    __nv_bfloat162 hp = __halves2bfloat162(h0, h1);
    __nv_bfloat162 lp = __halves2bfloat162(l0, l1);
    lo_out = *reinterpret_cast<uint32_t*>(&lp);
    return *reinterpret_cast<uint32_t*>(&hp);
}

// ---------------- RoPE tables ----------------
__global__ void rope_table_kernel() {
    int idx = blockIdx.x * blockDim.x + threadIdx.x;
    if (idx >= S_*(D_/2)) return;
    int t = idx / (D_/2);
    int i = idx % (D_/2);
    double inv = exp(-((double)(2*i) / (double)D_) * log(10000.0));
    double ang = (double)t * inv;
    g_cos[idx] = (float)cos(ang);
    g_sin[idx] = (float)sin(ang);
}

// ---------------- split fp32 [Mr,Kc] -> blocked bf16 hi/lo ----------------
__global__ void split_blocked_kernel(const float* __restrict__ X,
                                     __nv_bfloat16* __restrict__ Hi,
                                     __nv_bfloat16* __restrict__ Lo,
                                     int Mr, int Kc) {
    int idx = blockIdx.x * blockDim.x + threadIdx.x;
    int KB = Kc >> 3;
    if (idx >= Mr * KB) return;
    int row = idx / KB, kb = idx % KB;
    const float* src = X + (size_t)row * Kc + kb * 8;
    float4 v0 = *(const float4*)src;
    float4 v1 = *(const float4*)(src + 4);
    float xs[8] = {v0.x, v0.y, v0.z, v0.w, v1.x, v1.y, v1.z, v1.w};
    uint32_t hw[4], lw[4];
    #pragma unroll
    for (int j = 0; j < 4; j++)
        hw[j] = pack_bf16_split(xs[2*j], xs[2*j+1], lw[j]);
    size_t off = (((size_t)(row >> 3) * KB + kb) << 6) + (size_t)(row & 7) * 8;
    *(uint4*)(Hi + off) = make_uint4(hw[0], hw[1], hw[2], hw[3]);
    *(uint4*)(Lo + off) = make_uint4(lw[0], lw[1], lw[2], lw[3]);
}

// ---------------- transpose+split: W[K,N] fp32 -> blocked BT hi/lo [N,K] ----------------
__global__ void wtrans_split_kernel(const float* __restrict__ W,
                                    __nv_bfloat16* __restrict__ Thi,
                                    __nv_bfloat16* __restrict__ Tlo,
                                    int Kdim, int Ndim) {
    __shared__ float tile[32][33];
    int n0 = blockIdx.x * 32, k0 = blockIdx.y * 32;
    int tx = threadIdx.x, ty = threadIdx.y;  // (32, 8)
    #pragma unroll
    for (int dy = 0; dy < 32; dy += 8)
        tile[ty + dy][tx] = W[(size_t)(k0 + ty + dy) * Ndim + n0 + tx];
    __syncthreads();
    int KB = Kdim >> 3;
    #pragma unroll
    for (int dy = 0; dy < 32; dy += 8) {
        int n = n0 + ty + dy, k = k0 + tx;
        float x = tile[tx][ty + dy];
        __nv_bfloat16 h = __float2bfloat16_rn(x);
        __nv_bfloat16 l = __float2bfloat16_rn(x - __bfloat162float(h));
        size_t off = (((size_t)(n >> 3) * KB + (k >> 3)) << 6) + (size_t)(n & 7) * 8 + (k & 7);
        Thi[off] = h;
        Tlo[off] = l;
    }
}

// ---------------- 3xBF16 mma.sync GEMM (128x128 tile, k-chunk 64) ----------------
// MODE 0: plain fp32 output
// MODE 1: fused bias + RoPE + split -> g_qb blocked
// MODE 2: fused bias + RoPE + split -> g_kb blocked
// MODE 3: fused bias + transpose + split -> g_vb blocked
template<int MODE>
__global__ __launch_bounds__(256, 1)
void bf16x3_gemm_kernel(const __nv_bfloat16* __restrict__ Ahi, const __nv_bfloat16* __restrict__ Alo,
                        const __nv_bfloat16* __restrict__ Bhi, const __nv_bfloat16* __restrict__ Blo,
                        const float* __restrict__ bias, float* __restrict__ C,
                        const int* __restrict__ pos,
                        __nv_bfloat16* __restrict__ outHi, __nv_bfloat16* __restrict__ outLo,
                        int Mdim, int Ndim, int Kdim) {
    extern __shared__ char smc[];
    const uint32_t sbase = smem_u32(smc);
    const int tid  = threadIdx.x;
    const int warp = tid >> 5, lane = tid & 31;
    const int KB   = Kdim >> 3;
    const int mb0  = blockIdx.y * 16;
    const int nb0  = blockIdx.x * 16;
    const int NC   = Kdim >> 6;

    float acc[4][4][4];
    #pragma unroll
    for (int t = 0; t < 4; t++)
        #pragma unroll
        for (int u = 0; u < 4; u++)
            #pragma unroll
            for (int j = 0; j < 4; j++) acc[t][u][j] = 0.f;

    const char* pAhi = (const char*)Ahi;
    const char* pAlo = (const char*)Alo;
    const char* pBhi = (const char*)Bhi;
    const char* pBlo = (const char*)Blo;

    auto prefetch = [&](int chunk, int st) {
        uint32_t sbuf = sbase + (uint32_t)st * 65536u;
        int kb0 = chunk << 3;
        #pragma unroll
        for (int j = 0; j < 4; j++) {
            int u = tid + j * 256;
            int rb = u >> 6, kb = (u >> 3) & 7, w = u & 7;
            size_t gA = ((size_t)(mb0 + rb) * KB + (kb0 + kb)) * 128u + (size_t)w * 16u;
            size_t gB = ((size_t)(nb0 + rb) * KB + (kb0 + kb)) * 128u + (size_t)w * 16u;
            uint32_t so = (uint32_t)(((rb * 8 + kb) * 8 + w) * 16);
            cp16(sbuf + so,           pAhi + gA);
            cp16(sbuf + 16384u + so,  pAlo + gA);
            cp16(sbuf + 32768u + so,  pBhi + gB);
            cp16(sbuf + 49152u + so,  pBlo + gB);
        }
    };

    const int wmb   = (warp >> 2) * 8;
    const int wnb   = (warp & 3) * 4;
    const int selAm = (lane >> 3) & 1;
    const int selAk = (lane >> 3) >> 1;
    const int selBn = (lane >> 4) & 1;
    const int selBk = (lane >> 3) & 1;
    const int rrow  = lane & 7;

    prefetch(0, 0);
    asm volatile("cp.async.commit_group;" ::: "memory");

    for (int i = 0; i < NC; i++) {
        asm volatile("cp.async.wait_group 0;" ::: "memory");
        __syncthreads();
        if (i + 1 < NC) {
            prefetch(i + 1, (i + 1) & 1);
            asm volatile("cp.async.commit_group;" ::: "memory");
        }
        uint32_t sbuf = sbase + (uint32_t)(i & 1) * 65536u;
        #pragma unroll
        for (int ks = 0; ks < 4; ks++) {
            uint32_t ahi[4][4], alo[4][4], bhi[2][4], blo[2][4];
            #pragma unroll
            for (int t = 0; t < 4; t++) {
                int mbb = wmb + 2*t + selAm;
                int kbb = 2*ks + selAk;
                uint32_t off = (uint32_t)((mbb * 8 + kbb) * 128 + rrow * 16);
                ldsm_x4(ahi[t], sbuf + off);
                ldsm_x4(alo[t], sbuf + 16384u + off);
            }
            #pragma unroll
            for (int u2 = 0; u2 < 2; u2++) {
                int nbb = wnb + 2*u2 + selBn;
                int kbb = 2*ks + selBk;
                uint32_t off = (uint32_t)((nbb * 8 + kbb) * 128 + rrow * 16);
                ldsm_x4(bhi[u2], sbuf + 32768u + off);
                ldsm_x4(blo[u2], sbuf + 49152u + off);
            }
            #pragma unroll
            for (int t = 0; t < 4; t++)
                #pragma unroll
                for (int u = 0; u < 4; u++) {
                    const uint32_t* bh = &bhi[u >> 1][(u & 1) * 2];
                    const uint32_t* bl = &blo[u >> 1][(u & 1) * 2];
                    mma_bf16(acc[t][u], ahi[t], bh);
                    mma_bf16(acc[t][u], alo[t], bh);
                    mma_bf16(acc[t][u], ahi[t], bl);
                }
        }
    }

    const int mrow = mb0 * 8 + (warp >> 2) * 64;
    const int ncol = nb0 * 8 + (warp & 3) * 32;
    const int gg = lane >> 2, qq = lane & 3;

    if (MODE == 0) {
        #pragma unroll
        for (int t = 0; t < 4; t++) {
            #pragma unroll
            for (int u = 0; u < 4; u++) {
                int row = mrow + t * 16 + gg;
                int col = ncol + u * 8 + qq * 2;
                float2 b2 = make_float2(0.f, 0.f);
                if (bias) b2 = *(const float2*)(bias + col);
                float2 v0 = make_float2(acc[t][u][0] + b2.x, acc[t][u][1] + b2.y);
                float2 v1 = make_float2(acc[t][u][2] + b2.x, acc[t][u][3] + b2.y);
                *(float2*)(C + (size_t)row * Ndim + col)       = v0;
                *(float2*)(C + (size_t)(row + 8) * Ndim + col) = v1;
            }
        }
        return;
    }

    // ---- fused epilogues: stage acc+bias to smem fp32 [128 rows][132 pitch] ----
    float* st = (float*)smc;
    __syncthreads();
    {
        const int lrow = (warp >> 2) * 64;
        const int lcol = (warp & 3) * 32;
        #pragma unroll
        for (int t = 0; t < 4; t++) {
            #pragma unroll
            for (int u = 0; u < 4; u++) {
                int r = lrow + t * 16 + gg;
                int c = lcol + u * 8 + qq * 2;
                float2 b2 = *(const float2*)(bias + nb0 * 8 + c);
                st[r * 132 + c]           = acc[t][u][0] + b2.x;
                st[r * 132 + c + 1]       = acc[t][u][1] + b2.y;
                st[(r + 8) * 132 + c]     = acc[t][u][2] + b2.x;
                st[(r + 8) * 132 + c + 1] = acc[t][u][3] + b2.y;
            }
        }
    }
    __syncthreads();

    if (MODE == 1 || MODE == 2) {
        const int hh = blockIdx.x;
        #pragma unroll
        for (int j = 0; j < 4; j++) {
            int idx = tid + j * 256;
            int kbl = idx & 7;
            int r   = idx >> 3;
            int token = blockIdx.y * 128 + r;
            int b = token >> 11;
            int s = token & (S_ - 1);
            int p = pos[b * S_ + s];
            int i0 = kbl * 8;
            float y1[8], y2[8];
            #pragma unroll
            for (int jj = 0; jj < 8; jj++) {
                float x1 = st[r * 132 + i0 + jj];
                float x2 = st[r * 132 + 64 + i0 + jj];
                float c  = g_cos[p * 64 + i0 + jj];
                float sn = g_sin[p * 64 + i0 + jj];
                y1[jj] = x1 * c - x2 * sn;
                y2[jj] = x2 * c + x1 * sn;
            }
            uint32_t h1[4], l1[4], h2[4], l2[4];
            #pragma unroll
            for (int jj = 0; jj < 4; jj++) {
                h1[jj] = pack_bf16_split(y1[2*jj], y1[2*jj+1], l1[jj]);
                h2[jj] = pack_bf16_split(y2[2*jj], y2[2*jj+1], l2[jj]);
            }
            size_t dbase;
            if (MODE == 1) {
                int qt = s >> 7, sbw = (s >> 3) & 15;
                dbase = ((((size_t)(b * H_ + hh) * (S_/128) + qt) * 16 + sbw) * 16);
            } else {
                int kt = s >> 6, sbw = (s >> 3) & 7;
                dbase = ((((size_t)(b * KVH_ + hh) * (S_/64) + kt) * 8 + sbw) * 16);
            }
            int rr = s & 7;
            size_t o1 = (dbase + kbl)     * 64 + (size_t)rr * 8;
            size_t o2 = (dbase + kbl + 8) * 64 + (size_t)rr * 8;
            *(uint4*)(outHi + o1) = make_uint4(h1[0], h1[1], h1[2], h1[3]);
            *(uint4*)(outLo + o1) = make_uint4(l1[0], l1[1], l1[2], l1[3]);
            *(uint4*)(outHi + o2) = make_uint4(h2[0], h2[1], h2[2], h2[3]);
            *(uint4*)(outLo + o2) = make_uint4(l2[0], l2[1], l2[2], l2[3]);
        }
    } else {
        const int kvh = blockIdx.x;
        const int token0 = blockIdx.y * 128;
        const int b = token0 >> 11;
        const int sbase0 = token0 & (S_ - 1);
        #pragma unroll
        for (int j = 0; j < 8; j++) {
            int idx = tid + j * 256;
            int dr  = idx & 7;
            int sbw = (idx >> 3) & 7;
            int db  = (idx >> 6) & 15;
            int ktl = idx >> 10;
            int d = db * 8 + dr;
            int sl = ktl * 64 + sbw * 8;
            uint32_t hw[4], lw[4];
            #pragma unroll
            for (int jj = 0; jj < 4; jj++) {
                float x0 = st[(sl + 2*jj)     * 132 + d];
                float x1 = st[(sl + 2*jj + 1) * 132 + d];
                hw[jj] = pack_bf16_split(x0, x1, lw[jj]);
            }
            int s = sbase0 + sl;
            int kt = s >> 6;
            size_t off = (((((size_t)(b * KVH_ + kvh) * (S_/64) + kt) * 16 + db) * 8 + sbw) * 64)
                       + (size_t)dr * 8;
            *(uint4*)(outHi + off) = make_uint4(hw[0], hw[1], hw[2], hw[3]);
            *(uint4*)(outLo + off) = make_uint4(lw[0], lw[1], lw[2], lw[3]);
        }
    }
}

// ---------------- mma flash attention: double-buffered KV, register softmax ----------------
// smem: Q 64K | KV stage0 64K | KV stage1 64K | P 32K | stats
#define FQHI   0u
#define FQLO   32768u
#define FKV0   65536u          // per-stage: KHI+0 KLO+16K VHI+32K VLO+48K
#define FPBH   196608u
#define FPBL   212992u
#define FMS    229376u
#define FLS    229888u
#define FALS   230400u
#define FPART  230912u
#define FTOT   231936u

__global__ __launch_bounds__(256, 1)
void flash_mma_kernel() {
    extern __shared__ char fs[];
    const uint32_t sb = smem_u32(fs);
    float* m_s  = (float*)(fs + FMS);
    float* l_s  = (float*)(fs + FLS);
    float* al_s = (float*)(fs + FALS);
    float* part = (float*)(fs + FPART);

    const int tid  = threadIdx.x;
    const int warp = tid >> 5, lane = tid & 31;
    const int qt = (S_/128 - 1) - blockIdx.x;   // longest-first
    const int h = blockIdx.y, b = blockIdx.z;
    const int q0 = qt * 128;
    const int kvh = h >> 2;
    const float scale = 0.08838834764831845f;

    const int selAm = (lane >> 3) & 1;
    const int selAk = (lane >> 3) >> 1;
    const int selBn = (lane >> 4) & 1;
    const int selBk = (lane >> 3) & 1;
    const int rrow  = lane & 7;
    const int gr = lane >> 2, qq = lane & 3;

    const size_t kvbase = (size_t)(b*KVH_ + kvh) * (S_/64);
    auto prefetch_kv = [&](int kt, int st) {
        size_t tb = (kvbase + kt) << 13;
        uint32_t sbuf = sb + FKV0 + (uint32_t)st * 65536u;
        const char* kh = (const char*)(g_kb_hi + tb);
        const char* kl = (const char*)(g_kb_lo + tb);
        const char* vh = (const char*)(g_vb_hi + tb);
        const char* vl = (const char*)(g_vb_lo + tb);
        #pragma unroll
        for (int j = 0; j < 4; j++) {
            uint32_t u = (uint32_t)(tid + j * 256) * 16u;
            cp16(sbuf + u,           kh + u);
            cp16(sbuf + 16384u + u,  kl + u);
            cp16(sbuf + 32768u + u,  vh + u);
            cp16(sbuf + 49152u + u,  vl + u);
        }
    };

    // prologue: Q + KV tile 0, one group
    {
        const char* qh = (const char*)(g_qb_hi + (((size_t)(b*H_ + h) * (S_/128) + qt) << 14));
        const char* ql = (const char*)(g_qb_lo + (((size_t)(b*H_ + h) * (S_/128) + qt) << 14));
        #pragma unroll
        for (int j = 0; j < 8; j++) {
            uint32_t u = (uint32_t)(tid + j * 256) * 16u;
            cp16(sb + FQHI + u, qh + u);
            cp16(sb + FQLO + u, ql + u);
        }
        prefetch_kv(0, 0);
        asm volatile("cp.async.commit_group;" ::: "memory");
    }
    if (tid < 128) { m_s[tid] = -1e30f; l_s[tid] = 0.f; }

    const int pwm = (warp >> 2) * 64;
    const int pwn = (warp & 3) * 32;
    float acc[4][4][4];
    #pragma unroll
    for (int t = 0; t < 4; t++)
        #pragma unroll
        for (int u = 0; u < 4; u++)
            #pragma unroll
            for (int j = 0; j < 4; j++) acc[t][u][j] = 0.f;

    const int wm = (warp >> 1) * 32;
    const int wn = (warp & 1) * 32;
    const int wcol = warp & 1;

    const int NK = 2 * qt + 2;
    for (int kt = 0; kt < NK; kt++) {
        const int k0 = kt * 64;
        asm volatile("cp.async.wait_group 0;" ::: "memory");
        __syncthreads();               // KV tile kt visible to all warps
        const uint32_t kvs = sb + FKV0 + (uint32_t)(kt & 1) * 65536u;

        // ---- S = Q @ K^T (3-split) ----
        float sacc[2][4][4];
        #pragma unroll
        for (int t = 0; t < 2; t++)
            #pragma unroll
            for (int u = 0; u < 4; u++)
                #pragma unroll
                for (int j = 0; j < 4; j++) sacc[t][u][j] = 0.f;

        #pragma unroll
        for (int ks = 0; ks < 8; ks++) {
            uint32_t qhi[2][4], qlo[2][4], khi[2][4], klo[2][4];
            #pragma unroll
            for (int t = 0; t < 2; t++) {
                int mbb = (wm >> 3) + 2*t + selAm;
                int kbb = 2*ks + selAk;
                uint32_t off = (uint32_t)((mbb * 16 + kbb) * 128 + rrow * 16);
                ldsm_x4(qhi[t], sb + FQHI + off);
                ldsm_x4(qlo[t], sb + FQLO + off);
            }
            #pragma unroll
            for (int u2 = 0; u2 < 2; u2++) {
                int nbb = (wn >> 3) + 2*u2 + selBn;
                int kbb = 2*ks + selBk;
                uint32_t off = (uint32_t)((nbb * 16 + kbb) * 128 + rrow * 16);
                ldsm_x4(khi[u2], kvs + off);
                ldsm_x4(klo[u2], kvs + 16384u + off);
            }
            #pragma unroll
            for (int t = 0; t < 2; t++)
                #pragma unroll
                for (int u = 0; u < 4; u++) {
                    const uint32_t* kh = &khi[u >> 1][(u & 1) * 2];
                    const uint32_t* kl = &klo[u >> 1][(u & 1) * 2];
                    mma_bf16(sacc[t][u], qhi[t], kh);
                    mma_bf16(sacc[t][u], qlo[t], kh);
                    mma_bf16(sacc[t][u], qhi[t], kl);
                }
        }

        // ---- register softmax: scale + mask + quad row-max ----
        const bool needmask = (kt >= 2 * qt);
        #pragma unroll
        for (int t = 0; t < 2; t++) {
            int r1 = wm + t * 16 + gr;
            float m1 = -1e30f, m2 = -1e30f;
            #pragma unroll
            for (int u = 0; u < 4; u++) {
                int c0 = wn + u * 8 + qq * 2;
                float s0 = sacc[t][u][0] * scale;
                float s1 = sacc[t][u][1] * scale;
                float s2 = sacc[t][u][2] * scale;
                float s3 = sacc[t][u][3] * scale;
                if (needmask) {
                    if (k0 + c0     > q0 + r1)     s0 = -1e30f;
                    if (k0 + c0 + 1 > q0 + r1)     s1 = -1e30f;
                    if (k0 + c0     > q0 + r1 + 8) s2 = -1e30f;
                    if (k0 + c0 + 1 > q0 + r1 + 8) s3 = -1e30f;
                }
                sacc[t][u][0] = s0; sacc[t][u][1] = s1;
                sacc[t][u][2] = s2; sacc[t][u][3] = s3;
                m1 = fmaxf(m1, fmaxf(s0, s1));
                m2 = fmaxf(m2, fmaxf(s2, s3));
            }
            m1 = fmaxf(m1, __shfl_xor_sync(0xffffffffu, m1, 1));
            m1 = fmaxf(m1, __shfl_xor_sync(0xffffffffu, m1, 2));
            m2 = fmaxf(m2, __shfl_xor_sync(0xffffffffu, m2, 1));
            m2 = fmaxf(m2, __shfl_xor_sync(0xffffffffu, m2, 2));
            if (qq == 0) {
                part[r1*2 + wcol]     = m1;
                part[(r1+8)*2 + wcol] = m2;
            }
        }
        __syncthreads();   // all warps past QK of kt (hence past PV of kt-1)

        // prefetch next KV tile into the other stage (overlaps rest of softmax + PV)
        if (kt + 1 < NK) {
            prefetch_kv(kt + 1, (kt + 1) & 1);
            asm volatile("cp.async.commit_group;" ::: "memory");
        }

        if (tid < 128) {
            float mx = fmaxf(part[tid*2], part[tid*2+1]);
            float mo = m_s[tid];
            float mn = fmaxf(mo, mx);
            m_s[tid]  = mn;
            al_s[tid] = __expf(mo - mn);
        }
        __syncthreads();

        // ---- exp in registers + quad row-sum + split P to blocked smem ----
        {
            __nv_bfloat16* ph = (__nv_bfloat16*)(fs + FPBH);
            __nv_bfloat16* pl = (__nv_bfloat16*)(fs + FPBL);
            #pragma unroll
            for (int t = 0; t < 2; t++) {
                int r1 = wm + t * 16 + gr;
                int r2 = r1 + 8;
                float mm1 = m_s[r1], mm2 = m_s[r2];
                float sum1 = 0.f, sum2 = 0.f;
                #pragma unroll
                for (int u = 0; u < 4; u++) {
                    float e0 = __expf(sacc[t][u][0] - mm1);
                    float e1 = __expf(sacc[t][u][1] - mm1);
                    float e2 = __expf(sacc[t][u][2] - mm2);
                    float e3 = __expf(sacc[t][u][3] - mm2);
                    sum1 += e0 + e1;
                    sum2 += e2 + e3;
                    int cb = (wn >> 3) + u;
                    uint32_t lo;
                    uint32_t hi = pack_bf16_split(e0, e1, lo);
                    uint32_t o1 = (uint32_t)((((r1 >> 3) * 8 + cb) << 6) + (r1 & 7) * 8 + qq * 2);
                    *(uint32_t*)(ph + o1) = hi;
                    *(uint32_t*)(pl + o1) = lo;
                    hi = pack_bf16_split(e2, e3, lo);
                    uint32_t o2 = (uint32_t)((((r2 >> 3) * 8 + cb) << 6) + (r2 & 7) * 8 + qq * 2);
                    *(uint32_t*)(ph + o2) = hi;
                    *(uint32_t*)(pl + o2) = lo;
                }
                sum1 += __shfl_xor_sync(0xffffffffu, sum1, 1);
                sum1 += __shfl_xor_sync(0xffffffffu, sum1, 2);
                sum2 += __shfl_xor_sync(0xffffffffu, sum2, 1);
                sum2 += __shfl_xor_sync(0xffffffffu, sum2, 2);
                if (qq == 0) {
                    part[r1*2 + wcol] = sum1;
                    part[r2*2 + wcol] = sum2;
                }
            }
        }
        __syncthreads();
        if (tid < 128) l_s[tid] = l_s[tid] * al_s[tid] + part[tid*2] + part[tid*2+1];

        // ---- rescale PV accumulators ----
        #pragma unroll
        for (int t = 0; t < 4; t++) {
            float a1 = al_s[pwm + t*16 + gr];
            float a2 = al_s[pwm + t*16 + gr + 8];
            #pragma unroll
            for (int u = 0; u < 4; u++) {
                acc[t][u][0] *= a1; acc[t][u][1] *= a1;
                acc[t][u][2] *= a2; acc[t][u][3] *= a2;
            }
        }

        // ---- O += P @ V (3-split) ----
        #pragma unroll
        for (int ks = 0; ks < 4; ks++) {
            uint32_t phiF[4][4], ploF[4][4], vhiF[2][4], vloF[2][4];
            #pragma unroll
            for (int t = 0; t < 4; t++) {
                int mbb = (pwm >> 3) + 2*t + selAm;
                int kbb = 2*ks + selAk;
                uint32_t off = (uint32_t)((mbb * 8 + kbb) * 128 + rrow * 16);
                ldsm_x4(phiF[t], sb + FPBH + off);
                ldsm_x4(ploF[t], sb + FPBL + off);
            }
            #pragma unroll
            for (int u2 = 0; u2 < 2; u2++) {
                int nbb = (pwn >> 3) + 2*u2 + selBn;
                int kbb = 2*ks + selBk;
                uint32_t off = (uint32_t)((nbb * 8 + kbb) * 128 + rrow * 16);
                ldsm_x4(vhiF[u2], kvs + 32768u + off);
                ldsm_x4(vloF[u2], kvs + 49152u + off);
            }
            #pragma unroll
            for (int t = 0; t < 4; t++)
                #pragma unroll
                for (int u = 0; u < 4; u++) {
                    const uint32_t* vh = &vhiF[u >> 1][(u & 1) * 2];
                    const uint32_t* vl = &vloF[u >> 1][(u & 1) * 2];
                    mma_bf16(acc[t][u], phiF[t], vh);
                    mma_bf16(acc[t][u], ploF[t], vh);
                    mma_bf16(acc[t][u], phiF[t], vl);
                }
        }
    }

    __syncthreads();

    // ---- epilogue: normalize + write blocked bf16 hi/lo ----
    {
        const int KB = HD_ >> 3;
        #pragma unroll
        for (int t = 0; t < 4; t++) {
            int r1 = pwm + t*16 + gr;
            float inv1 = 1.f / l_s[r1];
            float inv2 = 1.f / l_s[r1 + 8];
            int grow1 = b*S_ + q0 + r1;
            int grow2 = grow1 + 8;
            #pragma unroll
            for (int u = 0; u < 4; u++) {
                int col = h * D_ + pwn + u*8 + qq * 2;
                int kb = col >> 3, cw = col & 7;
                uint32_t lo1, lo2;
                uint32_t hi1 = pack_bf16_split(acc[t][u][0]*inv1, acc[t][u][1]*inv1, lo1);
                uint32_t hi2 = pack_bf16_split(acc[t][u][2]*inv2, acc[t][u][3]*inv2, lo2);
                size_t o1 = (((size_t)(grow1 >> 3) * KB + kb) << 6) + (size_t)(grow1 & 7) * 8 + cw;
                size_t o2 = (((size_t)(grow2 >> 3) * KB + kb) << 6) + (size_t)(grow2 & 7) * 8 + cw;
                *(uint32_t*)(g_attn_hi + o1) = hi1;
                *(uint32_t*)(g_attn_lo + o1) = lo1;
                *(uint32_t*)(g_attn_hi + o2) = hi2;
                *(uint32_t*)(g_attn_lo + o2) = lo2;
            }
        }
    }
}

// ---------------- launch ----------------
extern "C" void kernel_launch(void* const* d_in, const int* in_sizes, int n_in,
                              void* d_out, int out_size) {
    const float* hidden = (const float*)d_in[0];
    const int*   pos    = (const int*)  d_in[2];
    const float* Wq     = (const float*)d_in[3];
    const float* bq     = (const float*)d_in[4];
    const float* Wk     = (const float*)d_in[5];
    const float* bk     = (const float*)d_in[6];
    const float* Wv     = (const float*)d_in[7];
    const float* bv     = (const float*)d_in[8];
    const float* Wo     = (const float*)d_in[9];
    float* out = (float*)d_out;

    __nv_bfloat16 *hhi, *hlo, *wqh, *wql, *wkh, *wkl, *wvh, *wvl, *woh, *wol, *ahi, *alo;
    __nv_bfloat16 *qbh, *qbl, *kbh, *kbl2, *vbh, *vbl;
    cudaGetSymbolAddress((void**)&hhi, g_hid_hi);
    cudaGetSymbolAddress((void**)&hlo, g_hid_lo);
    cudaGetSymbolAddress((void**)&wqh, g_wq_hi);
    cudaGetSymbolAddress((void**)&wql, g_wq_lo);
    cudaGetSymbolAddress((void**)&wkh, g_wk_hi);
    cudaGetSymbolAddress((void**)&wkl, g_wk_lo);
    cudaGetSymbolAddress((void**)&wvh, g_wv_hi);
    cudaGetSymbolAddress((void**)&wvl, g_wv_lo);
    cudaGetSymbolAddress((void**)&woh, g_wo_hi);
    cudaGetSymbolAddress((void**)&wol, g_wo_lo);
    cudaGetSymbolAddress((void**)&ahi, g_attn_hi);
    cudaGetSymbolAddress((void**)&alo, g_attn_lo);
    cudaGetSymbolAddress((void**)&qbh, g_qb_hi);
    cudaGetSymbolAddress((void**)&qbl, g_qb_lo);
    cudaGetSymbolAddress((void**)&kbh, g_kb_hi);
    cudaGetSymbolAddress((void**)&kbl2, g_kb_lo);
    cudaGetSymbolAddress((void**)&vbh, g_vb_hi);
    cudaGetSymbolAddress((void**)&vbl, g_vb_lo);

    const size_t gsmem = 131072;
    cudaFuncSetAttribute(bf16x3_gemm_kernel<0>, cudaFuncAttributeMaxDynamicSharedMemorySize, (int)gsmem);
    cudaFuncSetAttribute(bf16x3_gemm_kernel<1>, cudaFuncAttributeMaxDynamicSharedMemorySize, (int)gsmem);
    cudaFuncSetAttribute(bf16x3_gemm_kernel<2>, cudaFuncAttributeMaxDynamicSharedMemorySize, (int)gsmem);
    cudaFuncSetAttribute(bf16x3_gemm_kernel<3>, cudaFuncAttributeMaxDynamicSharedMemorySize, (int)gsmem);
    cudaFuncSetAttribute(flash_mma_kernel, cudaFuncAttributeMaxDynamicSharedMemorySize, (int)FTOT);

    rope_table_kernel<<<(S_*(D_/2) + 255)/256, 256>>>();
    {
        int n = M_ * (E_ >> 3);
        split_blocked_kernel<<<(n + 255)/256, 256>>>(hidden, hhi, hlo, M_, E_);
    }
    wtrans_split_kernel<<<dim3(HD_/32,   E_/32), dim3(32,8)>>>(Wq, wqh, wql, E_,  HD_);
    wtrans_split_kernel<<<dim3(KVHD_/32, E_/32), dim3(32,8)>>>(Wk, wkh, wkl, E_,  KVHD_);
    wtrans_split_kernel<<<dim3(KVHD_/32, E_/32), dim3(32,8)>>>(Wv, wvh, wvl, E_,  KVHD_);

    bf16x3_gemm_kernel<1><<<dim3(HD_/128,   M_/128), 256, gsmem>>>(hhi, hlo, wqh, wql, bq, nullptr, pos, qbh, qbl, M_, HD_,   E_);
    bf16x3_gemm_kernel<2><<<dim3(KVHD_/128, M_/128), 256, gsmem>>>(hhi, hlo, wkh, wkl, bk, nullptr, pos, kbh, kbl2, M_, KVHD_, E_);
    bf16x3_gemm_kernel<3><<<dim3(KVHD_/128, M_/128), 256, gsmem>>>(hhi, hlo, wvh, wvl, bv, nullptr, pos, vbh, vbl, M_, KVHD_, E_);

    flash_mma_kernel<<<dim3(S_/128, H_, B_), 256, FTOT>>>();

    wtrans_split_kernel<<<dim3(E_/32, HD_/32), dim3(32,8)>>>(Wo, woh, wol, HD_, E_);
    bf16x3_gemm_kernel<0><<<dim3(E_/128, M_/128), 256, gsmem>>>(ahi, alo, woh, wol, nullptr, out, nullptr, nullptr, nullptr, M_, E_, HD_);
}

// round 10
// speedup vs baseline: 1.3657x; 1.3475x over previous
#include <cuda_runtime.h>
#include <cuda_fp16.h>
#include <math.h>
#include <stdint.h>

#define B_    2
#define S_    2048
#define E_    4096
#define H_    32
#define KVH_  8
#define D_    128
#define HD_   (H_*D_)      // 4096
#define KVHD_ (KVH_*D_)    // 1024
#define M_    (B_*S_)      // 4096

// ---------------- scratch (no allocations allowed) ----------------
__device__ float g_cos [S_*(D_/2)];
__device__ float g_sin [S_*(D_/2)];

// fp16 operands, 8x8-blocked layout: [R/8][C/8][8][8] (128B per block)
__device__ __align__(16) __half g_hid_hi [(size_t)M_*E_];       // A-side: hi only
__device__ __align__(16) __half g_wq_hi  [(size_t)HD_*E_];
__device__ __align__(16) __half g_wq_lo  [(size_t)HD_*E_];
__device__ __align__(16) __half g_wk_hi  [(size_t)KVHD_*E_];
__device__ __align__(16) __half g_wk_lo  [(size_t)KVHD_*E_];
__device__ __align__(16) __half g_wv_hi  [(size_t)KVHD_*E_];
__device__ __align__(16) __half g_wv_lo  [(size_t)KVHD_*E_];
__device__ __align__(16) __half g_wo_hi  [(size_t)E_*HD_];
__device__ __align__(16) __half g_wo_lo  [(size_t)E_*HD_];
__device__ __align__(16) __half g_attn_hi[(size_t)M_*HD_];      // A-side: hi only

// pre-blocked attention operands
__device__ __align__(16) __half g_qb_hi[(size_t)B_*H_*S_*D_];   // QK is 3-term: Q hi+lo
__device__ __align__(16) __half g_qb_lo[(size_t)B_*H_*S_*D_];
__device__ __align__(16) __half g_kb_hi[(size_t)B_*KVH_*S_*D_];
__device__ __align__(16) __half g_kb_lo[(size_t)B_*KVH_*S_*D_];
__device__ __align__(16) __half g_vb_hi[(size_t)B_*KVH_*S_*D_]; // PV 2-term: V hi+lo, P hi only
__device__ __align__(16) __half g_vb_lo[(size_t)B_*KVH_*S_*D_];

// ---------------- helpers ----------------
__device__ __forceinline__ uint32_t smem_u32(const void* p) {
    uint32_t a;
    asm("{ .reg .u64 t; cvta.to.shared.u64 t, %1; cvt.u32.u64 %0, t; }" : "=r"(a) : "l"(p));
    return a;
}
__device__ __forceinline__ void ldsm_x4(uint32_t* r, uint32_t a) {
    asm volatile("ldmatrix.sync.aligned.m8n8.x4.shared.b16 {%0,%1,%2,%3}, [%4];"
                 : "=r"(r[0]), "=r"(r[1]), "=r"(r[2]), "=r"(r[3]) : "r"(a));
}
__device__ __forceinline__ void mma_f16(float* c, const uint32_t* a, const uint32_t* b) {
    asm volatile("mma.sync.aligned.m16n8k16.row.col.f32.f16.f16.f32 "
                 "{%0,%1,%2,%3}, {%4,%5,%6,%7}, {%8,%9}, {%0,%1,%2,%3};"
                 : "+f"(c[0]), "+f"(c[1]), "+f"(c[2]), "+f"(c[3])
                 : "r"(a[0]), "r"(a[1]), "r"(a[2]), "r"(a[3]), "r"(b[0]), "r"(b[1]));
}
__device__ __forceinline__ void cp16(uint32_t saddr, const void* g) {
    asm volatile("cp.async.cg.shared.global [%0], [%1], 16;" :: "r"(saddr), "l"(g) : "memory");
}
__device__ __forceinline__ uint32_t pack_f16_split(float x0, float x1, uint32_t& lo_out) {
    __half h0 = __float2half_rn(x0);
    __half h1 = __float2half_rn(x1);
    __half l0 = __float2half_rn(x0 - __half2float(h0));
    __half l1 = __float2half_rn(x1 - __half2float(h1));
    __half2 hp = __halves2half2(h0, h1);
    __half2 lp = __halves2half2(l0, l1);
    lo_out = *reinterpret_cast<uint32_t*>(&lp);
    return *reinterpret_cast<uint32_t*>(&hp);
}
__device__ __forceinline__ uint32_t pack_f16_pair(float x0, float x1) {
    __half2 hp = __halves2half2(__float2half_rn(x0), __float2half_rn(x1));
    return *reinterpret_cast<uint32_t*>(&hp);
}

// ---------------- RoPE tables ----------------
__global__ void rope_table_kernel() {
    int idx = blockIdx.x * blockDim.x + threadIdx.x;
    if (idx >= S_*(D_/2)) return;
    int t = idx / (D_/2);
    int i = idx % (D_/2);
    double inv = exp(-((double)(2*i) / (double)D_) * log(10000.0));
    double ang = (double)t * inv;
    g_cos[idx] = (float)cos(ang);
    g_sin[idx] = (float)sin(ang);
}

// ---------------- fp32 [Mr,Kc] -> blocked fp16 hi (A-side; no lo) ----------------
__global__ void split_blocked_kernel(const float* __restrict__ X,
                                     __half* __restrict__ Hi,
                                     int Mr, int Kc) {
    int idx = blockIdx.x * blockDim.x + threadIdx.x;
    int KB = Kc >> 3;
    if (idx >= Mr * KB) return;
    int row = idx / KB, kb = idx % KB;
    const float* src = X + (size_t)row * Kc + kb * 8;
    float4 v0 = *(const float4*)src;
    float4 v1 = *(const float4*)(src + 4);
    uint32_t hw[4];
    hw[0] = pack_f16_pair(v0.x, v0.y);
    hw[1] = pack_f16_pair(v0.z, v0.w);
    hw[2] = pack_f16_pair(v1.x, v1.y);
    hw[3] = pack_f16_pair(v1.z, v1.w);
    size_t off = (((size_t)(row >> 3) * KB + kb) << 6) + (size_t)(row & 7) * 8;
    *(uint4*)(Hi + off) = make_uint4(hw[0], hw[1], hw[2], hw[3]);
}

// ---------------- transpose+split: W[K,N] fp32 -> blocked BT hi/lo [N,K] ----------------
__global__ void wtrans_split_kernel(const float* __restrict__ W,
                                    __half* __restrict__ Thi,
                                    __half* __restrict__ Tlo,
                                    int Kdim, int Ndim) {
    __shared__ float tile[32][33];
    int n0 = blockIdx.x * 32, k0 = blockIdx.y * 32;
    int tx = threadIdx.x, ty = threadIdx.y;  // (32, 8)
    #pragma unroll
    for (int dy = 0; dy < 32; dy += 8)
        tile[ty + dy][tx] = W[(size_t)(k0 + ty + dy) * Ndim + n0 + tx];
    __syncthreads();
    int KB = Kdim >> 3;
    #pragma unroll
    for (int dy = 0; dy < 32; dy += 8) {
        int n = n0 + ty + dy, k = k0 + tx;
        float x = tile[tx][ty + dy];
        __half h = __float2half_rn(x);
        __half l = __float2half_rn(x - __half2float(h));
        size_t off = (((size_t)(n >> 3) * KB + (k >> 3)) << 6) + (size_t)(n & 7) * 8 + (k & 7);
        Thi[off] = h;
        Tlo[off] = l;
    }
}

// ---------------- 2xFP16 mma.sync GEMM (128x128 tile, k-chunk 64) ----------------
// D = Ah*(Bh+Bl). Stage: Ahi 16K | Bhi 16K | Blo 16K = 48KB, 2 stages.
// MODE 0: plain fp32 output
// MODE 1: fused bias + RoPE + split -> g_qb blocked
// MODE 2: fused bias + RoPE + split -> g_kb blocked
// MODE 3: fused bias + transpose + split -> g_vb blocked
template<int MODE>
__global__ __launch_bounds__(256, 1)
void f16x2_gemm_kernel(const __half* __restrict__ Ahi,
                       const __half* __restrict__ Bhi, const __half* __restrict__ Blo,
                       const float* __restrict__ bias, float* __restrict__ C,
                       const int* __restrict__ pos,
                       __half* __restrict__ outHi, __half* __restrict__ outLo,
                       int Mdim, int Ndim, int Kdim) {
    extern __shared__ char smc[];
    const uint32_t sbase = smem_u32(smc);
    const int tid  = threadIdx.x;
    const int warp = tid >> 5, lane = tid & 31;
    const int KB   = Kdim >> 3;
    const int mb0  = blockIdx.y * 16;
    const int nb0  = blockIdx.x * 16;
    const int NC   = Kdim >> 6;

    float acc[4][4][4];
    #pragma unroll
    for (int t = 0; t < 4; t++)
        #pragma unroll
        for (int u = 0; u < 4; u++)
            #pragma unroll
            for (int j = 0; j < 4; j++) acc[t][u][j] = 0.f;

    const char* pAhi = (const char*)Ahi;
    const char* pBhi = (const char*)Bhi;
    const char* pBlo = (const char*)Blo;

    auto prefetch = [&](int chunk, int st) {
        uint32_t sbuf = sbase + (uint32_t)st * 49152u;
        int kb0 = chunk << 3;
        #pragma unroll
        for (int j = 0; j < 4; j++) {
            int u = tid + j * 256;
            int rb = u >> 6, kb = (u >> 3) & 7, w = u & 7;
            size_t gA = ((size_t)(mb0 + rb) * KB + (kb0 + kb)) * 128u + (size_t)w * 16u;
            size_t gB = ((size_t)(nb0 + rb) * KB + (kb0 + kb)) * 128u + (size_t)w * 16u;
            uint32_t so = (uint32_t)(((rb * 8 + kb) * 8 + w) * 16);
            cp16(sbuf + so,           pAhi + gA);
            cp16(sbuf + 16384u + so,  pBhi + gB);
            cp16(sbuf + 32768u + so,  pBlo + gB);
        }
    };

    const int wmb   = (warp >> 2) * 8;
    const int wnb   = (warp & 3) * 4;
    const int selAm = (lane >> 3) & 1;
    const int selAk = (lane >> 3) >> 1;
    const int selBn = (lane >> 4) & 1;
    const int selBk = (lane >> 3) & 1;
    const int rrow  = lane & 7;

    prefetch(0, 0);
    asm volatile("cp.async.commit_group;" ::: "memory");

    for (int i = 0; i < NC; i++) {
        asm volatile("cp.async.wait_group 0;" ::: "memory");
        __syncthreads();
        if (i + 1 < NC) {
            prefetch(i + 1, (i + 1) & 1);
            asm volatile("cp.async.commit_group;" ::: "memory");
        }
        uint32_t sbuf = sbase + (uint32_t)(i & 1) * 49152u;
        #pragma unroll
        for (int ks = 0; ks < 4; ks++) {
            uint32_t ahi[4][4], bhi[2][4], blo[2][4];
            #pragma unroll
            for (int t = 0; t < 4; t++) {
                int mbb = wmb + 2*t + selAm;
                int kbb = 2*ks + selAk;
                uint32_t off = (uint32_t)((mbb * 8 + kbb) * 128 + rrow * 16);
                ldsm_x4(ahi[t], sbuf + off);
            }
            #pragma unroll
            for (int u2 = 0; u2 < 2; u2++) {
                int nbb = wnb + 2*u2 + selBn;
                int kbb = 2*ks + selBk;
                uint32_t off = (uint32_t)((nbb * 8 + kbb) * 128 + rrow * 16);
                ldsm_x4(bhi[u2], sbuf + 16384u + off);
                ldsm_x4(blo[u2], sbuf + 32768u + off);
            }
            #pragma unroll
            for (int t = 0; t < 4; t++)
                #pragma unroll
                for (int u = 0; u < 4; u++) {
                    const uint32_t* bh = &bhi[u >> 1][(u & 1) * 2];
                    const uint32_t* bl = &blo[u >> 1][(u & 1) * 2];
                    mma_f16(acc[t][u], ahi[t], bh);
                    mma_f16(acc[t][u], ahi[t], bl);
                }
        }
    }

    const int mrow = mb0 * 8 + (warp >> 2) * 64;
    const int ncol = nb0 * 8 + (warp & 3) * 32;
    const int gg = lane >> 2, qq = lane & 3;

    if (MODE == 0) {
        #pragma unroll
        for (int t = 0; t < 4; t++) {
            #pragma unroll
            for (int u = 0; u < 4; u++) {
                int row = mrow + t * 16 + gg;
                int col = ncol + u * 8 + qq * 2;
                float2 b2 = make_float2(0.f, 0.f);
                if (bias) b2 = *(const float2*)(bias + col);
                float2 v0 = make_float2(acc[t][u][0] + b2.x, acc[t][u][1] + b2.y);
                float2 v1 = make_float2(acc[t][u][2] + b2.x, acc[t][u][3] + b2.y);
                *(float2*)(C + (size_t)row * Ndim + col)       = v0;
                *(float2*)(C + (size_t)(row + 8) * Ndim + col) = v1;
            }
        }
        return;
    }

    // ---- fused epilogues: stage acc+bias to smem fp32 [128 rows][132 pitch] ----
    float* st = (float*)smc;
    __syncthreads();
    {
        const int lrow = (warp >> 2) * 64;
        const int lcol = (warp & 3) * 32;
        #pragma unroll
        for (int t = 0; t < 4; t++) {
            #pragma unroll
            for (int u = 0; u < 4; u++) {
                int r = lrow + t * 16 + gg;
                int c = lcol + u * 8 + qq * 2;
                float2 b2 = *(const float2*)(bias + nb0 * 8 + c);
                st[r * 132 + c]           = acc[t][u][0] + b2.x;
                st[r * 132 + c + 1]       = acc[t][u][1] + b2.y;
                st[(r + 8) * 132 + c]     = acc[t][u][2] + b2.x;
                st[(r + 8) * 132 + c + 1] = acc[t][u][3] + b2.y;
            }
        }
    }
    __syncthreads();

    if (MODE == 1 || MODE == 2) {
        const int hh = blockIdx.x;
        #pragma unroll
        for (int j = 0; j < 4; j++) {
            int idx = tid + j * 256;
            int kbl = idx & 7;
            int r   = idx >> 3;
            int token = blockIdx.y * 128 + r;
            int b = token >> 11;
            int s = token & (S_ - 1);
            int p = pos[b * S_ + s];
            int i0 = kbl * 8;
            float y1[8], y2[8];
            #pragma unroll
            for (int jj = 0; jj < 8; jj++) {
                float x1 = st[r * 132 + i0 + jj];
                float x2 = st[r * 132 + 64 + i0 + jj];
                float c  = g_cos[p * 64 + i0 + jj];
                float sn = g_sin[p * 64 + i0 + jj];
                y1[jj] = x1 * c - x2 * sn;
                y2[jj] = x2 * c + x1 * sn;
            }
            uint32_t h1[4], l1[4], h2[4], l2[4];
            #pragma unroll
            for (int jj = 0; jj < 4; jj++) {
                h1[jj] = pack_f16_split(y1[2*jj], y1[2*jj+1], l1[jj]);
                h2[jj] = pack_f16_split(y2[2*jj], y2[2*jj+1], l2[jj]);
            }
            size_t dbase;
            if (MODE == 1) {
                int qt = s >> 7, sbw = (s >> 3) & 15;
                dbase = ((((size_t)(b * H_ + hh) * (S_/128) + qt) * 16 + sbw) * 16);
            } else {
                int kt = s >> 6, sbw = (s >> 3) & 7;
                dbase = ((((size_t)(b * KVH_ + hh) * (S_/64) + kt) * 8 + sbw) * 16);
            }
            int rr = s & 7;
            size_t o1 = (dbase + kbl)     * 64 + (size_t)rr * 8;
            size_t o2 = (dbase + kbl + 8) * 64 + (size_t)rr * 8;
            *(uint4*)(outHi + o1) = make_uint4(h1[0], h1[1], h1[2], h1[3]);
            *(uint4*)(outLo + o1) = make_uint4(l1[0], l1[1], l1[2], l1[3]);
            *(uint4*)(outHi + o2) = make_uint4(h2[0], h2[1], h2[2], h2[3]);
            *(uint4*)(outLo + o2) = make_uint4(l2[0], l2[1], l2[2], l2[3]);
        }
    } else {
        const int kvh = blockIdx.x;
        const int token0 = blockIdx.y * 128;
        const int b = token0 >> 11;
        const int sbase0 = token0 & (S_ - 1);
        #pragma unroll
        for (int j = 0; j < 8; j++) {
            int idx = tid + j * 256;
            int dr  = idx & 7;
            int sbw = (idx >> 3) & 7;
            int db  = (idx >> 6) & 15;
            int ktl = idx >> 10;
            int d = db * 8 + dr;
            int sl = ktl * 64 + sbw * 8;
            uint32_t hw[4], lw[4];
            #pragma unroll
            for (int jj = 0; jj < 4; jj++) {
                float x0 = st[(sl + 2*jj)     * 132 + d];
                float x1 = st[(sl + 2*jj + 1) * 132 + d];
                hw[jj] = pack_f16_split(x0, x1, lw[jj]);
            }
            int s = sbase0 + sl;
            int kt = s >> 6;
            size_t off = (((((size_t)(b * KVH_ + kvh) * (S_/64) + kt) * 16 + db) * 8 + sbw) * 64)
                       + (size_t)dr * 8;
            *(uint4*)(outHi + off) = make_uint4(hw[0], hw[1], hw[2], hw[3]);
            *(uint4*)(outLo + off) = make_uint4(lw[0], lw[1], lw[2], lw[3]);
        }
    }
}

// ---------------- mma flash attention: double-buffered KV, register softmax ----------------
// QK 3-term (Q hi/lo x K hi/lo, drop lo.lo); PV 2-term (Ph x (Vh+Vl)).
// smem: Q 64K | KV stage0 64K | KV stage1 64K | Phi 16K | stats
#define FQHI   0u
#define FQLO   32768u
#define FKV0   65536u          // per-stage: KHI+0 KLO+16K VHI+32K VLO+48K
#define FPBH   196608u
#define FMS    212992u
#define FLS    213504u
#define FALS   214016u
#define FPART  214528u
#define FTOT   215552u

__global__ __launch_bounds__(256, 1)
void flash_mma_kernel() {
    extern __shared__ char fs[];
    const uint32_t sb = smem_u32(fs);
    float* m_s  = (float*)(fs + FMS);
    float* l_s  = (float*)(fs + FLS);
    float* al_s = (float*)(fs + FALS);
    float* part = (float*)(fs + FPART);

    const int tid  = threadIdx.x;
    const int warp = tid >> 5, lane = tid & 31;
    const int qt = (S_/128 - 1) - blockIdx.x;   // longest-first
    const int h = blockIdx.y, b = blockIdx.z;
    const int q0 = qt * 128;
    const int kvh = h >> 2;
    const float scale = 0.08838834764831845f;

    const int selAm = (lane >> 3) & 1;
    const int selAk = (lane >> 3) >> 1;
    const int selBn = (lane >> 4) & 1;
    const int selBk = (lane >> 3) & 1;
    const int rrow  = lane & 7;
    const int gr = lane >> 2, qq = lane & 3;

    const size_t kvbase = (size_t)(b*KVH_ + kvh) * (S_/64);
    auto prefetch_kv = [&](int kt, int st) {
        size_t tb = (kvbase + kt) << 13;
        uint32_t sbuf = sb + FKV0 + (uint32_t)st * 65536u;
        const char* kh = (const char*)(g_kb_hi + tb);
        const char* kl = (const char*)(g_kb_lo + tb);
        const char* vh = (const char*)(g_vb_hi + tb);
        const char* vl = (const char*)(g_vb_lo + tb);
        #pragma unroll
        for (int j = 0; j < 4; j++) {
            uint32_t u = (uint32_t)(tid + j * 256) * 16u;
            cp16(sbuf + u,           kh + u);
            cp16(sbuf + 16384u + u,  kl + u);
            cp16(sbuf + 32768u + u,  vh + u);
            cp16(sbuf + 49152u + u,  vl + u);
        }
    };

    {
        const char* qh = (const char*)(g_qb_hi + (((size_t)(b*H_ + h) * (S_/128) + qt) << 14));
        const char* ql = (const char*)(g_qb_lo + (((size_t)(b*H_ + h) * (S_/128) + qt) << 14));
        #pragma unroll
        for (int j = 0; j < 8; j++) {
            uint32_t u = (uint32_t)(tid + j * 256) * 16u;
            cp16(sb + FQHI + u, qh + u);
            cp16(sb + FQLO + u, ql + u);
        }
        prefetch_kv(0, 0);
        asm volatile("cp.async.commit_group;" ::: "memory");
    }
    if (tid < 128) { m_s[tid] = -1e30f; l_s[tid] = 0.f; }

    const int pwm = (warp >> 2) * 64;
    const int pwn = (warp & 3) * 32;
    float acc[4][4][4];
    #pragma unroll
    for (int t = 0; t < 4; t++)
        #pragma unroll
        for (int u = 0; u < 4; u++)
            #pragma unroll
            for (int j = 0; j < 4; j++) acc[t][u][j] = 0.f;

    const int wm = (warp >> 1) * 32;
    const int wn = (warp & 1) * 32;
    const int wcol = warp & 1;

    const int NK = 2 * qt + 2;
    for (int kt = 0; kt < NK; kt++) {
        const int k0 = kt * 64;
        asm volatile("cp.async.wait_group 0;" ::: "memory");
        __syncthreads();
        const uint32_t kvs = sb + FKV0 + (uint32_t)(kt & 1) * 65536u;

        // ---- S = Q @ K^T (3-term) ----
        float sacc[2][4][4];
        #pragma unroll
        for (int t = 0; t < 2; t++)
            #pragma unroll
            for (int u = 0; u < 4; u++)
                #pragma unroll
                for (int j = 0; j < 4; j++) sacc[t][u][j] = 0.f;

        #pragma unroll
        for (int ks = 0; ks < 8; ks++) {
            uint32_t qhi[2][4], qlo[2][4], khi[2][4], klo[2][4];
            #pragma unroll
            for (int t = 0; t < 2; t++) {
                int mbb = (wm >> 3) + 2*t + selAm;
                int kbb = 2*ks + selAk;
                uint32_t off = (uint32_t)((mbb * 16 + kbb) * 128 + rrow * 16);
                ldsm_x4(qhi[t], sb + FQHI + off);
                ldsm_x4(qlo[t], sb + FQLO + off);
            }
            #pragma unroll
            for (int u2 = 0; u2 < 2; u2++) {
                int nbb = (wn >> 3) + 2*u2 + selBn;
                int kbb = 2*ks + selBk;
                uint32_t off = (uint32_t)((nbb * 16 + kbb) * 128 + rrow * 16);
                ldsm_x4(khi[u2], kvs + off);
                ldsm_x4(klo[u2], kvs + 16384u + off);
            }
            #pragma unroll
            for (int t = 0; t < 2; t++)
                #pragma unroll
                for (int u = 0; u < 4; u++) {
                    const uint32_t* kh = &khi[u >> 1][(u & 1) * 2];
                    const uint32_t* kl = &klo[u >> 1][(u & 1) * 2];
                    mma_f16(sacc[t][u], qhi[t], kh);
                    mma_f16(sacc[t][u], qlo[t], kh);
                    mma_f16(sacc[t][u], qhi[t], kl);
                }
        }

        // ---- register softmax: scale + mask + quad row-max ----
        const bool needmask = (kt >= 2 * qt);
        #pragma unroll
        for (int t = 0; t < 2; t++) {
            int r1 = wm + t * 16 + gr;
            float m1 = -1e30f, m2 = -1e30f;
            #pragma unroll
            for (int u = 0; u < 4; u++) {
                int c0 = wn + u * 8 + qq * 2;
                float s0 = sacc[t][u][0] * scale;
                float s1 = sacc[t][u][1] * scale;
                float s2 = sacc[t][u][2] * scale;
                float s3 = sacc[t][u][3] * scale;
                if (needmask) {
                    if (k0 + c0     > q0 + r1)     s0 = -1e30f;
                    if (k0 + c0 + 1 > q0 + r1)     s1 = -1e30f;
                    if (k0 + c0     > q0 + r1 + 8) s2 = -1e30f;
                    if (k0 + c0 + 1 > q0 + r1 + 8) s3 = -1e30f;
                }
                sacc[t][u][0] = s0; sacc[t][u][1] = s1;
                sacc[t][u][2] = s2; sacc[t][u][3] = s3;
                m1 = fmaxf(m1, fmaxf(s0, s1));
                m2 = fmaxf(m2, fmaxf(s2, s3));
            }
            m1 = fmaxf(m1, __shfl_xor_sync(0xffffffffu, m1, 1));
            m1 = fmaxf(m1, __shfl_xor_sync(0xffffffffu, m1, 2));
            m2 = fmaxf(m2, __shfl_xor_sync(0xffffffffu, m2, 1));
            m2 = fmaxf(m2, __shfl_xor_sync(0xffffffffu, m2, 2));
            if (qq == 0) {
                part[r1*2 + wcol]     = m1;
                part[(r1+8)*2 + wcol] = m2;
            }
        }
        __syncthreads();   // all warps past QK of kt (hence past PV of kt-1)

        // prefetch next KV tile (overlaps softmax + PV)
        if (kt + 1 < NK) {
            prefetch_kv(kt + 1, (kt + 1) & 1);
            asm volatile("cp.async.commit_group;" ::: "memory");
        }

        if (tid < 128) {
            float mx = fmaxf(part[tid*2], part[tid*2+1]);
            float mo = m_s[tid];
            float mn = fmaxf(mo, mx);
            m_s[tid]  = mn;
            al_s[tid] = __expf(mo - mn);
        }
        __syncthreads();

        // ---- exp in registers + quad row-sum + P(hi) to blocked smem ----
        {
            __half* ph = (__half*)(fs + FPBH);
            #pragma unroll
            for (int t = 0; t < 2; t++) {
                int r1 = wm + t * 16 + gr;
                int r2 = r1 + 8;
                float mm1 = m_s[r1], mm2 = m_s[r2];
                float sum1 = 0.f, sum2 = 0.f;
                #pragma unroll
                for (int u = 0; u < 4; u++) {
                    float e0 = __expf(sacc[t][u][0] - mm1);
                    float e1 = __expf(sacc[t][u][1] - mm1);
                    float e2 = __expf(sacc[t][u][2] - mm2);
                    float e3 = __expf(sacc[t][u][3] - mm2);
                    sum1 += e0 + e1;
                    sum2 += e2 + e3;
                    int cb = (wn >> 3) + u;
                    uint32_t o1 = (uint32_t)((((r1 >> 3) * 8 + cb) << 6) + (r1 & 7) * 8 + qq * 2);
                    uint32_t o2 = (uint32_t)((((r2 >> 3) * 8 + cb) << 6) + (r2 & 7) * 8 + qq * 2);
                    *(uint32_t*)(ph + o1) = pack_f16_pair(e0, e1);
                    *(uint32_t*)(ph + o2) = pack_f16_pair(e2, e3);
                }
                sum1 += __shfl_xor_sync(0xffffffffu, sum1, 1);
                sum1 += __shfl_xor_sync(0xffffffffu, sum1, 2);
                sum2 += __shfl_xor_sync(0xffffffffu, sum2, 1);
                sum2 += __shfl_xor_sync(0xffffffffu, sum2, 2);
                if (qq == 0) {
                    part[r1*2 + wcol] = sum1;
                    part[r2*2 + wcol] = sum2;
                }
            }
        }
        __syncthreads();
        if (tid < 128) l_s[tid] = l_s[tid] * al_s[tid] + part[tid*2] + part[tid*2+1];

        // ---- rescale PV accumulators ----
        #pragma unroll
        for (int t = 0; t < 4; t++) {
            float a1 = al_s[pwm + t*16 + gr];
            float a2 = al_s[pwm + t*16 + gr + 8];
            #pragma unroll
            for (int u = 0; u < 4; u++) {
                acc[t][u][0] *= a1; acc[t][u][1] *= a1;
                acc[t][u][2] *= a2; acc[t][u][3] *= a2;
            }
        }

        // ---- O += P @ V (2-term: Ph*(Vh+Vl)) ----
        #pragma unroll
        for (int ks = 0; ks < 4; ks++) {
            uint32_t phiF[4][4], vhiF[2][4], vloF[2][4];
            #pragma unroll
            for (int t = 0; t < 4; t++) {
                int mbb = (pwm >> 3) + 2*t + selAm;
                int kbb = 2*ks + selAk;
                uint32_t off = (uint32_t)((mbb * 8 + kbb) * 128 + rrow * 16);
                ldsm_x4(phiF[t], sb + FPBH + off);
            }
            #pragma unroll
            for (int u2 = 0; u2 < 2; u2++) {
                int nbb = (pwn >> 3) + 2*u2 + selBn;
                int kbb = 2*ks + selBk;
                uint32_t off = (uint32_t)((nbb * 8 + kbb) * 128 + rrow * 16);
                ldsm_x4(vhiF[u2], kvs + 32768u + off);
                ldsm_x4(vloF[u2], kvs + 49152u + off);
            }
            #pragma unroll
            for (int t = 0; t < 4; t++)
                #pragma unroll
                for (int u = 0; u < 4; u++) {
                    const uint32_t* vh = &vhiF[u >> 1][(u & 1) * 2];
                    const uint32_t* vl = &vloF[u >> 1][(u & 1) * 2];
                    mma_f16(acc[t][u], phiF[t], vh);
                    mma_f16(acc[t][u], phiF[t], vl);
                }
        }
    }

    __syncthreads();

    // ---- epilogue: normalize + write blocked fp16 hi (O-proj A-side) ----
    {
        const int KB = HD_ >> 3;
        #pragma unroll
        for (int t = 0; t < 4; t++) {
            int r1 = pwm + t*16 + gr;
            float inv1 = 1.f / l_s[r1];
            float inv2 = 1.f / l_s[r1 + 8];
            int grow1 = b*S_ + q0 + r1;
            int grow2 = grow1 + 8;
            #pragma unroll
            for (int u = 0; u < 4; u++) {
                int col = h * D_ + pwn + u*8 + qq * 2;
                int kb = col >> 3, cw = col & 7;
                size_t o1 = (((size_t)(grow1 >> 3) * KB + kb) << 6) + (size_t)(grow1 & 7) * 8 + cw;
                size_t o2 = (((size_t)(grow2 >> 3) * KB + kb) << 6) + (size_t)(grow2 & 7) * 8 + cw;
                *(uint32_t*)(g_attn_hi + o1) = pack_f16_pair(acc[t][u][0]*inv1, acc[t][u][1]*inv1);
                *(uint32_t*)(g_attn_hi + o2) = pack_f16_pair(acc[t][u][2]*inv2, acc[t][u][3]*inv2);
            }
        }
    }
}

// ---------------- launch ----------------
extern "C" void kernel_launch(void* const* d_in, const int* in_sizes, int n_in,
                              void* d_out, int out_size) {
    const float* hidden = (const float*)d_in[0];
    const int*   pos    = (const int*)  d_in[2];
    const float* Wq     = (const float*)d_in[3];
    const float* bq     = (const float*)d_in[4];
    const float* Wk     = (const float*)d_in[5];
    const float* bk     = (const float*)d_in[6];
    const float* Wv     = (const float*)d_in[7];
    const float* bv     = (const float*)d_in[8];
    const float* Wo     = (const float*)d_in[9];
    float* out = (float*)d_out;

    __half *hhi, *wqh, *wql, *wkh, *wkl, *wvh, *wvl, *woh, *wol, *ahi;
    __half *qbh, *qbl, *kbh, *kbl2, *vbh, *vbl;
    cudaGetSymbolAddress((void**)&hhi, g_hid_hi);
    cudaGetSymbolAddress((void**)&wqh, g_wq_hi);
    cudaGetSymbolAddress((void**)&wql, g_wq_lo);
    cudaGetSymbolAddress((void**)&wkh, g_wk_hi);
    cudaGetSymbolAddress((void**)&wkl, g_wk_lo);
    cudaGetSymbolAddress((void**)&wvh, g_wv_hi);
    cudaGetSymbolAddress((void**)&wvl, g_wv_lo);
    cudaGetSymbolAddress((void**)&woh, g_wo_hi);
    cudaGetSymbolAddress((void**)&wol, g_wo_lo);
    cudaGetSymbolAddress((void**)&ahi, g_attn_hi);
    cudaGetSymbolAddress((void**)&qbh, g_qb_hi);
    cudaGetSymbolAddress((void**)&qbl, g_qb_lo);
    cudaGetSymbolAddress((void**)&kbh, g_kb_hi);
    cudaGetSymbolAddress((void**)&kbl2, g_kb_lo);
    cudaGetSymbolAddress((void**)&vbh, g_vb_hi);
    cudaGetSymbolAddress((void**)&vbl, g_vb_lo);

    const size_t gsmem = 98304;
    cudaFuncSetAttribute(f16x2_gemm_kernel<0>, cudaFuncAttributeMaxDynamicSharedMemorySize, (int)gsmem);
    cudaFuncSetAttribute(f16x2_gemm_kernel<1>, cudaFuncAttributeMaxDynamicSharedMemorySize, (int)gsmem);
    cudaFuncSetAttribute(f16x2_gemm_kernel<2>, cudaFuncAttributeMaxDynamicSharedMemorySize, (int)gsmem);
    cudaFuncSetAttribute(f16x2_gemm_kernel<3>, cudaFuncAttributeMaxDynamicSharedMemorySize, (int)gsmem);
    cudaFuncSetAttribute(flash_mma_kernel, cudaFuncAttributeMaxDynamicSharedMemorySize, (int)FTOT);

    rope_table_kernel<<<(S_*(D_/2) + 255)/256, 256>>>();
    {
        int n = M_ * (E_ >> 3);
        split_blocked_kernel<<<(n + 255)/256, 256>>>(hidden, hhi, M_, E_);
    }
    wtrans_split_kernel<<<dim3(HD_/32,   E_/32), dim3(32,8)>>>(Wq, wqh, wql, E_,  HD_);
    wtrans_split_kernel<<<dim3(KVHD_/32, E_/32), dim3(32,8)>>>(Wk, wkh, wkl, E_,  KVHD_);
    wtrans_split_kernel<<<dim3(KVHD_/32, E_/32), dim3(32,8)>>>(Wv, wvh, wvl, E_,  KVHD_);

    f16x2_gemm_kernel<1><<<dim3(HD_/128,   M_/128), 256, gsmem>>>(hhi, wqh, wql, bq, nullptr, pos, qbh, qbl, M_, HD_,   E_);
    f16x2_gemm_kernel<2><<<dim3(KVHD_/128, M_/128), 256, gsmem>>>(hhi, wkh, wkl, bk, nullptr, pos, kbh, kbl2, M_, KVHD_, E_);
    f16x2_gemm_kernel<3><<<dim3(KVHD_/128, M_/128), 256, gsmem>>>(hhi, wvh, wvl, bv, nullptr, pos, vbh, vbl, M_, KVHD_, E_);

    flash_mma_kernel<<<dim3(S_/128, H_, B_), 256, FTOT>>>();

    wtrans_split_kernel<<<dim3(E_/32, HD_/32), dim3(32,8)>>>(Wo, woh, wol, HD_, E_);
    f16x2_gemm_kernel<0><<<dim3(E_/128, M_/128), 256, gsmem>>>(ahi, woh, wol, nullptr, out, nullptr, nullptr, nullptr, M_, E_, HD_);
}

// round 11
// speedup vs baseline: 1.3945x; 1.0210x over previous
#include <cuda_runtime.h>
#include <cuda_fp16.h>
#include <math.h>
#include <stdint.h>

#define B_    2
#define S_    2048
#define E_    4096
#define H_    32
#define KVH_  8
#define D_    128
#define HD_   (H_*D_)      // 4096
#define KVHD_ (KVH_*D_)    // 1024
#define M_    (B_*S_)      // 4096

// ---------------- scratch (no allocations allowed) ----------------
__device__ float g_cos [S_*(D_/2)];
__device__ float g_sin [S_*(D_/2)];

__device__ __align__(16) __half g_hid_hi [(size_t)M_*E_];
__device__ __align__(16) __half g_wq_hi  [(size_t)HD_*E_];
__device__ __align__(16) __half g_wq_lo  [(size_t)HD_*E_];
__device__ __align__(16) __half g_wk_hi  [(size_t)KVHD_*E_];
__device__ __align__(16) __half g_wk_lo  [(size_t)KVHD_*E_];
__device__ __align__(16) __half g_wv_hi  [(size_t)KVHD_*E_];
__device__ __align__(16) __half g_wv_lo  [(size_t)KVHD_*E_];
__device__ __align__(16) __half g_wo_hi  [(size_t)E_*HD_];
__device__ __align__(16) __half g_wo_lo  [(size_t)E_*HD_];
__device__ __align__(16) __half g_attn_hi[(size_t)M_*HD_];

__device__ __align__(16) __half g_qb_hi[(size_t)B_*H_*S_*D_];
__device__ __align__(16) __half g_qb_lo[(size_t)B_*H_*S_*D_];
__device__ __align__(16) __half g_kb_hi[(size_t)B_*KVH_*S_*D_];
__device__ __align__(16) __half g_kb_lo[(size_t)B_*KVH_*S_*D_];
__device__ __align__(16) __half g_vb_hi[(size_t)B_*KVH_*S_*D_];
__device__ __align__(16) __half g_vb_lo[(size_t)B_*KVH_*S_*D_];

// ---------------- helpers ----------------
__device__ __forceinline__ uint32_t smem_u32(const void* p) {
    uint32_t a;
    asm("{ .reg .u64 t; cvta.to.shared.u64 t, %1; cvt.u32.u64 %0, t; }" : "=r"(a) : "l"(p));
    return a;
}
__device__ __forceinline__ void ldsm_x4(uint32_t* r, uint32_t a) {
    asm volatile("ldmatrix.sync.aligned.m8n8.x4.shared.b16 {%0,%1,%2,%3}, [%4];"
                 : "=r"(r[0]), "=r"(r[1]), "=r"(r[2]), "=r"(r[3]) : "r"(a));
}
__device__ __forceinline__ void mma_f16(float* c, const uint32_t* a, const uint32_t* b) {
    asm volatile("mma.sync.aligned.m16n8k16.row.col.f32.f16.f16.f32 "
                 "{%0,%1,%2,%3}, {%4,%5,%6,%7}, {%8,%9}, {%0,%1,%2,%3};"
                 : "+f"(c[0]), "+f"(c[1]), "+f"(c[2]), "+f"(c[3])
                 : "r"(a[0]), "r"(a[1]), "r"(a[2]), "r"(a[3]), "r"(b[0]), "r"(b[1]));
}
__device__ __forceinline__ void cp16(uint32_t saddr, const void* g) {
    asm volatile("cp.async.cg.shared.global [%0], [%1], 16;" :: "r"(saddr), "l"(g) : "memory");
}
__device__ __forceinline__ uint32_t pack_f16_split(float x0, float x1, uint32_t& lo_out) {
    __half h0 = __float2half_rn(x0);
    __half h1 = __float2half_rn(x1);
    __half l0 = __float2half_rn(x0 - __half2float(h0));
    __half l1 = __float2half_rn(x1 - __half2float(h1));
    __half2 hp = __halves2half2(h0, h1);
    __half2 lp = __halves2half2(l0, l1);
    lo_out = *reinterpret_cast<uint32_t*>(&lp);
    return *reinterpret_cast<uint32_t*>(&hp);
}
__device__ __forceinline__ uint32_t pack_f16_pair(float x0, float x1) {
    __half2 hp = __halves2half2(__float2half_rn(x0), __float2half_rn(x1));
    return *reinterpret_cast<uint32_t*>(&hp);
}

// ---------------- unified prep kernel: rope table + hid split + 4 weight transposes ----------------
// segment block counts
#define RT_B   ((S_*(D_/2))/256)                 // 512
#define SP_B   ((M_*(E_>>3))/256)                // 8192
#define WQ_B   ((HD_/32)*(E_/32))                // 16384
#define WK_B   ((KVHD_/32)*(E_/32))              // 4096
#define WV_B   WK_B
#define WO_B   ((E_/32)*(HD_/32))                // 16384
#define PREP_TOTAL (RT_B + SP_B + WQ_B + WK_B + WV_B + WO_B)

__device__ __forceinline__ void do_wtrans(const float* __restrict__ W,
                                          __half* __restrict__ Thi, __half* __restrict__ Tlo,
                                          int Kdim, int Ndim, int seg, int tid,
                                          float (*tile)[33]) {
    int nTiles = Ndim / 32;
    int bx = seg % nTiles, by = seg / nTiles;
    int n0 = bx * 32, k0 = by * 32;
    int tx = tid & 31, ty = tid >> 5;   // (32, 8)
    #pragma unroll
    for (int dy = 0; dy < 32; dy += 8)
        tile[ty + dy][tx] = W[(size_t)(k0 + ty + dy) * Ndim + n0 + tx];
    __syncthreads();
    int KB = Kdim >> 3;
    #pragma unroll
    for (int dy = 0; dy < 32; dy += 8) {
        int n = n0 + ty + dy, k = k0 + tx;
        float x = tile[tx][ty + dy];
        __half h = __float2half_rn(x);
        __half l = __float2half_rn(x - __half2float(h));
        size_t off = (((size_t)(n >> 3) * KB + (k >> 3)) << 6) + (size_t)(n & 7) * 8 + (k & 7);
        Thi[off] = h;
        Tlo[off] = l;
    }
}

__global__ __launch_bounds__(256)
void prep_all_kernel(const float* __restrict__ hidden,
                     const float* __restrict__ Wq, const float* __restrict__ Wk,
                     const float* __restrict__ Wv, const float* __restrict__ Wo) {
    __shared__ float tile[32][33];
    const int tid = threadIdx.x;
    int blk = blockIdx.x;

    if (blk < RT_B) {
        int idx = blk * 256 + tid;
        int t = idx / (D_/2);
        int i = idx % (D_/2);
        double inv = exp(-((double)(2*i) / (double)D_) * log(10000.0));
        double ang = (double)t * inv;
        g_cos[idx] = (float)cos(ang);
        g_sin[idx] = (float)sin(ang);
        return;
    }
    blk -= RT_B;
    if (blk < SP_B) {
        int idx = blk * 256 + tid;
        const int KB = E_ >> 3;
        int row = idx / KB, kb = idx % KB;
        const float* src = hidden + (size_t)row * E_ + kb * 8;
        float4 v0 = *(const float4*)src;
        float4 v1 = *(const float4*)(src + 4);
        uint32_t hw[4];
        hw[0] = pack_f16_pair(v0.x, v0.y);
        hw[1] = pack_f16_pair(v0.z, v0.w);
        hw[2] = pack_f16_pair(v1.x, v1.y);
        hw[3] = pack_f16_pair(v1.z, v1.w);
        size_t off = (((size_t)(row >> 3) * KB + kb) << 6) + (size_t)(row & 7) * 8;
        *(uint4*)(g_hid_hi + off) = make_uint4(hw[0], hw[1], hw[2], hw[3]);
        return;
    }
    blk -= SP_B;
    if (blk < WQ_B) { do_wtrans(Wq, g_wq_hi, g_wq_lo, E_,  HD_, blk, tid, tile); return; }
    blk -= WQ_B;
    if (blk < WK_B) { do_wtrans(Wk, g_wk_hi, g_wk_lo, E_,  KVHD_, blk, tid, tile); return; }
    blk -= WK_B;
    if (blk < WV_B) { do_wtrans(Wv, g_wv_hi, g_wv_lo, E_,  KVHD_, blk, tid, tile); return; }
    blk -= WV_B;
    do_wtrans(Wo, g_wo_hi, g_wo_lo, HD_, E_, blk, tid, tile);
}

// ---------------- 2xFP16 mma.sync GEMM (128x128 tile, k-chunk 64, 3-stage) ----------------
// D = Ah*(Bh+Bl). Stage: Ahi 16K | Bhi 16K | Blo 16K = 48KB, 3 stages.
template<int MODE>
__global__ __launch_bounds__(256, 1)
void f16x2_gemm_kernel(const __half* __restrict__ Ahi,
                       const __half* __restrict__ Bhi, const __half* __restrict__ Blo,
                       const float* __restrict__ bias, float* __restrict__ C,
                       const int* __restrict__ pos,
                       __half* __restrict__ outHi, __half* __restrict__ outLo,
                       int Mdim, int Ndim, int Kdim) {
    extern __shared__ char smc[];
    const uint32_t sbase = smem_u32(smc);
    const int tid  = threadIdx.x;
    const int warp = tid >> 5, lane = tid & 31;
    const int KB   = Kdim >> 3;
    const int mb0  = blockIdx.y * 16;
    const int nb0  = blockIdx.x * 16;
    const int NC   = Kdim >> 6;

    float acc[4][4][4];
    #pragma unroll
    for (int t = 0; t < 4; t++)
        #pragma unroll
        for (int u = 0; u < 4; u++)
            #pragma unroll
            for (int j = 0; j < 4; j++) acc[t][u][j] = 0.f;

    const char* pAhi = (const char*)Ahi;
    const char* pBhi = (const char*)Bhi;
    const char* pBlo = (const char*)Blo;

    auto prefetch = [&](int chunk, int st) {
        uint32_t sbuf = sbase + (uint32_t)st * 49152u;
        int kb0 = chunk << 3;
        #pragma unroll
        for (int j = 0; j < 4; j++) {
            int u = tid + j * 256;
            int rb = u >> 6, kb = (u >> 3) & 7, w = u & 7;
            size_t gA = ((size_t)(mb0 + rb) * KB + (kb0 + kb)) * 128u + (size_t)w * 16u;
            size_t gB = ((size_t)(nb0 + rb) * KB + (kb0 + kb)) * 128u + (size_t)w * 16u;
            uint32_t so = (uint32_t)(((rb * 8 + kb) * 8 + w) * 16);
            cp16(sbuf + so,           pAhi + gA);
            cp16(sbuf + 16384u + so,  pBhi + gB);
            cp16(sbuf + 32768u + so,  pBlo + gB);
        }
    };

    const int wmb   = (warp >> 2) * 8;
    const int wnb   = (warp & 3) * 4;
    const int selAm = (lane >> 3) & 1;
    const int selAk = (lane >> 3) >> 1;
    const int selBn = (lane >> 4) & 1;
    const int selBk = (lane >> 3) & 1;
    const int rrow  = lane & 7;

    prefetch(0, 0);
    asm volatile("cp.async.commit_group;" ::: "memory");
    prefetch(1, 1);
    asm volatile("cp.async.commit_group;" ::: "memory");

    for (int i = 0; i < NC; i++) {
        asm volatile("cp.async.wait_group 1;" ::: "memory");  // stage i ready; i+1 may pend
        __syncthreads();
        if (i + 2 < NC) {
            int st = i + 2;
            prefetch(st, st % 3);
            asm volatile("cp.async.commit_group;" ::: "memory");
        } else {
            // keep group count consistent: commit empty group
            asm volatile("cp.async.commit_group;" ::: "memory");
        }
        uint32_t sbuf = sbase + (uint32_t)(i % 3) * 49152u;
        #pragma unroll
        for (int ks = 0; ks < 4; ks++) {
            uint32_t ahi[4][4], bhi[2][4], blo[2][4];
            #pragma unroll
            for (int t = 0; t < 4; t++) {
                int mbb = wmb + 2*t + selAm;
                int kbb = 2*ks + selAk;
                uint32_t off = (uint32_t)((mbb * 8 + kbb) * 128 + rrow * 16);
                ldsm_x4(ahi[t], sbuf + off);
            }
            #pragma unroll
            for (int u2 = 0; u2 < 2; u2++) {
                int nbb = wnb + 2*u2 + selBn;
                int kbb = 2*ks + selBk;
                uint32_t off = (uint32_t)((nbb * 8 + kbb) * 128 + rrow * 16);
                ldsm_x4(bhi[u2], sbuf + 16384u + off);
                ldsm_x4(blo[u2], sbuf + 32768u + off);
            }
            #pragma unroll
            for (int t = 0; t < 4; t++)
                #pragma unroll
                for (int u = 0; u < 4; u++) {
                    const uint32_t* bh = &bhi[u >> 1][(u & 1) * 2];
                    const uint32_t* bl = &blo[u >> 1][(u & 1) * 2];
                    mma_f16(acc[t][u], ahi[t], bh);
                    mma_f16(acc[t][u], ahi[t], bl);
                }
        }
    }

    const int mrow = mb0 * 8 + (warp >> 2) * 64;
    const int ncol = nb0 * 8 + (warp & 3) * 32;
    const int gg = lane >> 2, qq = lane & 3;

    if (MODE == 0) {
        #pragma unroll
        for (int t = 0; t < 4; t++) {
            #pragma unroll
            for (int u = 0; u < 4; u++) {
                int row = mrow + t * 16 + gg;
                int col = ncol + u * 8 + qq * 2;
                float2 b2 = make_float2(0.f, 0.f);
                if (bias) b2 = *(const float2*)(bias + col);
                float2 v0 = make_float2(acc[t][u][0] + b2.x, acc[t][u][1] + b2.y);
                float2 v1 = make_float2(acc[t][u][2] + b2.x, acc[t][u][3] + b2.y);
                *(float2*)(C + (size_t)row * Ndim + col)       = v0;
                *(float2*)(C + (size_t)(row + 8) * Ndim + col) = v1;
            }
        }
        return;
    }

    // ---- fused epilogues: stage acc+bias to smem fp32 [128 rows][132 pitch] ----
    float* st = (float*)smc;
    __syncthreads();
    {
        const int lrow = (warp >> 2) * 64;
        const int lcol = (warp & 3) * 32;
        #pragma unroll
        for (int t = 0; t < 4; t++) {
            #pragma unroll
            for (int u = 0; u < 4; u++) {
                int r = lrow + t * 16 + gg;
                int c = lcol + u * 8 + qq * 2;
                float2 b2 = *(const float2*)(bias + nb0 * 8 + c);
                st[r * 132 + c]           = acc[t][u][0] + b2.x;
                st[r * 132 + c + 1]       = acc[t][u][1] + b2.y;
                st[(r + 8) * 132 + c]     = acc[t][u][2] + b2.x;
                st[(r + 8) * 132 + c + 1] = acc[t][u][3] + b2.y;
            }
        }
    }
    __syncthreads();

    if (MODE == 1 || MODE == 2) {
        const int hh = blockIdx.x;
        #pragma unroll
        for (int j = 0; j < 4; j++) {
            int idx = tid + j * 256;
            int kbl = idx & 7;
            int r   = idx >> 3;
            int token = blockIdx.y * 128 + r;
            int b = token >> 11;
            int s = token & (S_ - 1);
            int p = pos[b * S_ + s];
            int i0 = kbl * 8;
            float y1[8], y2[8];
            #pragma unroll
            for (int jj = 0; jj < 8; jj++) {
                float x1 = st[r * 132 + i0 + jj];
                float x2 = st[r * 132 + 64 + i0 + jj];
                float c  = g_cos[p * 64 + i0 + jj];
                float sn = g_sin[p * 64 + i0 + jj];
                y1[jj] = x1 * c - x2 * sn;
                y2[jj] = x2 * c + x1 * sn;
            }
            uint32_t h1[4], l1[4], h2[4], l2[4];
            #pragma unroll
            for (int jj = 0; jj < 4; jj++) {
                h1[jj] = pack_f16_split(y1[2*jj], y1[2*jj+1], l1[jj]);
                h2[jj] = pack_f16_split(y2[2*jj], y2[2*jj+1], l2[jj]);
            }
            size_t dbase;
            if (MODE == 1) {
                int qt = s >> 7, sbw = (s >> 3) & 15;
                dbase = ((((size_t)(b * H_ + hh) * (S_/128) + qt) * 16 + sbw) * 16);
            } else {
                int kt = s >> 6, sbw = (s >> 3) & 7;
                dbase = ((((size_t)(b * KVH_ + hh) * (S_/64) + kt) * 8 + sbw) * 16);
            }
            int rr = s & 7;
            size_t o1 = (dbase + kbl)     * 64 + (size_t)rr * 8;
            size_t o2 = (dbase + kbl + 8) * 64 + (size_t)rr * 8;
            *(uint4*)(outHi + o1) = make_uint4(h1[0], h1[1], h1[2], h1[3]);
            *(uint4*)(outLo + o1) = make_uint4(l1[0], l1[1], l1[2], l1[3]);
            *(uint4*)(outHi + o2) = make_uint4(h2[0], h2[1], h2[2], h2[3]);
            *(uint4*)(outLo + o2) = make_uint4(l2[0], l2[1], l2[2], l2[3]);
        }
    } else {
        const int kvh = blockIdx.x;
        const int token0 = blockIdx.y * 128;
        const int b = token0 >> 11;
        const int sbase0 = token0 & (S_ - 1);
        #pragma unroll
        for (int j = 0; j < 8; j++) {
            int idx = tid + j * 256;
            int dr  = idx & 7;
            int sbw = (idx >> 3) & 7;
            int db  = (idx >> 6) & 15;
            int ktl = idx >> 10;
            int d = db * 8 + dr;
            int sl = ktl * 64 + sbw * 8;
            uint32_t hw[4], lw[4];
            #pragma unroll
            for (int jj = 0; jj < 4; jj++) {
                float x0 = st[(sl + 2*jj)     * 132 + d];
                float x1 = st[(sl + 2*jj + 1) * 132 + d];
                hw[jj] = pack_f16_split(x0, x1, lw[jj]);
            }
            int s = sbase0 + sl;
            int kt = s >> 6;
            size_t off = (((((size_t)(b * KVH_ + kvh) * (S_/64) + kt) * 16 + db) * 8 + sbw) * 64)
                       + (size_t)dr * 8;
            *(uint4*)(outHi + off) = make_uint4(hw[0], hw[1], hw[2], hw[3]);
            *(uint4*)(outLo + off) = make_uint4(lw[0], lw[1], lw[2], lw[3]);
        }
    }
}

// ---------------- mma flash attention: double-buffered KV, register softmax ----------------
// QK 3-term; PV 2-term. smem: Q 64K | KV stage0 64K | KV stage1 64K | Phi 16K | stats
#define FQHI   0u
#define FQLO   32768u
#define FKV0   65536u
#define FPBH   196608u
#define FMS    212992u
#define FLS    213504u
#define FALS   214016u
#define FPART  214528u
#define FTOT   215552u

__global__ __launch_bounds__(256, 1)
void flash_mma_kernel() {
    extern __shared__ char fs[];
    const uint32_t sb = smem_u32(fs);
    float* m_s  = (float*)(fs + FMS);
    float* l_s  = (float*)(fs + FLS);
    float* al_s = (float*)(fs + FALS);
    float* part = (float*)(fs + FPART);

    const int tid  = threadIdx.x;
    const int warp = tid >> 5, lane = tid & 31;
    const int qt = (S_/128 - 1) - blockIdx.x;
    const int h = blockIdx.y, b = blockIdx.z;
    const int q0 = qt * 128;
    const int kvh = h >> 2;
    const float scale = 0.08838834764831845f;

    const int selAm = (lane >> 3) & 1;
    const int selAk = (lane >> 3) >> 1;
    const int selBn = (lane >> 4) & 1;
    const int selBk = (lane >> 3) & 1;
    const int rrow  = lane & 7;
    const int gr = lane >> 2, qq = lane & 3;

    const size_t kvbase = (size_t)(b*KVH_ + kvh) * (S_/64);
    auto prefetch_kv = [&](int kt, int st) {
        size_t tb = (kvbase + kt) << 13;
        uint32_t sbuf = sb + FKV0 + (uint32_t)st * 65536u;
        const char* kh = (const char*)(g_kb_hi + tb);
        const char* kl = (const char*)(g_kb_lo + tb);
        const char* vh = (const char*)(g_vb_hi + tb);
        const char* vl = (const char*)(g_vb_lo + tb);
        #pragma unroll
        for (int j = 0; j < 4; j++) {
            uint32_t u = (uint32_t)(tid + j * 256) * 16u;
            cp16(sbuf + u,           kh + u);
            cp16(sbuf + 16384u + u,  kl + u);
            cp16(sbuf + 32768u + u,  vh + u);
            cp16(sbuf + 49152u + u,  vl + u);
        }
    };

    {
        const char* qh = (const char*)(g_qb_hi + (((size_t)(b*H_ + h) * (S_/128) + qt) << 14));
        const char* ql = (const char*)(g_qb_lo + (((size_t)(b*H_ + h) * (S_/128) + qt) << 14));
        #pragma unroll
        for (int j = 0; j < 8; j++) {
            uint32_t u = (uint32_t)(tid + j * 256) * 16u;
            cp16(sb + FQHI + u, qh + u);
            cp16(sb + FQLO + u, ql + u);
        }
        prefetch_kv(0, 0);
        asm volatile("cp.async.commit_group;" ::: "memory");
    }
    if (tid < 128) { m_s[tid] = -1e30f; l_s[tid] = 0.f; }

    const int pwm = (warp >> 2) * 64;
    const int pwn = (warp & 3) * 32;
    float acc[4][4][4];
    #pragma unroll
    for (int t = 0; t < 4; t++)
        #pragma unroll
        for (int u = 0; u < 4; u++)
            #pragma unroll
            for (int j = 0; j < 4; j++) acc[t][u][j] = 0.f;

    const int wm = (warp >> 1) * 32;
    const int wn = (warp & 1) * 32;
    const int wcol = warp & 1;

    const int NK = 2 * qt + 2;
    for (int kt = 0; kt < NK; kt++) {
        const int k0 = kt * 64;
        asm volatile("cp.async.wait_group 0;" ::: "memory");
        __syncthreads();
        const uint32_t kvs = sb + FKV0 + (uint32_t)(kt & 1) * 65536u;

        float sacc[2][4][4];
        #pragma unroll
        for (int t = 0; t < 2; t++)
            #pragma unroll
            for (int u = 0; u < 4; u++)
                #pragma unroll
                for (int j = 0; j < 4; j++) sacc[t][u][j] = 0.f;

        #pragma unroll
        for (int ks = 0; ks < 8; ks++) {
            uint32_t qhi[2][4], qlo[2][4], khi[2][4], klo[2][4];
            #pragma unroll
            for (int t = 0; t < 2; t++) {
                int mbb = (wm >> 3) + 2*t + selAm;
                int kbb = 2*ks + selAk;
                uint32_t off = (uint32_t)((mbb * 16 + kbb) * 128 + rrow * 16);
                ldsm_x4(qhi[t], sb + FQHI + off);
                ldsm_x4(qlo[t], sb + FQLO + off);
            }
            #pragma unroll
            for (int u2 = 0; u2 < 2; u2++) {
                int nbb = (wn >> 3) + 2*u2 + selBn;
                int kbb = 2*ks + selBk;
                uint32_t off = (uint32_t)((nbb * 16 + kbb) * 128 + rrow * 16);
                ldsm_x4(khi[u2], kvs + off);
                ldsm_x4(klo[u2], kvs + 16384u + off);
            }
            #pragma unroll
            for (int t = 0; t < 2; t++)
                #pragma unroll
                for (int u = 0; u < 4; u++) {
                    const uint32_t* kh = &khi[u >> 1][(u & 1) * 2];
                    const uint32_t* kl = &klo[u >> 1][(u & 1) * 2];
                    mma_f16(sacc[t][u], qhi[t], kh);
                    mma_f16(sacc[t][u], qlo[t], kh);
                    mma_f16(sacc[t][u], qhi[t], kl);
                }
        }

        const bool needmask = (kt >= 2 * qt);
        #pragma unroll
        for (int t = 0; t < 2; t++) {
            int r1 = wm + t * 16 + gr;
            float m1 = -1e30f, m2 = -1e30f;
            #pragma unroll
            for (int u = 0; u < 4; u++) {
                int c0 = wn + u * 8 + qq * 2;
                float s0 = sacc[t][u][0] * scale;
                float s1 = sacc[t][u][1] * scale;
                float s2 = sacc[t][u][2] * scale;
                float s3 = sacc[t][u][3] * scale;
                if (needmask) {
                    if (k0 + c0     > q0 + r1)     s0 = -1e30f;
                    if (k0 + c0 + 1 > q0 + r1)     s1 = -1e30f;
                    if (k0 + c0     > q0 + r1 + 8) s2 = -1e30f;
                    if (k0 + c0 + 1 > q0 + r1 + 8) s3 = -1e30f;
                }
                sacc[t][u][0] = s0; sacc[t][u][1] = s1;
                sacc[t][u][2] = s2; sacc[t][u][3] = s3;
                m1 = fmaxf(m1, fmaxf(s0, s1));
                m2 = fmaxf(m2, fmaxf(s2, s3));
            }
            m1 = fmaxf(m1, __shfl_xor_sync(0xffffffffu, m1, 1));
            m1 = fmaxf(m1, __shfl_xor_sync(0xffffffffu, m1, 2));
            m2 = fmaxf(m2, __shfl_xor_sync(0xffffffffu, m2, 1));
            m2 = fmaxf(m2, __shfl_xor_sync(0xffffffffu, m2, 2));
            if (qq == 0) {
                part[r1*2 + wcol]     = m1;
                part[(r1+8)*2 + wcol] = m2;
            }
        }
        __syncthreads();

        if (kt + 1 < NK) {
            prefetch_kv(kt + 1, (kt + 1) & 1);
            asm volatile("cp.async.commit_group;" ::: "memory");
        }

        if (tid < 128) {
            float mx = fmaxf(part[tid*2], part[tid*2+1]);
            float mo = m_s[tid];
            float mn = fmaxf(mo, mx);
            m_s[tid]  = mn;
            al_s[tid] = __expf(mo - mn);
        }
        __syncthreads();

        {
            __half* ph = (__half*)(fs + FPBH);
            #pragma unroll
            for (int t = 0; t < 2; t++) {
                int r1 = wm + t * 16 + gr;
                int r2 = r1 + 8;
                float mm1 = m_s[r1], mm2 = m_s[r2];
                float sum1 = 0.f, sum2 = 0.f;
                #pragma unroll
                for (int u = 0; u < 4; u++) {
                    float e0 = __expf(sacc[t][u][0] - mm1);
                    float e1 = __expf(sacc[t][u][1] - mm1);
                    float e2 = __expf(sacc[t][u][2] - mm2);
                    float e3 = __expf(sacc[t][u][3] - mm2);
                    sum1 += e0 + e1;
                    sum2 += e2 + e3;
                    int cb = (wn >> 3) + u;
                    uint32_t o1 = (uint32_t)((((r1 >> 3) * 8 + cb) << 6) + (r1 & 7) * 8 + qq * 2);
                    uint32_t o2 = (uint32_t)((((r2 >> 3) * 8 + cb) << 6) + (r2 & 7) * 8 + qq * 2);
                    *(uint32_t*)(ph + o1) = pack_f16_pair(e0, e1);
                    *(uint32_t*)(ph + o2) = pack_f16_pair(e2, e3);
                }
                sum1 += __shfl_xor_sync(0xffffffffu, sum1, 1);
                sum1 += __shfl_xor_sync(0xffffffffu, sum1, 2);
                sum2 += __shfl_xor_sync(0xffffffffu, sum2, 1);
                sum2 += __shfl_xor_sync(0xffffffffu, sum2, 2);
                if (qq == 0) {
                    part[r1*2 + wcol] = sum1;
                    part[r2*2 + wcol] = sum2;
                }
            }
        }
        __syncthreads();
        if (tid < 128) l_s[tid] = l_s[tid] * al_s[tid] + part[tid*2] + part[tid*2+1];

        #pragma unroll
        for (int t = 0; t < 4; t++) {
            float a1 = al_s[pwm + t*16 + gr];
            float a2 = al_s[pwm + t*16 + gr + 8];
            #pragma unroll
            for (int u = 0; u < 4; u++) {
                acc[t][u][0] *= a1; acc[t][u][1] *= a1;
                acc[t][u][2] *= a2; acc[t][u][3] *= a2;
            }
        }

        #pragma unroll
        for (int ks = 0; ks < 4; ks++) {
            uint32_t phiF[4][4], vhiF[2][4], vloF[2][4];
            #pragma unroll
            for (int t = 0; t < 4; t++) {
                int mbb = (pwm >> 3) + 2*t + selAm;
                int kbb = 2*ks + selAk;
                uint32_t off = (uint32_t)((mbb * 8 + kbb) * 128 + rrow * 16);
                ldsm_x4(phiF[t], sb + FPBH + off);
            }
            #pragma unroll
            for (int u2 = 0; u2 < 2; u2++) {
                int nbb = (pwn >> 3) + 2*u2 + selBn;
                int kbb = 2*ks + selBk;
                uint32_t off = (uint32_t)((nbb * 8 + kbb) * 128 + rrow * 16);
                ldsm_x4(vhiF[u2], kvs + 32768u + off);
                ldsm_x4(vloF[u2], kvs + 49152u + off);
            }
            #pragma unroll
            for (int t = 0; t < 4; t++)
                #pragma unroll
                for (int u = 0; u < 4; u++) {
                    const uint32_t* vh = &vhiF[u >> 1][(u & 1) * 2];
                    const uint32_t* vl = &vloF[u >> 1][(u & 1) * 2];
                    mma_f16(acc[t][u], phiF[t], vh);
                    mma_f16(acc[t][u], phiF[t], vl);
                }
        }
    }

    __syncthreads();

    {
        const int KB = HD_ >> 3;
        #pragma unroll
        for (int t = 0; t < 4; t++) {
            int r1 = pwm + t*16 + gr;
            float inv1 = 1.f / l_s[r1];
            float inv2 = 1.f / l_s[r1 + 8];
            int grow1 = b*S_ + q0 + r1;
            int grow2 = grow1 + 8;
            #pragma unroll
            for (int u = 0; u < 4; u++) {
                int col = h * D_ + pwn + u*8 + qq * 2;
                int kb = col >> 3, cw = col & 7;
                size_t o1 = (((size_t)(grow1 >> 3) * KB + kb) << 6) + (size_t)(grow1 & 7) * 8 + cw;
                size_t o2 = (((size_t)(grow2 >> 3) * KB + kb) << 6) + (size_t)(grow2 & 7) * 8 + cw;
                *(uint32_t*)(g_attn_hi + o1) = pack_f16_pair(acc[t][u][0]*inv1, acc[t][u][1]*inv1);
                *(uint32_t*)(g_attn_hi + o2) = pack_f16_pair(acc[t][u][2]*inv2, acc[t][u][3]*inv2);
            }
        }
    }
}

// ---------------- launch ----------------
extern "C" void kernel_launch(void* const* d_in, const int* in_sizes, int n_in,
                              void* d_out, int out_size) {
    const float* hidden = (const float*)d_in[0];
    const int*   pos    = (const int*)  d_in[2];
    const float* Wq     = (const float*)d_in[3];
    const float* bq     = (const float*)d_in[4];
    const float* Wk     = (const float*)d_in[5];
    const float* bk     = (const float*)d_in[6];
    const float* Wv     = (const float*)d_in[7];
    const float* bv     = (const float*)d_in[8];
    const float* Wo     = (const float*)d_in[9];
    float* out = (float*)d_out;

    __half *hhi, *wqh, *wql, *wkh, *wkl, *wvh, *wvl, *woh, *wol, *ahi;
    __half *qbh, *qbl, *kbh, *kbl2, *vbh, *vbl;
    cudaGetSymbolAddress((void**)&hhi, g_hid_hi);
    cudaGetSymbolAddress((void**)&wqh, g_wq_hi);
    cudaGetSymbolAddress((void**)&wql, g_wq_lo);
    cudaGetSymbolAddress((void**)&wkh, g_wk_hi);
    cudaGetSymbolAddress((void**)&wkl, g_wk_lo);
    cudaGetSymbolAddress((void**)&wvh, g_wv_hi);
    cudaGetSymbolAddress((void**)&wvl, g_wv_lo);
    cudaGetSymbolAddress((void**)&woh, g_wo_hi);
    cudaGetSymbolAddress((void**)&wol, g_wo_lo);
    cudaGetSymbolAddress((void**)&ahi, g_attn_hi);
    cudaGetSymbolAddress((void**)&qbh, g_qb_hi);
    cudaGetSymbolAddress((void**)&qbl, g_qb_lo);
    cudaGetSymbolAddress((void**)&kbh, g_kb_hi);
    cudaGetSymbolAddress((void**)&kbl2, g_kb_lo);
    cudaGetSymbolAddress((void**)&vbh, g_vb_hi);
    cudaGetSymbolAddress((void**)&vbl, g_vb_lo);

    const size_t gsmem = 147456;   // 3 x 48KB stages
    cudaFuncSetAttribute(f16x2_gemm_kernel<0>, cudaFuncAttributeMaxDynamicSharedMemorySize, (int)gsmem);
    cudaFuncSetAttribute(f16x2_gemm_kernel<1>, cudaFuncAttributeMaxDynamicSharedMemorySize, (int)gsmem);
    cudaFuncSetAttribute(f16x2_gemm_kernel<2>, cudaFuncAttributeMaxDynamicSharedMemorySize, (int)gsmem);
    cudaFuncSetAttribute(f16x2_gemm_kernel<3>, cudaFuncAttributeMaxDynamicSharedMemorySize, (int)gsmem);
    cudaFuncSetAttribute(flash_mma_kernel, cudaFuncAttributeMaxDynamicSharedMemorySize, (int)FTOT);

    prep_all_kernel<<<PREP_TOTAL, 256>>>(hidden, Wq, Wk, Wv, Wo);

    f16x2_gemm_kernel<1><<<dim3(HD_/128,   M_/128), 256, gsmem>>>(hhi, wqh, wql, bq, nullptr, pos, qbh, qbl, M_, HD_,   E_);
    f16x2_gemm_kernel<2><<<dim3(KVHD_/128, M_/128), 256, gsmem>>>(hhi, wkh, wkl, bk, nullptr, pos, kbh, kbl2, M_, KVHD_, E_);
    f16x2_gemm_kernel<3><<<dim3(KVHD_/128, M_/128), 256, gsmem>>>(hhi, wvh, wvl, bv, nullptr, pos, vbh, vbl, M_, KVHD_, E_);

    flash_mma_kernel<<<dim3(S_/128, H_, B_), 256, FTOT>>>();

    f16x2_gemm_kernel<0><<<dim3(E_/128, M_/128), 256, gsmem>>>(ahi, woh, wol, nullptr, out, nullptr, nullptr, nullptr, M_, E_, HD_);
}

// round 13
// speedup vs baseline: 1.4221x; 1.0198x over previous
#include <cuda_runtime.h>
#include <cuda_fp16.h>
#include <math.h>
#include <stdint.h>

#define B_    2
#define S_    2048
#define E_    4096
#define H_    32
#define KVH_  8
#define D_    128
#define HD_   (H_*D_)      // 4096
#define KVHD_ (KVH_*D_)    // 1024
#define M_    (B_*S_)      // 4096

// ---------------- scratch (no allocations allowed) ----------------
__device__ float g_cos [S_*(D_/2)];
__device__ float g_sin [S_*(D_/2)];

__device__ __align__(16) __half g_hid_hi [(size_t)M_*E_];
__device__ __align__(16) __half g_wq_hi  [(size_t)HD_*E_];
__device__ __align__(16) __half g_wq_lo  [(size_t)HD_*E_];
__device__ __align__(16) __half g_wk_hi  [(size_t)KVHD_*E_];
__device__ __align__(16) __half g_wk_lo  [(size_t)KVHD_*E_];
__device__ __align__(16) __half g_wv_hi  [(size_t)KVHD_*E_];
__device__ __align__(16) __half g_wv_lo  [(size_t)KVHD_*E_];
__device__ __align__(16) __half g_wo_hi  [(size_t)E_*HD_];
__device__ __align__(16) __half g_wo_lo  [(size_t)E_*HD_];
__device__ __align__(16) __half g_attn_hi[(size_t)M_*HD_];

__device__ __align__(16) __half g_qb_hi[(size_t)B_*H_*S_*D_];
__device__ __align__(16) __half g_qb_lo[(size_t)B_*H_*S_*D_];
__device__ __align__(16) __half g_kb_hi[(size_t)B_*KVH_*S_*D_];
__device__ __align__(16) __half g_kb_lo[(size_t)B_*KVH_*S_*D_];
__device__ __align__(16) __half g_vb_hi[(size_t)B_*KVH_*S_*D_];
__device__ __align__(16) __half g_vb_lo[(size_t)B_*KVH_*S_*D_];

// ---------------- helpers ----------------
__device__ __forceinline__ uint32_t smem_u32(const void* p) {
    uint32_t a;
    asm("{ .reg .u64 t; cvta.to.shared.u64 t, %1; cvt.u32.u64 %0, t; }" : "=r"(a) : "l"(p));
    return a;
}
__device__ __forceinline__ void ldsm_x4(uint32_t* r, uint32_t a) {
    asm volatile("ldmatrix.sync.aligned.m8n8.x4.shared.b16 {%0,%1,%2,%3}, [%4];"
                 : "=r"(r[0]), "=r"(r[1]), "=r"(r[2]), "=r"(r[3]) : "r"(a));
}
__device__ __forceinline__ void mma_f16(float* c, const uint32_t* a, const uint32_t* b) {
    asm volatile("mma.sync.aligned.m16n8k16.row.col.f32.f16.f16.f32 "
                 "{%0,%1,%2,%3}, {%4,%5,%6,%7}, {%8,%9}, {%0,%1,%2,%3};"
                 : "+f"(c[0]), "+f"(c[1]), "+f"(c[2]), "+f"(c[3])
                 : "r"(a[0]), "r"(a[1]), "r"(a[2]), "r"(a[3]), "r"(b[0]), "r"(b[1]));
}
__device__ __forceinline__ void cp16(uint32_t saddr, const void* g) {
    asm volatile("cp.async.cg.shared.global [%0], [%1], 16;" :: "r"(saddr), "l"(g) : "memory");
}
__device__ __forceinline__ uint32_t pack_f16_split(float x0, float x1, uint32_t& lo_out) {
    __half h0 = __float2half_rn(x0);
    __half h1 = __float2half_rn(x1);
    __half l0 = __float2half_rn(x0 - __half2float(h0));
    __half l1 = __float2half_rn(x1 - __half2float(h1));
    __half2 hp = __halves2half2(h0, h1);
    __half2 lp = __halves2half2(l0, l1);
    lo_out = *reinterpret_cast<uint32_t*>(&lp);
    return *reinterpret_cast<uint32_t*>(&hp);
}
__device__ __forceinline__ uint32_t pack_f16_pair(float x0, float x1) {
    __half2 hp = __halves2half2(__float2half_rn(x0), __float2half_rn(x1));
    return *reinterpret_cast<uint32_t*>(&hp);
}

// ---------------- unified prep kernel ----------------
#define RT_B   ((S_*(D_/2))/256)
#define SP_B   ((M_*(E_>>3))/256)
#define WQ_B   ((HD_/32)*(E_/32))
#define WK_B   ((KVHD_/32)*(E_/32))
#define WV_B   WK_B
#define WO_B   ((E_/32)*(HD_/32))
#define PREP_TOTAL (RT_B + SP_B + WQ_B + WK_B + WV_B + WO_B)

__device__ __forceinline__ void do_wtrans(const float* __restrict__ W,
                                          __half* __restrict__ Thi, __half* __restrict__ Tlo,
                                          int Kdim, int Ndim, int seg, int tid,
                                          float (*tile)[33]) {
    int nTiles = Ndim / 32;
    int bx = seg % nTiles, by = seg / nTiles;
    int n0 = bx * 32, k0 = by * 32;
    int tx = tid & 31, ty = tid >> 5;
    #pragma unroll
    for (int dy = 0; dy < 32; dy += 8)
        tile[ty + dy][tx] = W[(size_t)(k0 + ty + dy) * Ndim + n0 + tx];
    __syncthreads();
    int KB = Kdim >> 3;
    #pragma unroll
    for (int dy = 0; dy < 32; dy += 8) {
        int n = n0 + ty + dy, k = k0 + tx;
        float x = tile[tx][ty + dy];
        __half h = __float2half_rn(x);
        __half l = __float2half_rn(x - __half2float(h));
        size_t off = (((size_t)(n >> 3) * KB + (k >> 3)) << 6) + (size_t)(n & 7) * 8 + (k & 7);
        Thi[off] = h;
        Tlo[off] = l;
    }
}

__global__ __launch_bounds__(256)
void prep_all_kernel(const float* __restrict__ hidden,
                     const float* __restrict__ Wq, const float* __restrict__ Wk,
                     const float* __restrict__ Wv, const float* __restrict__ Wo) {
    __shared__ float tile[32][33];
    const int tid = threadIdx.x;
    int blk = blockIdx.x;

    if (blk < RT_B) {
        int idx = blk * 256 + tid;
        int t = idx / (D_/2);
        int i = idx % (D_/2);
        double inv = exp(-((double)(2*i) / (double)D_) * log(10000.0));
        double ang = (double)t * inv;
        g_cos[idx] = (float)cos(ang);
        g_sin[idx] = (float)sin(ang);
        return;
    }
    blk -= RT_B;
    if (blk < SP_B) {
        int idx = blk * 256 + tid;
        const int KB = E_ >> 3;
        int row = idx / KB, kb = idx % KB;
        const float* src = hidden + (size_t)row * E_ + kb * 8;
        float4 v0 = *(const float4*)src;
        float4 v1 = *(const float4*)(src + 4);
        uint32_t hw[4];
        hw[0] = pack_f16_pair(v0.x, v0.y);
        hw[1] = pack_f16_pair(v0.z, v0.w);
        hw[2] = pack_f16_pair(v1.x, v1.y);
        hw[3] = pack_f16_pair(v1.z, v1.w);
        size_t off = (((size_t)(row >> 3) * KB + kb) << 6) + (size_t)(row & 7) * 8;
        *(uint4*)(g_hid_hi + off) = make_uint4(hw[0], hw[1], hw[2], hw[3]);
        return;
    }
    blk -= SP_B;
    if (blk < WQ_B) { do_wtrans(Wq, g_wq_hi, g_wq_lo, E_,  HD_, blk, tid, tile); return; }
    blk -= WQ_B;
    if (blk < WK_B) { do_wtrans(Wk, g_wk_hi, g_wk_lo, E_,  KVHD_, blk, tid, tile); return; }
    blk -= WK_B;
    if (blk < WV_B) { do_wtrans(Wv, g_wv_hi, g_wv_lo, E_,  KVHD_, blk, tid, tile); return; }
    blk -= WV_B;
    do_wtrans(Wo, g_wo_hi, g_wo_lo, HD_, E_, blk, tid, tile);
}

// ---------------- GEMM mainloop (shared by QKV + O kernels) ----------------
#define GEMM_MAINLOOP(pAhi_, pBhi_, pBlo_, Kdim_)                                           \
    const int KB = (Kdim_) >> 3;                                                            \
    const int NC = (Kdim_) >> 6;                                                            \
    float acc[4][4][4];                                                                     \
    _Pragma("unroll") for (int t = 0; t < 4; t++)                                           \
        _Pragma("unroll") for (int u = 0; u < 4; u++)                                       \
            _Pragma("unroll") for (int j = 0; j < 4; j++) acc[t][u][j] = 0.f;               \
    auto prefetch = [&](int chunk, int st) {                                                \
        uint32_t sbuf = sbase + (uint32_t)st * 49152u;                                      \
        int kb0 = chunk << 3;                                                               \
        _Pragma("unroll") for (int j = 0; j < 4; j++) {                                     \
            int u = tid + j * 256;                                                          \
            int rb = u >> 6, kb = (u >> 3) & 7, w = u & 7;                                  \
            size_t gA = ((size_t)(mb0 + rb) * KB + (kb0 + kb)) * 128u + (size_t)w * 16u;    \
            size_t gB = ((size_t)(nb0 + rb) * KB + (kb0 + kb)) * 128u + (size_t)w * 16u;    \
            uint32_t so = (uint32_t)(((rb * 8 + kb) * 8 + w) * 16);                         \
            cp16(sbuf + so,          (const char*)(pAhi_) + gA);                            \
            cp16(sbuf + 16384u + so, (const char*)(pBhi_) + gB);                            \
            cp16(sbuf + 32768u + so, (const char*)(pBlo_) + gB);                            \
        }                                                                                   \
    };                                                                                      \
    const int wmb   = (warp >> 2) * 8;                                                      \
    const int wnb   = (warp & 3) * 4;                                                       \
    const int selAm = (lane >> 3) & 1;                                                      \
    const int selAk = (lane >> 3) >> 1;                                                     \
    const int selBn = (lane >> 4) & 1;                                                      \
    const int selBk = (lane >> 3) & 1;                                                      \
    const int rrow  = lane & 7;                                                             \
    prefetch(0, 0);                                                                         \
    asm volatile("cp.async.commit_group;" ::: "memory");                                    \
    prefetch(1, 1);                                                                         \
    asm volatile("cp.async.commit_group;" ::: "memory");                                    \
    for (int i = 0; i < NC; i++) {                                                          \
        asm volatile("cp.async.wait_group 1;" ::: "memory");                                \
        __syncthreads();                                                                    \
        if (i + 2 < NC) {                                                                   \
            int st = i + 2;                                                                 \
            prefetch(st, st % 3);                                                           \
            asm volatile("cp.async.commit_group;" ::: "memory");                            \
        } else {                                                                            \
            asm volatile("cp.async.commit_group;" ::: "memory");                            \
        }                                                                                   \
        uint32_t sbuf = sbase + (uint32_t)(i % 3) * 49152u;                                 \
        _Pragma("unroll") for (int ks = 0; ks < 4; ks++) {                                  \
            uint32_t ahi[4][4], bhi[2][4], blo[2][4];                                       \
            _Pragma("unroll") for (int t = 0; t < 4; t++) {                                 \
                int mbb = wmb + 2*t + selAm;                                                \
                int kbb = 2*ks + selAk;                                                     \
                uint32_t off = (uint32_t)((mbb * 8 + kbb) * 128 + rrow * 16);               \
                ldsm_x4(ahi[t], sbuf + off);                                                \
            }                                                                               \
            _Pragma("unroll") for (int u2 = 0; u2 < 2; u2++) {                              \
                int nbb = wnb + 2*u2 + selBn;                                               \
                int kbb = 2*ks + selBk;                                                     \
                uint32_t off = (uint32_t)((nbb * 8 + kbb) * 128 + rrow * 16);               \
                ldsm_x4(bhi[u2], sbuf + 16384u + off);                                      \
                ldsm_x4(blo[u2], sbuf + 32768u + off);                                      \
            }                                                                               \
            _Pragma("unroll") for (int t = 0; t < 4; t++)                                   \
                _Pragma("unroll") for (int u = 0; u < 4; u++) {                             \
                    const uint32_t* bh = &bhi[u >> 1][(u & 1) * 2];                         \
                    const uint32_t* bl = &blo[u >> 1][(u & 1) * 2];                         \
                    mma_f16(acc[t][u], ahi[t], bh);                                         \
                    mma_f16(acc[t][u], ahi[t], bl);                                         \
                }                                                                           \
    }

// ---------------- merged QKV projection kernel ----------------
__global__ __launch_bounds__(256, 1)
void qkv_gemm_kernel(const float* __restrict__ bq, const float* __restrict__ bk,
                     const float* __restrict__ bv, const int* __restrict__ pos) {
    extern __shared__ char smc[];
    const uint32_t sbase = smem_u32(smc);
    const int tid  = threadIdx.x;
    const int warp = tid >> 5, lane = tid & 31;
    const int mb0  = blockIdx.y * 16;
    const int bx   = blockIdx.x;

    const __half *pBh, *pBl;
    const float* bias;
    int nb0, mode, hh;
    if (bx < 32)      { pBh = g_wq_hi; pBl = g_wq_lo; bias = bq; nb0 = bx * 16;        mode = 1; hh = bx; }
    else if (bx < 40) { pBh = g_wk_hi; pBl = g_wk_lo; bias = bk; nb0 = (bx - 32) * 16; mode = 2; hh = bx - 32; }
    else              { pBh = g_wv_hi; pBl = g_wv_lo; bias = bv; nb0 = (bx - 40) * 16; mode = 3; hh = bx - 40; }

    GEMM_MAINLOOP(g_hid_hi, pBh, pBl, E_)
    }

    const int gg = lane >> 2, qq = lane & 3;

    float* st = (float*)smc;
    __syncthreads();
    {
        const int lrow = (warp >> 2) * 64;
        const int lcol = (warp & 3) * 32;
        #pragma unroll
        for (int t = 0; t < 4; t++) {
            #pragma unroll
            for (int u = 0; u < 4; u++) {
                int r = lrow + t * 16 + gg;
                int c = lcol + u * 8 + qq * 2;
                float2 b2 = *(const float2*)(bias + nb0 * 8 + c);
                st[r * 132 + c]           = acc[t][u][0] + b2.x;
                st[r * 132 + c + 1]       = acc[t][u][1] + b2.y;
                st[(r + 8) * 132 + c]     = acc[t][u][2] + b2.x;
                st[(r + 8) * 132 + c + 1] = acc[t][u][3] + b2.y;
            }
        }
    }
    __syncthreads();

    if (mode == 1 || mode == 2) {
        __half* oHi = (mode == 1) ? g_qb_hi : g_kb_hi;
        __half* oLo = (mode == 1) ? g_qb_lo : g_kb_lo;
        #pragma unroll
        for (int j = 0; j < 4; j++) {
            int idx = tid + j * 256;
            int kbl = idx & 7;
            int r   = idx >> 3;
            int token = blockIdx.y * 128 + r;
            int b = token >> 11;
            int s = token & (S_ - 1);
            int p = pos[b * S_ + s];
            int i0 = kbl * 8;
            float y1[8], y2[8];
            #pragma unroll
            for (int jj = 0; jj < 8; jj++) {
                float x1 = st[r * 132 + i0 + jj];
                float x2 = st[r * 132 + 64 + i0 + jj];
                float c  = g_cos[p * 64 + i0 + jj];
                float sn = g_sin[p * 64 + i0 + jj];
                y1[jj] = x1 * c - x2 * sn;
                y2[jj] = x2 * c + x1 * sn;
            }
            uint32_t h1[4], l1[4], h2[4], l2[4];
            #pragma unroll
            for (int jj = 0; jj < 4; jj++) {
                h1[jj] = pack_f16_split(y1[2*jj], y1[2*jj+1], l1[jj]);
                h2[jj] = pack_f16_split(y2[2*jj], y2[2*jj+1], l2[jj]);
            }
            size_t dbase;
            if (mode == 1) {
                int qt = s >> 7, sbw = (s >> 3) & 15;
                dbase = ((((size_t)(b * H_ + hh) * (S_/128) + qt) * 16 + sbw) * 16);
            } else {
                int kt = s >> 6, sbw = (s >> 3) & 7;
                dbase = ((((size_t)(b * KVH_ + hh) * (S_/64) + kt) * 8 + sbw) * 16);
            }
            int rr = s & 7;
            size_t o1 = (dbase + kbl)     * 64 + (size_t)rr * 8;
            size_t o2 = (dbase + kbl + 8) * 64 + (size_t)rr * 8;
            *(uint4*)(oHi + o1) = make_uint4(h1[0], h1[1], h1[2], h1[3]);
            *(uint4*)(oLo + o1) = make_uint4(l1[0], l1[1], l1[2], l1[3]);
            *(uint4*)(oHi + o2) = make_uint4(h2[0], h2[1], h2[2], h2[3]);
            *(uint4*)(oLo + o2) = make_uint4(l2[0], l2[1], l2[2], l2[3]);
        }
    } else {
        const int token0 = blockIdx.y * 128;
        const int b = token0 >> 11;
        const int sbase0 = token0 & (S_ - 1);
        #pragma unroll
        for (int j = 0; j < 8; j++) {
            int idx = tid + j * 256;
            int dr  = idx & 7;
            int sbw = (idx >> 3) & 7;
            int db  = (idx >> 6) & 15;
            int ktl = idx >> 10;
            int d = db * 8 + dr;
            int sl = ktl * 64 + sbw * 8;
            uint32_t hw[4], lw[4];
            #pragma unroll
            for (int jj = 0; jj < 4; jj++) {
                float x0 = st[(sl + 2*jj)     * 132 + d];
                float x1 = st[(sl + 2*jj + 1) * 132 + d];
                hw[jj] = pack_f16_split(x0, x1, lw[jj]);
            }
            int s = sbase0 + sl;
            int kt = s >> 6;
            size_t off = (((((size_t)(b * KVH_ + hh) * (S_/64) + kt) * 16 + db) * 8 + sbw) * 64)
                       + (size_t)dr * 8;
            *(uint4*)(g_vb_hi + off) = make_uint4(hw[0], hw[1], hw[2], hw[3]);
            *(uint4*)(g_vb_lo + off) = make_uint4(lw[0], lw[1], lw[2], lw[3]);
        }
    }
}

// ---------------- O-projection kernel ----------------
__global__ __launch_bounds__(256, 1)
void o_gemm_kernel(float* __restrict__ C) {
    extern __shared__ char smc[];
    const uint32_t sbase = smem_u32(smc);
    const int tid  = threadIdx.x;
    const int warp = tid >> 5, lane = tid & 31;
    const int mb0  = blockIdx.y * 16;
    const int nb0  = blockIdx.x * 16;

    GEMM_MAINLOOP(g_attn_hi, g_wo_hi, g_wo_lo, HD_)
    }

    const int mrow = mb0 * 8 + (warp >> 2) * 64;
    const int ncol = nb0 * 8 + (warp & 3) * 32;
    const int gg = lane >> 2, qq = lane & 3;
    #pragma unroll
    for (int t = 0; t < 4; t++) {
        #pragma unroll
        for (int u = 0; u < 4; u++) {
            int row = mrow + t * 16 + gg;
            int col = ncol + u * 8 + qq * 2;
            *(float2*)(C + (size_t)row * E_ + col)       = make_float2(acc[t][u][0], acc[t][u][1]);
            *(float2*)(C + (size_t)(row + 8) * E_ + col) = make_float2(acc[t][u][2], acc[t][u][3]);
        }
    }
}

// ---------------- flash attention: FA2 register repack, 1 sync/tile ----------------
#define FQHI   0u
#define FQLO   32768u
#define FKV0   65536u
#define FTOT   196608u

__global__ __launch_bounds__(256, 1)
void flash_mma_kernel() {
    extern __shared__ char fs[];
    const uint32_t sb = smem_u32(fs);

    const int tid  = threadIdx.x;
    const int warp = tid >> 5, lane = tid & 31;
    const int qt = (S_/128 - 1) - blockIdx.x;
    const int h = blockIdx.y, b = blockIdx.z;
    const int q0 = qt * 128;
    const int kvh = h >> 2;
    const float scale = 0.08838834764831845f;

    const int selAm = (lane >> 3) & 1;
    const int selAk = (lane >> 3) >> 1;
    const int selBn = (lane >> 4) & 1;
    const int selBk = (lane >> 3) & 1;
    const int rrow  = lane & 7;
    const int gr = lane >> 2, qq = lane & 3;
    const int wm = warp * 16;

    const size_t kvbase = (size_t)(b*KVH_ + kvh) * (S_/64);
    auto prefetch_kv = [&](int kt, int st) {
        size_t tb = (kvbase + kt) * 16384u;   // BYTE offset of 16KB tile (R12 bug: was half-stride)
        uint32_t sbuf = sb + FKV0 + (uint32_t)st * 65536u;
        #pragma unroll
        for (int j = 0; j < 4; j++) {
            uint32_t u = (uint32_t)(tid + j * 256) * 16u;
            cp16(sbuf + u,           (const char*)g_kb_hi + tb + u);
            cp16(sbuf + 16384u + u,  (const char*)g_kb_lo + tb + u);
            cp16(sbuf + 32768u + u,  (const char*)g_vb_hi + tb + u);
            cp16(sbuf + 49152u + u,  (const char*)g_vb_lo + tb + u);
        }
    };

    {
        const char* qh = (const char*)(g_qb_hi + (((size_t)(b*H_ + h) * (S_/128) + qt) << 14));
        const char* ql = (const char*)(g_qb_lo + (((size_t)(b*H_ + h) * (S_/128) + qt) << 14));
        #pragma unroll
        for (int j = 0; j < 8; j++) {
            uint32_t u = (uint32_t)(tid + j * 256) * 16u;
            cp16(sb + FQHI + u, qh + u);
            cp16(sb + FQLO + u, ql + u);
        }
        prefetch_kv(0, 0);
        asm volatile("cp.async.commit_group;" ::: "memory");
    }

    float m1 = -1e30f, m2 = -1e30f, l1 = 0.f, l2 = 0.f;
    float acc[16][4];
    #pragma unroll
    for (int u = 0; u < 16; u++)
        #pragma unroll
        for (int j = 0; j < 4; j++) acc[u][j] = 0.f;

    const int r1 = wm + gr;
    const int r2 = r1 + 8;

    const int NK = 2 * qt + 2;
    for (int kt = 0; kt < NK; kt++) {
        const int k0 = kt * 64;
        asm volatile("cp.async.wait_group 0;" ::: "memory");
        __syncthreads();
        const uint32_t kvs = sb + FKV0 + (uint32_t)(kt & 1) * 65536u;

        if (kt + 1 < NK) {
            prefetch_kv(kt + 1, (kt + 1) & 1);
            asm volatile("cp.async.commit_group;" ::: "memory");
        }

        // ---- S = Q @ K^T (3-term), warp stripe 16x64 ----
        float sacc[8][4];
        #pragma unroll
        for (int u = 0; u < 8; u++)
            #pragma unroll
            for (int j = 0; j < 4; j++) sacc[u][j] = 0.f;

        #pragma unroll
        for (int ks = 0; ks < 8; ks++) {
            uint32_t qhi[4], qlo[4], khi[4][4], klo[4][4];
            {
                int mbb = 2*warp + selAm;
                int kbb = 2*ks + selAk;
                uint32_t off = (uint32_t)((mbb * 16 + kbb) * 128 + rrow * 16);
                ldsm_x4(qhi, sb + FQHI + off);
                ldsm_x4(qlo, sb + FQLO + off);
            }
            #pragma unroll
            for (int j = 0; j < 4; j++) {
                int nbb = 2*j + selBn;
                int kbb = 2*ks + selBk;
                uint32_t off = (uint32_t)((nbb * 16 + kbb) * 128 + rrow * 16);
                ldsm_x4(khi[j], kvs + off);
                ldsm_x4(klo[j], kvs + 16384u + off);
            }
            #pragma unroll
            for (int u = 0; u < 8; u++) {
                const uint32_t* kh = &khi[u >> 1][(u & 1) * 2];
                const uint32_t* kl = &klo[u >> 1][(u & 1) * 2];
                mma_f16(sacc[u], qhi, kh);
                mma_f16(sacc[u], qlo, kh);
                mma_f16(sacc[u], qhi, kl);
            }
        }

        // ---- in-register softmax ----
        const bool needmask = (kt >= 2 * qt);
        float tm1 = -1e30f, tm2 = -1e30f;
        #pragma unroll
        for (int u = 0; u < 8; u++) {
            int c0 = u * 8 + qq * 2;
            float s0 = sacc[u][0] * scale;
            float s1 = sacc[u][1] * scale;
            float s2 = sacc[u][2] * scale;
            float s3 = sacc[u][3] * scale;
            if (needmask) {
                if (k0 + c0     > q0 + r1) s0 = -1e30f;
                if (k0 + c0 + 1 > q0 + r1) s1 = -1e30f;
                if (k0 + c0     > q0 + r2) s2 = -1e30f;
                if (k0 + c0 + 1 > q0 + r2) s3 = -1e30f;
            }
            sacc[u][0] = s0; sacc[u][1] = s1;
            sacc[u][2] = s2; sacc[u][3] = s3;
            tm1 = fmaxf(tm1, fmaxf(s0, s1));
            tm2 = fmaxf(tm2, fmaxf(s2, s3));
        }
        tm1 = fmaxf(tm1, __shfl_xor_sync(0xffffffffu, tm1, 1));
        tm1 = fmaxf(tm1, __shfl_xor_sync(0xffffffffu, tm1, 2));
        tm2 = fmaxf(tm2, __shfl_xor_sync(0xffffffffu, tm2, 1));
        tm2 = fmaxf(tm2, __shfl_xor_sync(0xffffffffu, tm2, 2));
        float mn1 = fmaxf(m1, tm1), mn2 = fmaxf(m2, tm2);
        float a1 = __expf(m1 - mn1), a2 = __expf(m2 - mn2);
        m1 = mn1; m2 = mn2;

        uint32_t pf[4][4];
        float ts1 = 0.f, ts2 = 0.f;
        #pragma unroll
        for (int kk = 0; kk < 4; kk++) {
            #pragma unroll
            for (int half = 0; half < 2; half++) {
                int u = 2*kk + half;
                float e0 = __expf(sacc[u][0] - m1);
                float e1 = __expf(sacc[u][1] - m1);
                float e2 = __expf(sacc[u][2] - m2);
                float e3 = __expf(sacc[u][3] - m2);
                ts1 += e0 + e1;
                ts2 += e2 + e3;
                pf[kk][half*2]     = pack_f16_pair(e0, e1);
                pf[kk][half*2 + 1] = pack_f16_pair(e2, e3);
            }
        }
        ts1 += __shfl_xor_sync(0xffffffffu, ts1, 1);
        ts1 += __shfl_xor_sync(0xffffffffu, ts1, 2);
        ts2 += __shfl_xor_sync(0xffffffffu, ts2, 1);
        ts2 += __shfl_xor_sync(0xffffffffu, ts2, 2);
        l1 = l1 * a1 + ts1;
        l2 = l2 * a2 + ts2;

        #pragma unroll
        for (int u = 0; u < 16; u++) {
            acc[u][0] *= a1; acc[u][1] *= a1;
            acc[u][2] *= a2; acc[u][3] *= a2;
        }

        // ---- O += P @ V (2-term), P from registers ----
        #pragma unroll
        for (int ks = 0; ks < 4; ks++) {
            #pragma unroll
            for (int nh = 0; nh < 2; nh++) {
                uint32_t vhi[4][4], vlo[4][4];
                #pragma unroll
                for (int j = 0; j < 4; j++) {
                    int nbb = nh*8 + 2*j + selBn;
                    int kbb = 2*ks + selBk;
                    uint32_t off = (uint32_t)((nbb * 8 + kbb) * 128 + rrow * 16);
                    ldsm_x4(vhi[j], kvs + 32768u + off);
                    ldsm_x4(vlo[j], kvs + 49152u + off);
                }
                #pragma unroll
                for (int uu = 0; uu < 8; uu++) {
                    int u = nh*8 + uu;
                    const uint32_t* vh = &vhi[uu >> 1][(uu & 1) * 2];
                    const uint32_t* vl = &vlo[uu >> 1][(uu & 1) * 2];
                    mma_f16(acc[u], pf[ks], vh);
                    mma_f16(acc[u], pf[ks], vl);
                }
            }
        }
    }

    // ---- epilogue: normalize + write blocked fp16 hi ----
    {
        const int KB = HD_ >> 3;
        float inv1 = 1.f / l1;
        float inv2 = 1.f / l2;
        int grow1 = b*S_ + q0 + r1;
        int grow2 = grow1 + 8;
        #pragma unroll
        for (int u = 0; u < 16; u++) {
            int col = h * D_ + u*8 + qq * 2;
            int kb = col >> 3, cw = col & 7;
            size_t o1 = (((size_t)(grow1 >> 3) * KB + kb) << 6) + (size_t)(grow1 & 7) * 8 + cw;
            size_t o2 = (((size_t)(grow2 >> 3) * KB + kb) << 6) + (size_t)(grow2 & 7) * 8 + cw;
            *(uint32_t*)(g_attn_hi + o1) = pack_f16_pair(acc[u][0]*inv1, acc[u][1]*inv1);
            *(uint32_t*)(g_attn_hi + o2) = pack_f16_pair(acc[u][2]*inv2, acc[u][3]*inv2);
        }
    }
}

// ---------------- launch ----------------
extern "C" void kernel_launch(void* const* d_in, const int* in_sizes, int n_in,
                              void* d_out, int out_size) {
    const float* hidden = (const float*)d_in[0];
    const int*   pos    = (const int*)  d_in[2];
    const float* Wq     = (const float*)d_in[3];
    const float* bq     = (const float*)d_in[4];
    const float* Wk     = (const float*)d_in[5];
    const float* bk     = (const float*)d_in[6];
    const float* Wv     = (const float*)d_in[7];
    const float* bv     = (const float*)d_in[8];
    const float* Wo     = (const float*)d_in[9];
    float* out = (float*)d_out;

    const size_t gsmem = 147456;
    cudaFuncSetAttribute(qkv_gemm_kernel, cudaFuncAttributeMaxDynamicSharedMemorySize, (int)gsmem);
    cudaFuncSetAttribute(o_gemm_kernel,   cudaFuncAttributeMaxDynamicSharedMemorySize, (int)gsmem);
    cudaFuncSetAttribute(flash_mma_kernel, cudaFuncAttributeMaxDynamicSharedMemorySize, (int)FTOT);

    prep_all_kernel<<<PREP_TOTAL, 256>>>(hidden, Wq, Wk, Wv, Wo);
    qkv_gemm_kernel<<<dim3(48, M_/128), 256, gsmem>>>(bq, bk, bv, pos);
    flash_mma_kernel<<<dim3(S_/128, H_, B_), 256, FTOT>>>();
    o_gemm_kernel<<<dim3(E_/128, M_/128), 256, gsmem>>>(out);
}

// round 14
// speedup vs baseline: 1.5804x; 1.1113x over previous
#include <cuda_runtime.h>
#include <cuda_fp16.h>
#include <math.h>
#include <stdint.h>

#define B_    2
#define S_    2048
#define E_    4096
#define H_    32
#define KVH_  8
#define D_    128
#define HD_   (H_*D_)      // 4096
#define KVHD_ (KVH_*D_)    // 1024
#define M_    (B_*S_)      // 4096

// ---------------- scratch (no allocations allowed) ----------------
__device__ float g_cos [S_*(D_/2)];
__device__ float g_sin [S_*(D_/2)];

__device__ __align__(16) __half g_hid_hi [(size_t)M_*E_];
__device__ __align__(16) __half g_wq_hi  [(size_t)HD_*E_];
__device__ __align__(16) __half g_wq_lo  [(size_t)HD_*E_];
__device__ __align__(16) __half g_wk_hi  [(size_t)KVHD_*E_];
__device__ __align__(16) __half g_wk_lo  [(size_t)KVHD_*E_];
__device__ __align__(16) __half g_wv_hi  [(size_t)KVHD_*E_];
__device__ __align__(16) __half g_wv_lo  [(size_t)KVHD_*E_];
__device__ __align__(16) __half g_wo_hi  [(size_t)E_*HD_];
__device__ __align__(16) __half g_wo_lo  [(size_t)E_*HD_];
__device__ __align__(16) __half g_attn_hi[(size_t)M_*HD_];

__device__ __align__(16) __half g_qb_hi[(size_t)B_*H_*S_*D_];
__device__ __align__(16) __half g_qb_lo[(size_t)B_*H_*S_*D_];
__device__ __align__(16) __half g_kb_hi[(size_t)B_*KVH_*S_*D_];
__device__ __align__(16) __half g_kb_lo[(size_t)B_*KVH_*S_*D_];
__device__ __align__(16) __half g_vb_hi[(size_t)B_*KVH_*S_*D_];
__device__ __align__(16) __half g_vb_lo[(size_t)B_*KVH_*S_*D_];

// ---------------- helpers ----------------
__device__ __forceinline__ uint32_t smem_u32(const void* p) {
    uint32_t a;
    asm("{ .reg .u64 t; cvta.to.shared.u64 t, %1; cvt.u32.u64 %0, t; }" : "=r"(a) : "l"(p));
    return a;
}
__device__ __forceinline__ void ldsm_x4(uint32_t* r, uint32_t a) {
    asm volatile("ldmatrix.sync.aligned.m8n8.x4.shared.b16 {%0,%1,%2,%3}, [%4];"
                 : "=r"(r[0]), "=r"(r[1]), "=r"(r[2]), "=r"(r[3]) : "r"(a));
}
__device__ __forceinline__ void mma_f16(float* c, const uint32_t* a, const uint32_t* b) {
    asm volatile("mma.sync.aligned.m16n8k16.row.col.f32.f16.f16.f32 "
                 "{%0,%1,%2,%3}, {%4,%5,%6,%7}, {%8,%9}, {%0,%1,%2,%3};"
                 : "+f"(c[0]), "+f"(c[1]), "+f"(c[2]), "+f"(c[3])
                 : "r"(a[0]), "r"(a[1]), "r"(a[2]), "r"(a[3]), "r"(b[0]), "r"(b[1]));
}
__device__ __forceinline__ void cp16(uint32_t saddr, const void* g) {
    asm volatile("cp.async.cg.shared.global [%0], [%1], 16;" :: "r"(saddr), "l"(g) : "memory");
}
__device__ __forceinline__ uint32_t pack_f16_split(float x0, float x1, uint32_t& lo_out) {
    __half h0 = __float2half_rn(x0);
    __half h1 = __float2half_rn(x1);
    __half l0 = __float2half_rn(x0 - __half2float(h0));
    __half l1 = __float2half_rn(x1 - __half2float(h1));
    __half2 hp = __halves2half2(h0, h1);
    __half2 lp = __halves2half2(l0, l1);
    lo_out = *reinterpret_cast<uint32_t*>(&lp);
    return *reinterpret_cast<uint32_t*>(&hp);
}
__device__ __forceinline__ uint32_t pack_f16_pair(float x0, float x1) {
    __half2 hp = __halves2half2(__float2half_rn(x0), __float2half_rn(x1));
    return *reinterpret_cast<uint32_t*>(&hp);
}

// ---------------- unified prep kernel ----------------
#define RT_B   ((S_*(D_/2))/256)
#define SP_B   ((M_*(E_>>3))/256)
#define WQ_B   ((HD_/32)*(E_/32))
#define WK_B   ((KVHD_/32)*(E_/32))
#define WV_B   WK_B
#define WO_B   ((E_/32)*(HD_/32))
#define PREP_TOTAL (RT_B + SP_B + WQ_B + WK_B + WV_B + WO_B)

__device__ __forceinline__ void do_wtrans(const float* __restrict__ W,
                                          __half* __restrict__ Thi, __half* __restrict__ Tlo,
                                          int Kdim, int Ndim, int seg, int tid,
                                          float (*tile)[33]) {
    int nTiles = Ndim / 32;
    int bx = seg % nTiles, by = seg / nTiles;
    int n0 = bx * 32, k0 = by * 32;
    int tx = tid & 31, ty = tid >> 5;
    #pragma unroll
    for (int dy = 0; dy < 32; dy += 8)
        tile[ty + dy][tx] = W[(size_t)(k0 + ty + dy) * Ndim + n0 + tx];
    __syncthreads();
    int KB = Kdim >> 3;
    #pragma unroll
    for (int dy = 0; dy < 32; dy += 8) {
        int n = n0 + ty + dy, k = k0 + tx;
        float x = tile[tx][ty + dy];
        __half h = __float2half_rn(x);
        __half l = __float2half_rn(x - __half2float(h));
        size_t off = (((size_t)(n >> 3) * KB + (k >> 3)) << 6) + (size_t)(n & 7) * 8 + (k & 7);
        Thi[off] = h;
        Tlo[off] = l;
    }
}

__global__ __launch_bounds__(256)
void prep_all_kernel(const float* __restrict__ hidden,
                     const float* __restrict__ Wq, const float* __restrict__ Wk,
                     const float* __restrict__ Wv, const float* __restrict__ Wo) {
    __shared__ float tile[32][33];
    const int tid = threadIdx.x;
    int blk = blockIdx.x;

    if (blk < RT_B) {
        int idx = blk * 256 + tid;
        int t = idx / (D_/2);
        int i = idx % (D_/2);
        double inv = exp(-((double)(2*i) / (double)D_) * log(10000.0));
        double ang = (double)t * inv;
        g_cos[idx] = (float)cos(ang);
        g_sin[idx] = (float)sin(ang);
        return;
    }
    blk -= RT_B;
    if (blk < SP_B) {
        int idx = blk * 256 + tid;
        const int KB = E_ >> 3;
        int row = idx / KB, kb = idx % KB;
        const float* src = hidden + (size_t)row * E_ + kb * 8;
        float4 v0 = *(const float4*)src;
        float4 v1 = *(const float4*)(src + 4);
        uint32_t hw[4];
        hw[0] = pack_f16_pair(v0.x, v0.y);
        hw[1] = pack_f16_pair(v0.z, v0.w);
        hw[2] = pack_f16_pair(v1.x, v1.y);
        hw[3] = pack_f16_pair(v1.z, v1.w);
        size_t off = (((size_t)(row >> 3) * KB + kb) << 6) + (size_t)(row & 7) * 8;
        *(uint4*)(g_hid_hi + off) = make_uint4(hw[0], hw[1], hw[2], hw[3]);
        return;
    }
    blk -= SP_B;
    if (blk < WQ_B) { do_wtrans(Wq, g_wq_hi, g_wq_lo, E_,  HD_, blk, tid, tile); return; }
    blk -= WQ_B;
    if (blk < WK_B) { do_wtrans(Wk, g_wk_hi, g_wk_lo, E_,  KVHD_, blk, tid, tile); return; }
    blk -= WK_B;
    if (blk < WV_B) { do_wtrans(Wv, g_wv_hi, g_wv_lo, E_,  KVHD_, blk, tid, tile); return; }
    blk -= WV_B;
    do_wtrans(Wo, g_wo_hi, g_wo_lo, HD_, E_, blk, tid, tile);
}

// ---------------- GEMM mainloop (2-stage, 96KB -> 2 CTAs/SM) ----------------
#define GEMM_MAINLOOP(pAhi_, pBhi_, pBlo_, Kdim_)                                           \
    const int KB = (Kdim_) >> 3;                                                            \
    const int NC = (Kdim_) >> 6;                                                            \
    float acc[4][4][4];                                                                     \
    _Pragma("unroll") for (int t = 0; t < 4; t++)                                           \
        _Pragma("unroll") for (int u = 0; u < 4; u++)                                       \
            _Pragma("unroll") for (int j = 0; j < 4; j++) acc[t][u][j] = 0.f;               \
    auto prefetch = [&](int chunk, int st) {                                                \
        uint32_t sbuf = sbase + (uint32_t)st * 49152u;                                      \
        int kb0 = chunk << 3;                                                               \
        _Pragma("unroll") for (int j = 0; j < 4; j++) {                                     \
            int u = tid + j * 256;                                                          \
            int rb = u >> 6, kb = (u >> 3) & 7, w = u & 7;                                  \
            size_t gA = ((size_t)(mb0 + rb) * KB + (kb0 + kb)) * 128u + (size_t)w * 16u;    \
            size_t gB = ((size_t)(nb0 + rb) * KB + (kb0 + kb)) * 128u + (size_t)w * 16u;    \
            uint32_t so = (uint32_t)(((rb * 8 + kb) * 8 + w) * 16);                         \
            cp16(sbuf + so,          (const char*)(pAhi_) + gA);                            \
            cp16(sbuf + 16384u + so, (const char*)(pBhi_) + gB);                            \
            cp16(sbuf + 32768u + so, (const char*)(pBlo_) + gB);                            \
        }                                                                                   \
    };                                                                                      \
    const int wmb   = (warp >> 2) * 8;                                                      \
    const int wnb   = (warp & 3) * 4;                                                      \
    const int selAm = (lane >> 3) & 1;                                                      \
    const int selAk = (lane >> 3) >> 1;                                                     \
    const int selBn = (lane >> 4) & 1;                                                      \
    const int selBk = (lane >> 3) & 1;                                                      \
    const int rrow  = lane & 7;                                                             \
    prefetch(0, 0);                                                                         \
    asm volatile("cp.async.commit_group;" ::: "memory");                                    \
    for (int i = 0; i < NC; i++) {                                                          \
        asm volatile("cp.async.wait_group 0;" ::: "memory");                                \
        __syncthreads();                                                                    \
        if (i + 1 < NC) {                                                                   \
            prefetch(i + 1, (i + 1) & 1);                                                   \
            asm volatile("cp.async.commit_group;" ::: "memory");                            \
        }                                                                                   \
        uint32_t sbuf = sbase + (uint32_t)(i & 1) * 49152u;                                 \
        _Pragma("unroll") for (int ks = 0; ks < 4; ks++) {                                  \
            uint32_t ahi[4][4], bhi[2][4], blo[2][4];                                       \
            _Pragma("unroll") for (int t = 0; t < 4; t++) {                                 \
                int mbb = wmb + 2*t + selAm;                                                \
                int kbb = 2*ks + selAk;                                                     \
                uint32_t off = (uint32_t)((mbb * 8 + kbb) * 128 + rrow * 16);               \
                ldsm_x4(ahi[t], sbuf + off);                                                \
            }                                                                               \
            _Pragma("unroll") for (int u2 = 0; u2 < 2; u2++) {                              \
                int nbb = wnb + 2*u2 + selBn;                                               \
                int kbb = 2*ks + selBk;                                                     \
                uint32_t off = (uint32_t)((nbb * 8 + kbb) * 128 + rrow * 16);               \
                ldsm_x4(bhi[u2], sbuf + 16384u + off);                                      \
                ldsm_x4(blo[u2], sbuf + 32768u + off);                                      \
            }                                                                               \
            _Pragma("unroll") for (int t = 0; t < 4; t++)                                   \
                _Pragma("unroll") for (int u = 0; u < 4; u++) {                             \
                    const uint32_t* bh = &bhi[u >> 1][(u & 1) * 2];                         \
                    const uint32_t* bl = &blo[u >> 1][(u & 1) * 2];                         \
                    mma_f16(acc[t][u], ahi[t], bh);                                         \
                    mma_f16(acc[t][u], ahi[t], bl);                                         \
                }                                                                           \
        }                                                                                   \
        __syncthreads();                                                                    \
    {

// ---------------- merged QKV projection kernel ----------------
__global__ __launch_bounds__(256, 2)
void qkv_gemm_kernel(const float* __restrict__ bq, const float* __restrict__ bk,
                     const float* __restrict__ bv, const int* __restrict__ pos) {
    extern __shared__ char smc[];
    const uint32_t sbase = smem_u32(smc);
    const int tid  = threadIdx.x;
    const int warp = tid >> 5, lane = tid & 31;
    const int mb0  = blockIdx.y * 16;
    const int bx   = blockIdx.x;

    const __half *pBh, *pBl;
    const float* bias;
    int nb0, mode, hh;
    if (bx < 32)      { pBh = g_wq_hi; pBl = g_wq_lo; bias = bq; nb0 = bx * 16;        mode = 1; hh = bx; }
    else if (bx < 40) { pBh = g_wk_hi; pBl = g_wk_lo; bias = bk; nb0 = (bx - 32) * 16; mode = 2; hh = bx - 32; }
    else              { pBh = g_wv_hi; pBl = g_wv_lo; bias = bv; nb0 = (bx - 40) * 16; mode = 3; hh = bx - 40; }

    GEMM_MAINLOOP(g_hid_hi, pBh, pBl, E_)
    }}   // close inner block + mainloop for

    const int gg = lane >> 2, qq = lane & 3;

    float* st = (float*)smc;
    // last-iter bottom sync already ran; stage smem free to reuse
    {
        const int lrow = (warp >> 2) * 64;
        const int lcol = (warp & 3) * 32;
        #pragma unroll
        for (int t = 0; t < 4; t++) {
            #pragma unroll
            for (int u = 0; u < 4; u++) {
                int r = lrow + t * 16 + gg;
                int c = lcol + u * 8 + qq * 2;
                float2 b2 = *(const float2*)(bias + nb0 * 8 + c);
                st[r * 132 + c]           = acc[t][u][0] + b2.x;
                st[r * 132 + c + 1]       = acc[t][u][1] + b2.y;
                st[(r + 8) * 132 + c]     = acc[t][u][2] + b2.x;
                st[(r + 8) * 132 + c + 1] = acc[t][u][3] + b2.y;
            }
        }
    }
    __syncthreads();

    if (mode == 1 || mode == 2) {
        __half* oHi = (mode == 1) ? g_qb_hi : g_kb_hi;
        __half* oLo = (mode == 1) ? g_qb_lo : g_kb_lo;
        #pragma unroll
        for (int j = 0; j < 4; j++) {
            int idx = tid + j * 256;
            int kbl = idx & 7;
            int r   = idx >> 3;
            int token = blockIdx.y * 128 + r;
            int b = token >> 11;
            int s = token & (S_ - 1);
            int p = pos[b * S_ + s];
            int i0 = kbl * 8;
            float y1[8], y2[8];
            #pragma unroll
            for (int jj = 0; jj < 8; jj++) {
                float x1 = st[r * 132 + i0 + jj];
                float x2 = st[r * 132 + 64 + i0 + jj];
                float c  = g_cos[p * 64 + i0 + jj];
                float sn = g_sin[p * 64 + i0 + jj];
                y1[jj] = x1 * c - x2 * sn;
                y2[jj] = x2 * c + x1 * sn;
            }
            uint32_t h1[4], l1[4], h2[4], l2[4];
            #pragma unroll
            for (int jj = 0; jj < 4; jj++) {
                h1[jj] = pack_f16_split(y1[2*jj], y1[2*jj+1], l1[jj]);
                h2[jj] = pack_f16_split(y2[2*jj], y2[2*jj+1], l2[jj]);
            }
            size_t dbase;
            if (mode == 1) {
                int qt = s >> 7, sbw = (s >> 3) & 15;
                dbase = ((((size_t)(b * H_ + hh) * (S_/128) + qt) * 16 + sbw) * 16);
            } else {
                int kt = s >> 6, sbw = (s >> 3) & 7;
                dbase = ((((size_t)(b * KVH_ + hh) * (S_/64) + kt) * 8 + sbw) * 16);
            }
            int rr = s & 7;
            size_t o1 = (dbase + kbl)     * 64 + (size_t)rr * 8;
            size_t o2 = (dbase + kbl + 8) * 64 + (size_t)rr * 8;
            *(uint4*)(oHi + o1) = make_uint4(h1[0], h1[1], h1[2], h1[3]);
            *(uint4*)(oLo + o1) = make_uint4(l1[0], l1[1], l1[2], l1[3]);
            *(uint4*)(oHi + o2) = make_uint4(h2[0], h2[1], h2[2], h2[3]);
            *(uint4*)(oLo + o2) = make_uint4(l2[0], l2[1], l2[2], l2[3]);
        }
    } else {
        const int token0 = blockIdx.y * 128;
        const int b = token0 >> 11;
        const int sbase0 = token0 & (S_ - 1);
        #pragma unroll
        for (int j = 0; j < 8; j++) {
            int idx = tid + j * 256;
            int dr  = idx & 7;
            int sbw = (idx >> 3) & 7;
            int db  = (idx >> 6) & 15;
            int ktl = idx >> 10;
            int d = db * 8 + dr;
            int sl = ktl * 64 + sbw * 8;
            uint32_t hw[4], lw[4];
            #pragma unroll
            for (int jj = 0; jj < 4; jj++) {
                float x0 = st[(sl + 2*jj)     * 132 + d];
                float x1 = st[(sl + 2*jj + 1) * 132 + d];
                hw[jj] = pack_f16_split(x0, x1, lw[jj]);
            }
            int s = sbase0 + sl;
            int kt = s >> 6;
            size_t off = (((((size_t)(b * KVH_ + hh) * (S_/64) + kt) * 16 + db) * 8 + sbw) * 64)
                       + (size_t)dr * 8;
            *(uint4*)(g_vb_hi + off) = make_uint4(hw[0], hw[1], hw[2], hw[3]);
            *(uint4*)(g_vb_lo + off) = make_uint4(lw[0], lw[1], lw[2], lw[3]);
        }
    }
}

// ---------------- O-projection kernel ----------------
__global__ __launch_bounds__(256, 2)
void o_gemm_kernel(float* __restrict__ C) {
    extern __shared__ char smc[];
    const uint32_t sbase = smem_u32(smc);
    const int tid  = threadIdx.x;
    const int warp = tid >> 5, lane = tid & 31;
    const int mb0  = blockIdx.y * 16;
    const int nb0  = blockIdx.x * 16;

    GEMM_MAINLOOP(g_attn_hi, g_wo_hi, g_wo_lo, HD_)
    }}

    const int mrow = mb0 * 8 + (warp >> 2) * 64;
    const int ncol = nb0 * 8 + (warp & 3) * 32;
    const int gg = lane >> 2, qq = lane & 3;
    #pragma unroll
    for (int t = 0; t < 4; t++) {
        #pragma unroll
        for (int u = 0; u < 4; u++) {
            int row = mrow + t * 16 + gg;
            int col = ncol + u * 8 + qq * 2;
            *(float2*)(C + (size_t)row * E_ + col)       = make_float2(acc[t][u][0], acc[t][u][1]);
            *(float2*)(C + (size_t)(row + 8) * E_ + col) = make_float2(acc[t][u][2], acc[t][u][3]);
        }
    }
}

// ---------------- flash attention: FA2 register repack, 1 sync/tile ----------------
#define FQHI   0u
#define FQLO   32768u
#define FKV0   65536u
#define FTOT   196608u

__global__ __launch_bounds__(256, 1)
void flash_mma_kernel() {
    extern __shared__ char fs[];
    const uint32_t sb = smem_u32(fs);

    const int tid  = threadIdx.x;
    const int warp = tid >> 5, lane = tid & 31;
    const int qt = (S_/128 - 1) - blockIdx.x;
    const int h = blockIdx.y, b = blockIdx.z;
    const int q0 = qt * 128;
    const int kvh = h >> 2;
    const float scale = 0.08838834764831845f;

    const int selAm = (lane >> 3) & 1;
    const int selAk = (lane >> 3) >> 1;
    const int selBn = (lane >> 4) & 1;
    const int selBk = (lane >> 3) & 1;
    const int rrow  = lane & 7;
    const int gr = lane >> 2, qq = lane & 3;
    const int wm = warp * 16;

    const size_t kvbase = (size_t)(b*KVH_ + kvh) * (S_/64);
    auto prefetch_kv = [&](int kt, int st) {
        size_t tb = (kvbase + kt) * 16384u;   // byte offset of 16KB tile
        uint32_t sbuf = sb + FKV0 + (uint32_t)st * 65536u;
        #pragma unroll
        for (int j = 0; j < 4; j++) {
            uint32_t u = (uint32_t)(tid + j * 256) * 16u;
            cp16(sbuf + u,           (const char*)g_kb_hi + tb + u);
            cp16(sbuf + 16384u + u,  (const char*)g_kb_lo + tb + u);
            cp16(sbuf + 32768u + u,  (const char*)g_vb_hi + tb + u);
            cp16(sbuf + 49152u + u,  (const char*)g_vb_lo + tb + u);
        }
    };

    {
        const char* qh = (const char*)(g_qb_hi + (((size_t)(b*H_ + h) * (S_/128) + qt) << 14));
        const char* ql = (const char*)(g_qb_lo + (((size_t)(b*H_ + h) * (S_/128) + qt) << 14));
        #pragma unroll
        for (int j = 0; j < 8; j++) {
            uint32_t u = (uint32_t)(tid + j * 256) * 16u;
            cp16(sb + FQHI + u, qh + u);
            cp16(sb + FQLO + u, ql + u);
        }
        prefetch_kv(0, 0);
        asm volatile("cp.async.commit_group;" ::: "memory");
    }

    float m1 = -1e30f, m2 = -1e30f, l1 = 0.f, l2 = 0.f;
    float acc[16][4];
    #pragma unroll
    for (int u = 0; u < 16; u++)
        #pragma unroll
        for (int j = 0; j < 4; j++) acc[u][j] = 0.f;

    const int r1 = wm + gr;
    const int r2 = r1 + 8;

    const int NK = 2 * qt + 2;
    for (int kt = 0; kt < NK; kt++) {
        const int k0 = kt * 64;
        asm volatile("cp.async.wait_group 0;" ::: "memory");
        __syncthreads();
        const uint32_t kvs = sb + FKV0 + (uint32_t)(kt & 1) * 65536u;

        if (kt + 1 < NK) {
            prefetch_kv(kt + 1, (kt + 1) & 1);
            asm volatile("cp.async.commit_group;" ::: "memory");
        }

        // ---- S = Q @ K^T (3-term), warp stripe 16x64 ----
        float sacc[8][4];
        #pragma unroll
        for (int u = 0; u < 8; u++)
            #pragma unroll
            for (int j = 0; j < 4; j++) sacc[u][j] = 0.f;

        #pragma unroll
        for (int ks = 0; ks < 8; ks++) {
            uint32_t qhi[4], qlo[4], khi[4][4], klo[4][4];
            {
                int mbb = 2*warp + selAm;
                int kbb = 2*ks + selAk;
                uint32_t off = (uint32_t)((mbb * 16 + kbb) * 128 + rrow * 16);
                ldsm_x4(qhi, sb + FQHI + off);
                ldsm_x4(qlo, sb + FQLO + off);
            }
            #pragma unroll
            for (int j = 0; j < 4; j++) {
                int nbb = 2*j + selBn;
                int kbb = 2*ks + selBk;
                uint32_t off = (uint32_t)((nbb * 16 + kbb) * 128 + rrow * 16);
                ldsm_x4(khi[j], kvs + off);
                ldsm_x4(klo[j], kvs + 16384u + off);
            }
            #pragma unroll
            for (int u = 0; u < 8; u++) {
                const uint32_t* kh = &khi[u >> 1][(u & 1) * 2];
                const uint32_t* kl = &klo[u >> 1][(u & 1) * 2];
                mma_f16(sacc[u], qhi, kh);
                mma_f16(sacc[u], qlo, kh);
                mma_f16(sacc[u], qhi, kl);
            }
        }

        // ---- in-register softmax ----
        const bool needmask = (kt >= 2 * qt);
        float tm1 = -1e30f, tm2 = -1e30f;
        #pragma unroll
        for (int u = 0; u < 8; u++) {
            int c0 = u * 8 + qq * 2;
            float s0 = sacc[u][0] * scale;
            float s1 = sacc[u][1] * scale;
            float s2 = sacc[u][2] * scale;
            float s3 = sacc[u][3] * scale;
            if (needmask) {
                if (k0 + c0     > q0 + r1) s0 = -1e30f;
                if (k0 + c0 + 1 > q0 + r1) s1 = -1e30f;
                if (k0 + c0     > q0 + r2) s2 = -1e30f;
                if (k0 + c0 + 1 > q0 + r2) s3 = -1e30f;
            }
            sacc[u][0] = s0; sacc[u][1] = s1;
            sacc[u][2] = s2; sacc[u][3] = s3;
            tm1 = fmaxf(tm1, fmaxf(s0, s1));
            tm2 = fmaxf(tm2, fmaxf(s2, s3));
        }
        tm1 = fmaxf(tm1, __shfl_xor_sync(0xffffffffu, tm1, 1));
        tm1 = fmaxf(tm1, __shfl_xor_sync(0xffffffffu, tm1, 2));
        tm2 = fmaxf(tm2, __shfl_xor_sync(0xffffffffu, tm2, 1));
        tm2 = fmaxf(tm2, __shfl_xor_sync(0xffffffffu, tm2, 2));
        float mn1 = fmaxf(m1, tm1), mn2 = fmaxf(m2, tm2);
        float a1 = __expf(m1 - mn1), a2 = __expf(m2 - mn2);
        m1 = mn1; m2 = mn2;

        uint32_t pf[4][4];
        float ts1 = 0.f, ts2 = 0.f;
        #pragma unroll
        for (int kk = 0; kk < 4; kk++) {
            #pragma unroll
            for (int half = 0; half < 2; half++) {
                int u = 2*kk + half;
                float e0 = __expf(sacc[u][0] - m1);
                float e1 = __expf(sacc[u][1] - m1);
                float e2 = __expf(sacc[u][2] - m2);
                float e3 = __expf(sacc[u][3] - m2);
                ts1 += e0 + e1;
                ts2 += e2 + e3;
                pf[kk][half*2]     = pack_f16_pair(e0, e1);
                pf[kk][half*2 + 1] = pack_f16_pair(e2, e3);
            }
        }
        ts1 += __shfl_xor_sync(0xffffffffu, ts1, 1);
        ts1 += __shfl_xor_sync(0xffffffffu, ts1, 2);
        ts2 += __shfl_xor_sync(0xffffffffu, ts2, 1);
        ts2 += __shfl_xor_sync(0xffffffffu, ts2, 2);
        l1 = l1 * a1 + ts1;
        l2 = l2 * a2 + ts2;

        #pragma unroll
        for (int u = 0; u < 16; u++) {
            acc[u][0] *= a1; acc[u][1] *= a1;
            acc[u][2] *= a2; acc[u][3] *= a2;
        }

        // ---- O += P @ V (2-term), P from registers ----
        #pragma unroll
        for (int ks = 0; ks < 4; ks++) {
            #pragma unroll
            for (int nh = 0; nh < 2; nh++) {
                uint32_t vhi[4][4], vlo[4][4];
                #pragma unroll
                for (int j = 0; j < 4; j++) {
                    int nbb = nh*8 + 2*j + selBn;
                    int kbb = 2*ks + selBk;
                    uint32_t off = (uint32_t)((nbb * 8 + kbb) * 128 + rrow * 16);
                    ldsm_x4(vhi[j], kvs + 32768u + off);
                    ldsm_x4(vlo[j], kvs + 49152u + off);
                }
                #pragma unroll
                for (int uu = 0; uu < 8; uu++) {
                    int u = nh*8 + uu;
                    const uint32_t* vh = &vhi[uu >> 1][(uu & 1) * 2];
                    const uint32_t* vl = &vlo[uu >> 1][(uu & 1) * 2];
                    mma_f16(acc[u], pf[ks], vh);
                    mma_f16(acc[u], pf[ks], vl);
                }
            }
        }
    }

    // ---- epilogue: normalize + write blocked fp16 hi ----
    {
        const int KB = HD_ >> 3;
        float inv1 = 1.f / l1;
        float inv2 = 1.f / l2;
        int grow1 = b*S_ + q0 + r1;
        int grow2 = grow1 + 8;
        #pragma unroll
        for (int u = 0; u < 16; u++) {
            int col = h * D_ + u*8 + qq * 2;
            int kb = col >> 3, cw = col & 7;
            size_t o1 = (((size_t)(grow1 >> 3) * KB + kb) << 6) + (size_t)(grow1 & 7) * 8 + cw;
            size_t o2 = (((size_t)(grow2 >> 3) * KB + kb) << 6) + (size_t)(grow2 & 7) * 8 + cw;
            *(uint32_t*)(g_attn_hi + o1) = pack_f16_pair(acc[u][0]*inv1, acc[u][1]*inv1);
            *(uint32_t*)(g_attn_hi + o2) = pack_f16_pair(acc[u][2]*inv2, acc[u][3]*inv2);
        }
    }
}

// ---------------- launch ----------------
extern "C" void kernel_launch(void* const* d_in, const int* in_sizes, int n_in,
                              void* d_out, int out_size) {
    const float* hidden = (const float*)d_in[0];
    const int*   pos    = (const int*)  d_in[2];
    const float* Wq     = (const float*)d_in[3];
    const float* bq     = (const float*)d_in[4];
    const float* Wk     = (const float*)d_in[5];
    const float* bk     = (const float*)d_in[6];
    const float* Wv     = (const float*)d_in[7];
    const float* bv     = (const float*)d_in[8];
    const float* Wo     = (const float*)d_in[9];
    float* out = (float*)d_out;

    const size_t gsmem = 98304;    // 2 x 48KB stages -> 2 CTAs/SM
    cudaFuncSetAttribute(qkv_gemm_kernel, cudaFuncAttributeMaxDynamicSharedMemorySize, (int)gsmem);
    cudaFuncSetAttribute(o_gemm_kernel,   cudaFuncAttributeMaxDynamicSharedMemorySize, (int)gsmem);
    cudaFuncSetAttribute(flash_mma_kernel, cudaFuncAttributeMaxDynamicSharedMemorySize, (int)FTOT);

    prep_all_kernel<<<PREP_TOTAL, 256>>>(hidden, Wq, Wk, Wv, Wo);
    qkv_gemm_kernel<<<dim3(48, M_/128), 256, gsmem>>>(bq, bk, bv, pos);
    flash_mma_kernel<<<dim3(S_/128, H_, B_), 256, FTOT>>>();
    o_gemm_kernel<<<dim3(E_/128, M_/128), 256, gsmem>>>(out);
}

// round 15
// speedup vs baseline: 1.5874x; 1.0044x over previous
#include <cuda_runtime.h>
#include <cuda_fp16.h>
#include <math.h>
#include <stdint.h>

#define B_    2
#define S_    2048
#define E_    4096
#define H_    32
#define KVH_  8
#define D_    128
#define HD_   (H_*D_)      // 4096
#define KVHD_ (KVH_*D_)    // 1024
#define M_    (B_*S_)      // 4096

// ---------------- scratch (no allocations allowed) ----------------
__device__ float g_cos [S_*(D_/2)];
__device__ float g_sin [S_*(D_/2)];

__device__ __align__(16) __half g_hid_hi [(size_t)M_*E_];
__device__ __align__(16) __half g_wq_hi  [(size_t)HD_*E_];
__device__ __align__(16) __half g_wq_lo  [(size_t)HD_*E_];
__device__ __align__(16) __half g_wk_hi  [(size_t)KVHD_*E_];
__device__ __align__(16) __half g_wk_lo  [(size_t)KVHD_*E_];
__device__ __align__(16) __half g_wv_hi  [(size_t)KVHD_*E_];
__device__ __align__(16) __half g_wv_lo  [(size_t)KVHD_*E_];
__device__ __align__(16) __half g_wo_hi  [(size_t)E_*HD_];
__device__ __align__(16) __half g_wo_lo  [(size_t)E_*HD_];
__device__ __align__(16) __half g_attn_hi[(size_t)M_*HD_];

__device__ __align__(16) __half g_qb_hi[(size_t)B_*H_*S_*D_];
__device__ __align__(16) __half g_qb_lo[(size_t)B_*H_*S_*D_];
__device__ __align__(16) __half g_kb_hi[(size_t)B_*KVH_*S_*D_];
__device__ __align__(16) __half g_kb_lo[(size_t)B_*KVH_*S_*D_];
__device__ __align__(16) __half g_vb_hi[(size_t)B_*KVH_*S_*D_];
__device__ __align__(16) __half g_vb_lo[(size_t)B_*KVH_*S_*D_];

// ---------------- helpers ----------------
__device__ __forceinline__ uint32_t smem_u32(const void* p) {
    uint32_t a;
    asm("{ .reg .u64 t; cvta.to.shared.u64 t, %1; cvt.u32.u64 %0, t; }" : "=r"(a) : "l"(p));
    return a;
}
__device__ __forceinline__ void ldsm_x4(uint32_t* r, uint32_t a) {
    asm volatile("ldmatrix.sync.aligned.m8n8.x4.shared.b16 {%0,%1,%2,%3}, [%4];"
                 : "=r"(r[0]), "=r"(r[1]), "=r"(r[2]), "=r"(r[3]) : "r"(a));
}
__device__ __forceinline__ void mma_f16(float* c, const uint32_t* a, const uint32_t* b) {
    asm volatile("mma.sync.aligned.m16n8k16.row.col.f32.f16.f16.f32 "
                 "{%0,%1,%2,%3}, {%4,%5,%6,%7}, {%8,%9}, {%0,%1,%2,%3};"
                 : "+f"(c[0]), "+f"(c[1]), "+f"(c[2]), "+f"(c[3])
                 : "r"(a[0]), "r"(a[1]), "r"(a[2]), "r"(a[3]), "r"(b[0]), "r"(b[1]));
}
__device__ __forceinline__ void cp16(uint32_t saddr, const void* g) {
    asm volatile("cp.async.cg.shared.global [%0], [%1], 16;" :: "r"(saddr), "l"(g) : "memory");
}
__device__ __forceinline__ uint32_t pack_f16_split(float x0, float x1, uint32_t& lo_out) {
    __half h0 = __float2half_rn(x0);
    __half h1 = __float2half_rn(x1);
    __half l0 = __float2half_rn(x0 - __half2float(h0));
    __half l1 = __float2half_rn(x1 - __half2float(h1));
    __half2 hp = __halves2half2(h0, h1);
    __half2 lp = __halves2half2(l0, l1);
    lo_out = *reinterpret_cast<uint32_t*>(&lp);
    return *reinterpret_cast<uint32_t*>(&hp);
}
__device__ __forceinline__ uint32_t pack_f16_pair(float x0, float x1) {
    __half2 hp = __halves2half2(__float2half_rn(x0), __float2half_rn(x1));
    return *reinterpret_cast<uint32_t*>(&hp);
}

// ---------------- unified prep kernel ----------------
#define RT_B   ((S_*(D_/2))/256)
#define SP_B   ((M_*(E_>>3))/256)
#define WQ_B   ((HD_/32)*(E_/32))
#define WK_B   ((KVHD_/32)*(E_/32))
#define WV_B   WK_B
#define WO_B   ((E_/32)*(HD_/32))
#define PREP_TOTAL (RT_B + SP_B + WQ_B + WK_B + WV_B + WO_B)

__device__ __forceinline__ void do_wtrans(const float* __restrict__ W,
                                          __half* __restrict__ Thi, __half* __restrict__ Tlo,
                                          int Kdim, int Ndim, int seg, int tid,
                                          float (*tile)[33]) {
    int nTiles = Ndim / 32;
    int bx = seg % nTiles, by = seg / nTiles;
    int n0 = bx * 32, k0 = by * 32;
    int tx = tid & 31, ty = tid >> 5;
    #pragma unroll
    for (int dy = 0; dy < 32; dy += 8)
        tile[ty + dy][tx] = W[(size_t)(k0 + ty + dy) * Ndim + n0 + tx];
    __syncthreads();
    int KB = Kdim >> 3;
    #pragma unroll
    for (int dy = 0; dy < 32; dy += 8) {
        int n = n0 + ty + dy, k = k0 + tx;
        float x = tile[tx][ty + dy];
        __half h = __float2half_rn(x);
        __half l = __float2half_rn(x - __half2float(h));
        size_t off = (((size_t)(n >> 3) * KB + (k >> 3)) << 6) + (size_t)(n & 7) * 8 + (k & 7);
        Thi[off] = h;
        Tlo[off] = l;
    }
}

__global__ __launch_bounds__(256)
void prep_all_kernel(const float* __restrict__ hidden,
                     const float* __restrict__ Wq, const float* __restrict__ Wk,
                     const float* __restrict__ Wv, const float* __restrict__ Wo) {
    __shared__ float tile[32][33];
    const int tid = threadIdx.x;
    int blk = blockIdx.x;

    if (blk < RT_B) {
        int idx = blk * 256 + tid;
        int t = idx / (D_/2);
        int i = idx % (D_/2);
        double inv = exp(-((double)(2*i) / (double)D_) * log(10000.0));
        double ang = (double)t * inv;
        g_cos[idx] = (float)cos(ang);
        g_sin[idx] = (float)sin(ang);
        return;
    }
    blk -= RT_B;
    if (blk < SP_B) {
        int idx = blk * 256 + tid;
        const int KB = E_ >> 3;
        int row = idx / KB, kb = idx % KB;
        const float* src = hidden + (size_t)row * E_ + kb * 8;
        float4 v0 = *(const float4*)src;
        float4 v1 = *(const float4*)(src + 4);
        uint32_t hw[4];
        hw[0] = pack_f16_pair(v0.x, v0.y);
        hw[1] = pack_f16_pair(v0.z, v0.w);
        hw[2] = pack_f16_pair(v1.x, v1.y);
        hw[3] = pack_f16_pair(v1.z, v1.w);
        size_t off = (((size_t)(row >> 3) * KB + kb) << 6) + (size_t)(row & 7) * 8;
        *(uint4*)(g_hid_hi + off) = make_uint4(hw[0], hw[1], hw[2], hw[3]);
        return;
    }
    blk -= SP_B;
    if (blk < WQ_B) { do_wtrans(Wq, g_wq_hi, g_wq_lo, E_,  HD_, blk, tid, tile); return; }
    blk -= WQ_B;
    if (blk < WK_B) { do_wtrans(Wk, g_wk_hi, g_wk_lo, E_,  KVHD_, blk, tid, tile); return; }
    blk -= WK_B;
    if (blk < WV_B) { do_wtrans(Wv, g_wv_hi, g_wv_lo, E_,  KVHD_, blk, tid, tile); return; }
    blk -= WV_B;
    do_wtrans(Wo, g_wo_hi, g_wo_lo, HD_, E_, blk, tid, tile);
}

// ---------------- GEMM mainloop (2-stage, 96KB, 2 CTAs/SM, 1 sync/chunk) ----------------
// Top sync (after wait_group 0) orders: every warp finished iter i-1's ldsm reads
// before stage (i+1)&1 (read in i-1) is overwritten by the prefetch below it.
#define GEMM_MAINLOOP(pAhi_, pBhi_, pBlo_, Kdim_)                                           \
    const int KB = (Kdim_) >> 3;                                                            \
    const int NC = (Kdim_) >> 6;                                                            \
    float acc[4][4][4];                                                                     \
    _Pragma("unroll") for (int t = 0; t < 4; t++)                                           \
        _Pragma("unroll") for (int u = 0; u < 4; u++)                                       \
            _Pragma("unroll") for (int j = 0; j < 4; j++) acc[t][u][j] = 0.f;               \
    auto prefetch = [&](int chunk, int st) {                                                \
        uint32_t sbuf = sbase + (uint32_t)st * 49152u;                                      \
        int kb0 = chunk << 3;                                                               \
        _Pragma("unroll") for (int j = 0; j < 4; j++) {                                     \
            int u = tid + j * 256;                                                          \
            int rb = u >> 6, kb = (u >> 3) & 7, w = u & 7;                                  \
            size_t gA = ((size_t)(mb0 + rb) * KB + (kb0 + kb)) * 128u + (size_t)w * 16u;    \
            size_t gB = ((size_t)(nb0 + rb) * KB + (kb0 + kb)) * 128u + (size_t)w * 16u;    \
            uint32_t so = (uint32_t)(((rb * 8 + kb) * 8 + w) * 16);                         \
            cp16(sbuf + so,          (const char*)(pAhi_) + gA);                            \
            cp16(sbuf + 16384u + so, (const char*)(pBhi_) + gB);                            \
            cp16(sbuf + 32768u + so, (const char*)(pBlo_) + gB);                            \
        }                                                                                   \
    };                                                                                      \
    const int wmb   = (warp >> 2) * 8;                                                      \
    const int wnb   = (warp & 3) * 4;                                                       \
    const int selAm = (lane >> 3) & 1;                                                      \
    const int selAk = (lane >> 3) >> 1;                                                     \
    const int selBn = (lane >> 4) & 1;                                                      \
    const int selBk = (lane >> 3) & 1;                                                      \
    const int rrow  = lane & 7;                                                             \
    prefetch(0, 0);                                                                         \
    asm volatile("cp.async.commit_group;" ::: "memory");                                    \
    for (int i = 0; i < NC; i++) {                                                          \
        asm volatile("cp.async.wait_group 0;" ::: "memory");                                \
        __syncthreads();                                                                    \
        if (i + 1 < NC) {                                                                   \
            prefetch(i + 1, (i + 1) & 1);                                                   \
            asm volatile("cp.async.commit_group;" ::: "memory");                            \
        }                                                                                   \
        uint32_t sbuf = sbase + (uint32_t)(i & 1) * 49152u;                                 \
        _Pragma("unroll") for (int ks = 0; ks < 4; ks++) {                                  \
            uint32_t ahi[4][4], bhi[2][4], blo[2][4];                                       \
            _Pragma("unroll") for (int t = 0; t < 4; t++) {                                 \
                int mbb = wmb + 2*t + selAm;                                                \
                int kbb = 2*ks + selAk;                                                     \
                uint32_t off = (uint32_t)((mbb * 8 + kbb) * 128 + rrow * 16);               \
                ldsm_x4(ahi[t], sbuf + off);                                                \
            }                                                                               \
            _Pragma("unroll") for (int u2 = 0; u2 < 2; u2++) {                              \
                int nbb = wnb + 2*u2 + selBn;                                               \
                int kbb = 2*ks + selBk;                                                     \
                uint32_t off = (uint32_t)((nbb * 8 + kbb) * 128 + rrow * 16);               \
                ldsm_x4(bhi[u2], sbuf + 16384u + off);                                      \
                ldsm_x4(blo[u2], sbuf + 32768u + off);                                      \
            }                                                                               \
            _Pragma("unroll") for (int t = 0; t < 4; t++)                                   \
                _Pragma("unroll") for (int u = 0; u < 4; u++) {                             \
                    const uint32_t* bh = &bhi[u >> 1][(u & 1) * 2];                         \
                    const uint32_t* bl = &blo[u >> 1][(u & 1) * 2];                         \
                    mma_f16(acc[t][u], ahi[t], bh);                                         \
                    mma_f16(acc[t][u], ahi[t], bl);                                         \
                }                                                                           \
        }                                                                                   \
    {

// ---------------- merged QKV projection kernel ----------------
__global__ __launch_bounds__(256, 2)
void qkv_gemm_kernel(const float* __restrict__ bq, const float* __restrict__ bk,
                     const float* __restrict__ bv, const int* __restrict__ pos) {
    extern __shared__ char smc[];
    const uint32_t sbase = smem_u32(smc);
    const int tid  = threadIdx.x;
    const int warp = tid >> 5, lane = tid & 31;
    const int mb0  = blockIdx.y * 16;
    const int bx   = blockIdx.x;

    const __half *pBh, *pBl;
    const float* bias;
    int nb0, mode, hh;
    if (bx < 32)      { pBh = g_wq_hi; pBl = g_wq_lo; bias = bq; nb0 = bx * 16;        mode = 1; hh = bx; }
    else if (bx < 40) { pBh = g_wk_hi; pBl = g_wk_lo; bias = bk; nb0 = (bx - 32) * 16; mode = 2; hh = bx - 32; }
    else              { pBh = g_wv_hi; pBl = g_wv_lo; bias = bv; nb0 = (bx - 40) * 16; mode = 3; hh = bx - 40; }

    GEMM_MAINLOOP(g_hid_hi, pBh, pBl, E_)
    }}   // close inner block + mainloop for

    const int gg = lane >> 2, qq = lane & 3;

    float* st = (float*)smc;
    __syncthreads();   // all warps done with final stage ldsm reads before smem reuse
    {
        const int lrow = (warp >> 2) * 64;
        const int lcol = (warp & 3) * 32;
        #pragma unroll
        for (int t = 0; t < 4; t++) {
            #pragma unroll
            for (int u = 0; u < 4; u++) {
                int r = lrow + t * 16 + gg;
                int c = lcol + u * 8 + qq * 2;
                float2 b2 = *(const float2*)(bias + nb0 * 8 + c);
                st[r * 132 + c]           = acc[t][u][0] + b2.x;
                st[r * 132 + c + 1]       = acc[t][u][1] + b2.y;
                st[(r + 8) * 132 + c]     = acc[t][u][2] + b2.x;
                st[(r + 8) * 132 + c + 1] = acc[t][u][3] + b2.y;
            }
        }
    }
    __syncthreads();

    if (mode == 1 || mode == 2) {
        __half* oHi = (mode == 1) ? g_qb_hi : g_kb_hi;
        __half* oLo = (mode == 1) ? g_qb_lo : g_kb_lo;
        #pragma unroll
        for (int j = 0; j < 4; j++) {
            int idx = tid + j * 256;
            int kbl = idx & 7;
            int r   = idx >> 3;
            int token = blockIdx.y * 128 + r;
            int b = token >> 11;
            int s = token & (S_ - 1);
            int p = pos[b * S_ + s];
            int i0 = kbl * 8;
            float y1[8], y2[8];
            #pragma unroll
            for (int jj = 0; jj < 8; jj++) {
                float x1 = st[r * 132 + i0 + jj];
                float x2 = st[r * 132 + 64 + i0 + jj];
                float c  = g_cos[p * 64 + i0 + jj];
                float sn = g_sin[p * 64 + i0 + jj];
                y1[jj] = x1 * c - x2 * sn;
                y2[jj] = x2 * c + x1 * sn;
            }
            uint32_t h1[4], l1[4], h2[4], l2[4];
            #pragma unroll
            for (int jj = 0; jj < 4; jj++) {
                h1[jj] = pack_f16_split(y1[2*jj], y1[2*jj+1], l1[jj]);
                h2[jj] = pack_f16_split(y2[2*jj], y2[2*jj+1], l2[jj]);
            }
            size_t dbase;
            if (mode == 1) {
                int qt = s >> 7, sbw = (s >> 3) & 15;
                dbase = ((((size_t)(b * H_ + hh) * (S_/128) + qt) * 16 + sbw) * 16);
            } else {
                int kt = s >> 6, sbw = (s >> 3) & 7;
                dbase = ((((size_t)(b * KVH_ + hh) * (S_/64) + kt) * 8 + sbw) * 16);
            }
            int rr = s & 7;
            size_t o1 = (dbase + kbl)     * 64 + (size_t)rr * 8;
            size_t o2 = (dbase + kbl + 8) * 64 + (size_t)rr * 8;
            *(uint4*)(oHi + o1) = make_uint4(h1[0], h1[1], h1[2], h1[3]);
            *(uint4*)(oLo + o1) = make_uint4(l1[0], l1[1], l1[2], l1[3]);
            *(uint4*)(oHi + o2) = make_uint4(h2[0], h2[1], h2[2], h2[3]);
            *(uint4*)(oLo + o2) = make_uint4(l2[0], l2[1], l2[2], l2[3]);
        }
    } else {
        const int token0 = blockIdx.y * 128;
        const int b = token0 >> 11;
        const int sbase0 = token0 & (S_ - 1);
        #pragma unroll
        for (int j = 0; j < 8; j++) {
            int idx = tid + j * 256;
            int dr  = idx & 7;
            int sbw = (idx >> 3) & 7;
            int db  = (idx >> 6) & 15;
            int ktl = idx >> 10;
            int d = db * 8 + dr;
            int sl = ktl * 64 + sbw * 8;
            uint32_t hw[4], lw[4];
            #pragma unroll
            for (int jj = 0; jj < 4; jj++) {
                float x0 = st[(sl + 2*jj)     * 132 + d];
                float x1 = st[(sl + 2*jj + 1) * 132 + d];
                hw[jj] = pack_f16_split(x0, x1, lw[jj]);
            }
            int s = sbase0 + sl;
            int kt = s >> 6;
            size_t off = (((((size_t)(b * KVH_ + hh) * (S_/64) + kt) * 16 + db) * 8 + sbw) * 64)
                       + (size_t)dr * 8;
            *(uint4*)(g_vb_hi + off) = make_uint4(hw[0], hw[1], hw[2], hw[3]);
            *(uint4*)(g_vb_lo + off) = make_uint4(lw[0], lw[1], lw[2], lw[3]);
        }
    }
}

// ---------------- O-projection kernel ----------------
__global__ __launch_bounds__(256, 2)
void o_gemm_kernel(float* __restrict__ C) {
    extern __shared__ char smc[];
    const uint32_t sbase = smem_u32(smc);
    const int tid  = threadIdx.x;
    const int warp = tid >> 5, lane = tid & 31;
    const int mb0  = blockIdx.y * 16;
    const int nb0  = blockIdx.x * 16;

    GEMM_MAINLOOP(g_attn_hi, g_wo_hi, g_wo_lo, HD_)
    }}

    const int mrow = mb0 * 8 + (warp >> 2) * 64;
    const int ncol = nb0 * 8 + (warp & 3) * 32;
    const int gg = lane >> 2, qq = lane & 3;
    #pragma unroll
    for (int t = 0; t < 4; t++) {
        #pragma unroll
        for (int u = 0; u < 4; u++) {
            int row = mrow + t * 16 + gg;
            int col = ncol + u * 8 + qq * 2;
            *(float2*)(C + (size_t)row * E_ + col)       = make_float2(acc[t][u][0], acc[t][u][1]);
            *(float2*)(C + (size_t)(row + 8) * E_ + col) = make_float2(acc[t][u][2], acc[t][u][3]);
        }
    }
}

// ---------------- flash attention: FA2 register repack, exp2 softmax ----------------
#define FQHI   0u
#define FQLO   32768u
#define FKV0   65536u
#define FTOT   196608u

__global__ __launch_bounds__(256, 1)
void flash_mma_kernel() {
    extern __shared__ char fs[];
    const uint32_t sb = smem_u32(fs);

    const int tid  = threadIdx.x;
    const int warp = tid >> 5, lane = tid & 31;
    const int qt = (S_/128 - 1) - blockIdx.x;
    const int h = blockIdx.y, b = blockIdx.z;
    const int q0 = qt * 128;
    const int kvh = h >> 2;
    // scale * log2(e): softmax computed in base-2 domain (bare MUFU.EX2)
    const float scale2 = 0.08838834764831845f * 1.4426950408889634f;

    const int selAm = (lane >> 3) & 1;
    const int selAk = (lane >> 3) >> 1;
    const int selBn = (lane >> 4) & 1;
    const int selBk = (lane >> 3) & 1;
    const int rrow  = lane & 7;
    const int gr = lane >> 2, qq = lane & 3;
    const int wm = warp * 16;

    const size_t kvbase = (size_t)(b*KVH_ + kvh) * (S_/64);
    auto prefetch_kv = [&](int kt, int st) {
        size_t tb = (kvbase + kt) * 16384u;   // byte offset of 16KB tile
        uint32_t sbuf = sb + FKV0 + (uint32_t)st * 65536u;
        #pragma unroll
        for (int j = 0; j < 4; j++) {
            uint32_t u = (uint32_t)(tid + j * 256) * 16u;
            cp16(sbuf + u,           (const char*)g_kb_hi + tb + u);
            cp16(sbuf + 16384u + u,  (const char*)g_kb_lo + tb + u);
            cp16(sbuf + 32768u + u,  (const char*)g_vb_hi + tb + u);
            cp16(sbuf + 49152u + u,  (const char*)g_vb_lo + tb + u);
        }
    };

    {
        const char* qh = (const char*)(g_qb_hi + (((size_t)(b*H_ + h) * (S_/128) + qt) << 14));
        const char* ql = (const char*)(g_qb_lo + (((size_t)(b*H_ + h) * (S_/128) + qt) << 14));
        #pragma unroll
        for (int j = 0; j < 8; j++) {
            uint32_t u = (uint32_t)(tid + j * 256) * 16u;
            cp16(sb + FQHI + u, qh + u);
            cp16(sb + FQLO + u, ql + u);
        }
        prefetch_kv(0, 0);
        asm volatile("cp.async.commit_group;" ::: "memory");
    }

    float m1 = -1e30f, m2 = -1e30f, l1 = 0.f, l2 = 0.f;
    float acc[16][4];
    #pragma unroll
    for (int u = 0; u < 16; u++)
        #pragma unroll
        for (int j = 0; j < 4; j++) acc[u][j] = 0.f;

    const int r1 = wm + gr;
    const int r2 = r1 + 8;

    const int NK = 2 * qt + 2;
    for (int kt = 0; kt < NK; kt++) {
        const int k0 = kt * 64;
        asm volatile("cp.async.wait_group 0;" ::: "memory");
        __syncthreads();
        const uint32_t kvs = sb + FKV0 + (uint32_t)(kt & 1) * 65536u;

        if (kt + 1 < NK) {
            prefetch_kv(kt + 1, (kt + 1) & 1);
            asm volatile("cp.async.commit_group;" ::: "memory");
        }

        // ---- S = Q @ K^T (3-term), warp stripe 16x64 ----
        float sacc[8][4];
        #pragma unroll
        for (int u = 0; u < 8; u++)
            #pragma unroll
            for (int j = 0; j < 4; j++) sacc[u][j] = 0.f;

        #pragma unroll
        for (int ks = 0; ks < 8; ks++) {
            uint32_t qhi[4], qlo[4], khi[4][4], klo[4][4];
            {
                int mbb = 2*warp + selAm;
                int kbb = 2*ks + selAk;
                uint32_t off = (uint32_t)((mbb * 16 + kbb) * 128 + rrow * 16);
                ldsm_x4(qhi, sb + FQHI + off);
                ldsm_x4(qlo, sb + FQLO + off);
            }
            #pragma unroll
            for (int j = 0; j < 4; j++) {
                int nbb = 2*j + selBn;
                int kbb = 2*ks + selBk;
                uint32_t off = (uint32_t)((nbb * 16 + kbb) * 128 + rrow * 16);
                ldsm_x4(khi[j], kvs + off);
                ldsm_x4(klo[j], kvs + 16384u + off);
            }
            #pragma unroll
            for (int u = 0; u < 8; u++) {
                const uint32_t* kh = &khi[u >> 1][(u & 1) * 2];
                const uint32_t* kl = &klo[u >> 1][(u & 1) * 2];
                mma_f16(sacc[u], qhi, kh);
                mma_f16(sacc[u], qlo, kh);
                mma_f16(sacc[u], qhi, kl);
            }
        }

        // ---- in-register softmax (base-2 domain) ----
        const bool needmask = (kt >= 2 * qt);
        float tm1 = -1e30f, tm2 = -1e30f;
        #pragma unroll
        for (int u = 0; u < 8; u++) {
            int c0 = u * 8 + qq * 2;
            float s0 = sacc[u][0] * scale2;
            float s1 = sacc[u][1] * scale2;
            float s2 = sacc[u][2] * scale2;
            float s3 = sacc[u][3] * scale2;
            if (needmask) {
                if (k0 + c0     > q0 + r1) s0 = -1e30f;
                if (k0 + c0 + 1 > q0 + r1) s1 = -1e30f;
                if (k0 + c0     > q0 + r2) s2 = -1e30f;
                if (k0 + c0 + 1 > q0 + r2) s3 = -1e30f;
            }
            sacc[u][0] = s0; sacc[u][1] = s1;
            sacc[u][2] = s2; sacc[u][3] = s3;
            tm1 = fmaxf(tm1, fmaxf(s0, s1));
            tm2 = fmaxf(tm2, fmaxf(s2, s3));
        }
        tm1 = fmaxf(tm1, __shfl_xor_sync(0xffffffffu, tm1, 1));
        tm1 = fmaxf(tm1, __shfl_xor_sync(0xffffffffu, tm1, 2));
        tm2 = fmaxf(tm2, __shfl_xor_sync(0xffffffffu, tm2, 1));
        tm2 = fmaxf(tm2, __shfl_xor_sync(0xffffffffu, tm2, 2));
        float mn1 = fmaxf(m1, tm1), mn2 = fmaxf(m2, tm2);
        float a1 = exp2f(m1 - mn1), a2 = exp2f(m2 - mn2);
        m1 = mn1; m2 = mn2;

        uint32_t pf[4][4];
        float ts1 = 0.f, ts2 = 0.f;
        #pragma unroll
        for (int kk = 0; kk < 4; kk++) {
            #pragma unroll
            for (int half = 0; half < 2; half++) {
                int u = 2*kk + half;
                float e0 = exp2f(sacc[u][0] - m1);
                float e1 = exp2f(sacc[u][1] - m1);
                float e2 = exp2f(sacc[u][2] - m2);
                float e3 = exp2f(sacc[u][3] - m2);
                ts1 += e0 + e1;
                ts2 += e2 + e3;
                pf[kk][half*2]     = pack_f16_pair(e0, e1);
                pf[kk][half*2 + 1] = pack_f16_pair(e2, e3);
            }
        }
        ts1 += __shfl_xor_sync(0xffffffffu, ts1, 1);
        ts1 += __shfl_xor_sync(0xffffffffu, ts1, 2);
        ts2 += __shfl_xor_sync(0xffffffffu, ts2, 1);
        ts2 += __shfl_xor_sync(0xffffffffu, ts2, 2);
        l1 = l1 * a1 + ts1;
        l2 = l2 * a2 + ts2;

        #pragma unroll
        for (int u = 0; u < 16; u++) {
            acc[u][0] *= a1; acc[u][1] *= a1;
            acc[u][2] *= a2; acc[u][3] *= a2;
        }

        // ---- O += P @ V (2-term), P from registers ----
        #pragma unroll
        for (int ks = 0; ks < 4; ks++) {
            #pragma unroll
            for (int nh = 0; nh < 2; nh++) {
                uint32_t vhi[4][4], vlo[4][4];
                #pragma unroll
                for (int j = 0; j < 4; j++) {
                    int nbb = nh*8 + 2*j + selBn;
                    int kbb = 2*ks + selBk;
                    uint32_t off = (uint32_t)((nbb * 8 + kbb) * 128 + rrow * 16);
                    ldsm_x4(vhi[j], kvs + 32768u + off);
                    ldsm_x4(vlo[j], kvs + 49152u + off);
                }
                #pragma unroll
                for (int uu = 0; uu < 8; uu++) {
                    int u = nh*8 + uu;
                    const uint32_t* vh = &vhi[uu >> 1][(uu & 1) * 2];
                    const uint32_t* vl = &vlo[uu >> 1][(uu & 1) * 2];
                    mma_f16(acc[u], pf[ks], vh);
                    mma_f16(acc[u], pf[ks], vl);
                }
            }
        }
    }

    // ---- epilogue: normalize + write blocked fp16 hi ----
    {
        const int KB = HD_ >> 3;
        float inv1 = 1.f / l1;
        float inv2 = 1.f / l2;
        int grow1 = b*S_ + q0 + r1;
        int grow2 = grow1 + 8;
        #pragma unroll
        for (int u = 0; u < 16; u++) {
            int col = h * D_ + u*8 + qq * 2;
            int kb = col >> 3, cw = col & 7;
            size_t o1 = (((size_t)(grow1 >> 3) * KB + kb) << 6) + (size_t)(grow1 & 7) * 8 + cw;
            size_t o2 = (((size_t)(grow2 >> 3) * KB + kb) << 6) + (size_t)(grow2 & 7) * 8 + cw;
            *(uint32_t*)(g_attn_hi + o1) = pack_f16_pair(acc[u][0]*inv1, acc[u][1]*inv1);
            *(uint32_t*)(g_attn_hi + o2) = pack_f16_pair(acc[u][2]*inv2, acc[u][3]*inv2);
        }
    }
}

// ---------------- launch ----------------
extern "C" void kernel_launch(void* const* d_in, const int* in_sizes, int n_in,
                              void* d_out, int out_size) {
    const float* hidden = (const float*)d_in[0];
    const int*   pos    = (const int*)  d_in[2];
    const float* Wq     = (const float*)d_in[3];
    const float* bq     = (const float*)d_in[4];
    const float* Wk     = (const float*)d_in[5];
    const float* bk     = (const float*)d_in[6];
    const float* Wv     = (const float*)d_in[7];
    const float* bv     = (const float*)d_in[8];
    const float* Wo     = (const float*)d_in[9];
    float* out = (float*)d_out;

    const size_t gsmem = 98304;    // 2 x 48KB stages -> 2 CTAs/SM
    cudaFuncSetAttribute(qkv_gemm_kernel, cudaFuncAttributeMaxDynamicSharedMemorySize, (int)gsmem);
    cudaFuncSetAttribute(o_gemm_kernel,   cudaFuncAttributeMaxDynamicSharedMemorySize, (int)gsmem);
    cudaFuncSetAttribute(flash_mma_kernel, cudaFuncAttributeMaxDynamicSharedMemorySize, (int)FTOT);

    prep_all_kernel<<<PREP_TOTAL, 256>>>(hidden, Wq, Wk, Wv, Wo);
    qkv_gemm_kernel<<<dim3(48, M_/128), 256, gsmem>>>(bq, bk, bv, pos);
    flash_mma_kernel<<<dim3(S_/128, H_, B_), 256, FTOT>>>();
    o_gemm_kernel<<<dim3(E_/128, M_/128), 256, gsmem>>>(out);
}

// round 16
// speedup vs baseline: 1.5880x; 1.0004x over previous
#include <cuda_runtime.h>
#include <cuda_fp16.h>
#include <math.h>
#include <stdint.h>

#define B_    2
#define S_    2048
#define E_    4096
#define H_    32
#define KVH_  8
#define D_    128
#define HD_   (H_*D_)      // 4096
#define KVHD_ (KVH_*D_)    // 1024
#define M_    (B_*S_)      // 4096

// ---------------- scratch (no allocations allowed) ----------------
__device__ float g_cos [S_*(D_/2)];
__device__ float g_sin [S_*(D_/2)];

__device__ __align__(16) __half g_hid_hi [(size_t)M_*E_];
__device__ __align__(16) __half g_wq_hi  [(size_t)HD_*E_];
__device__ __align__(16) __half g_wq_lo  [(size_t)HD_*E_];
__device__ __align__(16) __half g_wk_hi  [(size_t)KVHD_*E_];
__device__ __align__(16) __half g_wk_lo  [(size_t)KVHD_*E_];
__device__ __align__(16) __half g_wv_hi  [(size_t)KVHD_*E_];
__device__ __align__(16) __half g_wv_lo  [(size_t)KVHD_*E_];
__device__ __align__(16) __half g_wo_hi  [(size_t)E_*HD_];
__device__ __align__(16) __half g_wo_lo  [(size_t)E_*HD_];
__device__ __align__(16) __half g_attn_hi[(size_t)M_*HD_];

__device__ __align__(16) __half g_qb_hi[(size_t)B_*H_*S_*D_];
__device__ __align__(16) __half g_qb_lo[(size_t)B_*H_*S_*D_];
__device__ __align__(16) __half g_kb_hi[(size_t)B_*KVH_*S_*D_];
__device__ __align__(16) __half g_kb_lo[(size_t)B_*KVH_*S_*D_];
__device__ __align__(16) __half g_vb_hi[(size_t)B_*KVH_*S_*D_];
__device__ __align__(16) __half g_vb_lo[(size_t)B_*KVH_*S_*D_];

// ---------------- helpers ----------------
__device__ __forceinline__ uint32_t smem_u32(const void* p) {
    uint32_t a;
    asm("{ .reg .u64 t; cvta.to.shared.u64 t, %1; cvt.u32.u64 %0, t; }" : "=r"(a) : "l"(p));
    return a;
}
__device__ __forceinline__ void ldsm_x4(uint32_t* r, uint32_t a) {
    asm volatile("ldmatrix.sync.aligned.m8n8.x4.shared.b16 {%0,%1,%2,%3}, [%4];"
                 : "=r"(r[0]), "=r"(r[1]), "=r"(r[2]), "=r"(r[3]) : "r"(a));
}
__device__ __forceinline__ void mma_f16(float* c, const uint32_t* a, const uint32_t* b) {
    asm volatile("mma.sync.aligned.m16n8k16.row.col.f32.f16.f16.f32 "
                 "{%0,%1,%2,%3}, {%4,%5,%6,%7}, {%8,%9}, {%0,%1,%2,%3};"
                 : "+f"(c[0]), "+f"(c[1]), "+f"(c[2]), "+f"(c[3])
                 : "r"(a[0]), "r"(a[1]), "r"(a[2]), "r"(a[3]), "r"(b[0]), "r"(b[1]));
}
__device__ __forceinline__ void cp16(uint32_t saddr, const void* g) {
    asm volatile("cp.async.cg.shared.global [%0], [%1], 16;" :: "r"(saddr), "l"(g) : "memory");
}
__device__ __forceinline__ uint32_t pack_f16_split(float x0, float x1, uint32_t& lo_out) {
    __half h0 = __float2half_rn(x0);
    __half h1 = __float2half_rn(x1);
    __half l0 = __float2half_rn(x0 - __half2float(h0));
    __half l1 = __float2half_rn(x1 - __half2float(h1));
    __half2 hp = __halves2half2(h0, h1);
    __half2 lp = __halves2half2(l0, l1);
    lo_out = *reinterpret_cast<uint32_t*>(&lp);
    return *reinterpret_cast<uint32_t*>(&hp);
}
__device__ __forceinline__ uint32_t pack_f16_pair(float x0, float x1) {
    __half2 hp = __halves2half2(__float2half_rn(x0), __float2half_rn(x1));
    return *reinterpret_cast<uint32_t*>(&hp);
}

// ---------------- unified prep kernel ----------------
#define RT_B   ((S_*(D_/2))/256)
#define SP_B   ((M_*(E_>>3))/256)
#define WQ_B   ((HD_/32)*(E_/32))
#define WK_B   ((KVHD_/32)*(E_/32))
#define WV_B   WK_B
#define WO_B   ((E_/32)*(HD_/32))
#define PREP_TOTAL (RT_B + SP_B + WQ_B + WK_B + WV_B + WO_B)

__device__ __forceinline__ void do_wtrans(const float* __restrict__ W,
                                          __half* __restrict__ Thi, __half* __restrict__ Tlo,
                                          int Kdim, int Ndim, int seg, int tid,
                                          float (*tile)[33]) {
    int nTiles = Ndim / 32;
    int bx = seg % nTiles, by = seg / nTiles;
    int n0 = bx * 32, k0 = by * 32;
    int tx = tid & 31, ty = tid >> 5;
    #pragma unroll
    for (int dy = 0; dy < 32; dy += 8)
        tile[ty + dy][tx] = W[(size_t)(k0 + ty + dy) * Ndim + n0 + tx];
    __syncthreads();
    int KB = Kdim >> 3;
    #pragma unroll
    for (int dy = 0; dy < 32; dy += 8) {
        int n = n0 + ty + dy, k = k0 + tx;
        float x = tile[tx][ty + dy];
        __half h = __float2half_rn(x);
        __half l = __float2half_rn(x - __half2float(h));
        size_t off = (((size_t)(n >> 3) * KB + (k >> 3)) << 6) + (size_t)(n & 7) * 8 + (k & 7);
        Thi[off] = h;
        Tlo[off] = l;
    }
}

__global__ __launch_bounds__(256)
void prep_all_kernel(const float* __restrict__ hidden,
                     const float* __restrict__ Wq, const float* __restrict__ Wk,
                     const float* __restrict__ Wv, const float* __restrict__ Wo) {
    __shared__ float tile[32][33];
    const int tid = threadIdx.x;
    int blk = blockIdx.x;

    if (blk < RT_B) {
        int idx = blk * 256 + tid;
        int t = idx / (D_/2);
        int i = idx % (D_/2);
        double inv = exp(-((double)(2*i) / (double)D_) * log(10000.0));
        double ang = (double)t * inv;
        g_cos[idx] = (float)cos(ang);
        g_sin[idx] = (float)sin(ang);
        return;
    }
    blk -= RT_B;
    if (blk < SP_B) {
        int idx = blk * 256 + tid;
        const int KB = E_ >> 3;
        int row = idx / KB, kb = idx % KB;
        const float* src = hidden + (size_t)row * E_ + kb * 8;
        float4 v0 = *(const float4*)src;
        float4 v1 = *(const float4*)(src + 4);
        uint32_t hw[4];
        hw[0] = pack_f16_pair(v0.x, v0.y);
        hw[1] = pack_f16_pair(v0.z, v0.w);
        hw[2] = pack_f16_pair(v1.x, v1.y);
        hw[3] = pack_f16_pair(v1.z, v1.w);
        size_t off = (((size_t)(row >> 3) * KB + kb) << 6) + (size_t)(row & 7) * 8;
        *(uint4*)(g_hid_hi + off) = make_uint4(hw[0], hw[1], hw[2], hw[3]);
        return;
    }
    blk -= SP_B;
    if (blk < WQ_B) { do_wtrans(Wq, g_wq_hi, g_wq_lo, E_,  HD_, blk, tid, tile); return; }
    blk -= WQ_B;
    if (blk < WK_B) { do_wtrans(Wk, g_wk_hi, g_wk_lo, E_,  KVHD_, blk, tid, tile); return; }
    blk -= WK_B;
    if (blk < WV_B) { do_wtrans(Wv, g_wv_hi, g_wv_lo, E_,  KVHD_, blk, tid, tile); return; }
    blk -= WV_B;
    do_wtrans(Wo, g_wo_hi, g_wo_lo, HD_, E_, blk, tid, tile);
}

// ---------------- GEMM mainloop (2-stage, 96KB, 2 CTAs/SM, 1 sync/chunk) ----------------
#define GEMM_MAINLOOP(pAhi_, pBhi_, pBlo_, Kdim_)                                           \
    const int KB = (Kdim_) >> 3;                                                            \
    const int NC = (Kdim_) >> 6;                                                            \
    float acc[4][4][4];                                                                     \
    _Pragma("unroll") for (int t = 0; t < 4; t++)                                           \
        _Pragma("unroll") for (int u = 0; u < 4; u++)                                       \
            _Pragma("unroll") for (int j = 0; j < 4; j++) acc[t][u][j] = 0.f;               \
    auto prefetch = [&](int chunk, int st) {                                                \
        uint32_t sbuf = sbase + (uint32_t)st * 49152u;                                      \
        int kb0 = chunk << 3;                                                               \
        _Pragma("unroll") for (int j = 0; j < 4; j++) {                                     \
            int u = tid + j * 256;                                                          \
            int rb = u >> 6, kb = (u >> 3) & 7, w = u & 7;                                  \
            size_t gA = ((size_t)(mb0 + rb) * KB + (kb0 + kb)) * 128u + (size_t)w * 16u;    \
            size_t gB = ((size_t)(nb0 + rb) * KB + (kb0 + kb)) * 128u + (size_t)w * 16u;    \
            uint32_t so = (uint32_t)(((rb * 8 + kb) * 8 + w) * 16);                         \
            cp16(sbuf + so,          (const char*)(pAhi_) + gA);                            \
            cp16(sbuf + 16384u + so, (const char*)(pBhi_) + gB);                            \
            cp16(sbuf + 32768u + so, (const char*)(pBlo_) + gB);                            \
        }                                                                                   \
    };                                                                                      \
    const int wmb   = (warp >> 2) * 8;                                                      \
    const int wnb   = (warp & 3) * 4;                                                       \
    const int selAm = (lane >> 3) & 1;                                                      \
    const int selAk = (lane >> 3) >> 1;                                                     \
    const int selBn = (lane >> 4) & 1;                                                      \
    const int selBk = (lane >> 3) & 1;                                                      \
    const int rrow  = lane & 7;                                                             \
    prefetch(0, 0);                                                                         \
    asm volatile("cp.async.commit_group;" ::: "memory");                                    \
    for (int i = 0; i < NC; i++) {                                                          \
        asm volatile("cp.async.wait_group 0;" ::: "memory");                                \
        __syncthreads();                                                                    \
        if (i + 1 < NC) {                                                                   \
            prefetch(i + 1, (i + 1) & 1);                                                   \
            asm volatile("cp.async.commit_group;" ::: "memory");                            \
        }                                                                                   \
        uint32_t sbuf = sbase + (uint32_t)(i & 1) * 49152u;                                 \
        _Pragma("unroll") for (int ks = 0; ks < 4; ks++) {                                  \
            uint32_t ahi[4][4], bhi[2][4], blo[2][4];                                       \
            _Pragma("unroll") for (int t = 0; t < 4; t++) {                                 \
                int mbb = wmb + 2*t + selAm;                                                \
                int kbb = 2*ks + selAk;                                                     \
                uint32_t off = (uint32_t)((mbb * 8 + kbb) * 128 + rrow * 16);               \
                ldsm_x4(ahi[t], sbuf + off);                                                \
            }                                                                               \
            _Pragma("unroll") for (int u2 = 0; u2 < 2; u2++) {                              \
                int nbb = wnb + 2*u2 + selBn;                                               \
                int kbb = 2*ks + selBk;                                                     \
                uint32_t off = (uint32_t)((nbb * 8 + kbb) * 128 + rrow * 16);               \
                ldsm_x4(bhi[u2], sbuf + 16384u + off);                                      \
                ldsm_x4(blo[u2], sbuf + 32768u + off);                                      \
            }                                                                               \
            _Pragma("unroll") for (int t = 0; t < 4; t++)                                   \
                _Pragma("unroll") for (int u = 0; u < 4; u++) {                             \
                    const uint32_t* bh = &bhi[u >> 1][(u & 1) * 2];                         \
                    const uint32_t* bl = &blo[u >> 1][(u & 1) * 2];                         \
                    mma_f16(acc[t][u], ahi[t], bh);                                         \
                    mma_f16(acc[t][u], ahi[t], bl);                                         \
                }                                                                           \
        }                                                                                   \
    {

// ---------------- merged QKV projection kernel ----------------
__global__ __launch_bounds__(256, 2)
void qkv_gemm_kernel(const float* __restrict__ bq, const float* __restrict__ bk,
                     const float* __restrict__ bv, const int* __restrict__ pos) {
    extern __shared__ char smc[];
    const uint32_t sbase = smem_u32(smc);
    const int tid  = threadIdx.x;
    const int warp = tid >> 5, lane = tid & 31;
    const int mb0  = blockIdx.y * 16;
    const int bx   = blockIdx.x;

    const __half *pBh, *pBl;
    const float* bias;
    int nb0, mode, hh;
    if (bx < 32)      { pBh = g_wq_hi; pBl = g_wq_lo; bias = bq; nb0 = bx * 16;        mode = 1; hh = bx; }
    else if (bx < 40) { pBh = g_wk_hi; pBl = g_wk_lo; bias = bk; nb0 = (bx - 32) * 16; mode = 2; hh = bx - 32; }
    else              { pBh = g_wv_hi; pBl = g_wv_lo; bias = bv; nb0 = (bx - 40) * 16; mode = 3; hh = bx - 40; }

    GEMM_MAINLOOP(g_hid_hi, pBh, pBl, E_)
    }}   // close inner block + mainloop for

    const int gg = lane >> 2, qq = lane & 3;

    float* st = (float*)smc;
    __syncthreads();
    {
        const int lrow = (warp >> 2) * 64;
        const int lcol = (warp & 3) * 32;
        #pragma unroll
        for (int t = 0; t < 4; t++) {
            #pragma unroll
            for (int u = 0; u < 4; u++) {
                int r = lrow + t * 16 + gg;
                int c = lcol + u * 8 + qq * 2;
                float2 b2 = *(const float2*)(bias + nb0 * 8 + c);
                st[r * 132 + c]           = acc[t][u][0] + b2.x;
                st[r * 132 + c + 1]       = acc[t][u][1] + b2.y;
                st[(r + 8) * 132 + c]     = acc[t][u][2] + b2.x;
                st[(r + 8) * 132 + c + 1] = acc[t][u][3] + b2.y;
            }
        }
    }
    __syncthreads();

    if (mode == 1 || mode == 2) {
        __half* oHi = (mode == 1) ? g_qb_hi : g_kb_hi;
        __half* oLo = (mode == 1) ? g_qb_lo : g_kb_lo;
        #pragma unroll
        for (int j = 0; j < 4; j++) {
            int idx = tid + j * 256;
            int kbl = idx & 7;
            int r   = idx >> 3;
            int token = blockIdx.y * 128 + r;
            int b = token >> 11;
            int s = token & (S_ - 1);
            int p = pos[b * S_ + s];
            int i0 = kbl * 8;
            float y1[8], y2[8];
            #pragma unroll
            for (int jj = 0; jj < 8; jj++) {
                float x1 = st[r * 132 + i0 + jj];
                float x2 = st[r * 132 + 64 + i0 + jj];
                float c  = g_cos[p * 64 + i0 + jj];
                float sn = g_sin[p * 64 + i0 + jj];
                y1[jj] = x1 * c - x2 * sn;
                y2[jj] = x2 * c + x1 * sn;
            }
            uint32_t h1[4], l1[4], h2[4], l2[4];
            #pragma unroll
            for (int jj = 0; jj < 4; jj++) {
                h1[jj] = pack_f16_split(y1[2*jj], y1[2*jj+1], l1[jj]);
                h2[jj] = pack_f16_split(y2[2*jj], y2[2*jj+1], l2[jj]);
            }
            size_t dbase;
            if (mode == 1) {
                int qt = s >> 7, sbw = (s >> 3) & 15;
                dbase = ((((size_t)(b * H_ + hh) * (S_/128) + qt) * 16 + sbw) * 16);
            } else {
                int kt = s >> 6, sbw = (s >> 3) & 7;
                dbase = ((((size_t)(b * KVH_ + hh) * (S_/64) + kt) * 8 + sbw) * 16);
            }
            int rr = s & 7;
            size_t o1 = (dbase + kbl)     * 64 + (size_t)rr * 8;
            size_t o2 = (dbase + kbl + 8) * 64 + (size_t)rr * 8;
            *(uint4*)(oHi + o1) = make_uint4(h1[0], h1[1], h1[2], h1[3]);
            *(uint4*)(oLo + o1) = make_uint4(l1[0], l1[1], l1[2], l1[3]);
            *(uint4*)(oHi + o2) = make_uint4(h2[0], h2[1], h2[2], h2[3]);
            *(uint4*)(oLo + o2) = make_uint4(l2[0], l2[1], l2[2], l2[3]);
        }
    } else {
        const int token0 = blockIdx.y * 128;
        const int b = token0 >> 11;
        const int sbase0 = token0 & (S_ - 1);
        #pragma unroll
        for (int j = 0; j < 8; j++) {
            int idx = tid + j * 256;
            int dr  = idx & 7;
            int sbw = (idx >> 3) & 7;
            int db  = (idx >> 6) & 15;
            int ktl = idx >> 10;
            int d = db * 8 + dr;
            int sl = ktl * 64 + sbw * 8;
            uint32_t hw[4], lw[4];
            #pragma unroll
            for (int jj = 0; jj < 4; jj++) {
                float x0 = st[(sl + 2*jj)     * 132 + d];
                float x1 = st[(sl + 2*jj + 1) * 132 + d];
                hw[jj] = pack_f16_split(x0, x1, lw[jj]);
            }
            int s = sbase0 + sl;
            int kt = s >> 6;
            size_t off = (((((size_t)(b * KVH_ + hh) * (S_/64) + kt) * 16 + db) * 8 + sbw) * 64)
                       + (size_t)dr * 8;
            *(uint4*)(g_vb_hi + off) = make_uint4(hw[0], hw[1], hw[2], hw[3]);
            *(uint4*)(g_vb_lo + off) = make_uint4(lw[0], lw[1], lw[2], lw[3]);
        }
    }
}

// ---------------- O-projection kernel ----------------
__global__ __launch_bounds__(256, 2)
void o_gemm_kernel(float* __restrict__ C) {
    extern __shared__ char smc[];
    const uint32_t sbase = smem_u32(smc);
    const int tid  = threadIdx.x;
    const int warp = tid >> 5, lane = tid & 31;
    const int mb0  = blockIdx.y * 16;
    const int nb0  = blockIdx.x * 16;

    GEMM_MAINLOOP(g_attn_hi, g_wo_hi, g_wo_lo, HD_)
    }}

    const int mrow = mb0 * 8 + (warp >> 2) * 64;
    const int ncol = nb0 * 8 + (warp & 3) * 32;
    const int gg = lane >> 2, qq = lane & 3;
    #pragma unroll
    for (int t = 0; t < 4; t++) {
        #pragma unroll
        for (int u = 0; u < 4; u++) {
            int row = mrow + t * 16 + gg;
            int col = ncol + u * 8 + qq * 2;
            *(float2*)(C + (size_t)row * E_ + col)       = make_float2(acc[t][u][0], acc[t][u][1]);
            *(float2*)(C + (size_t)(row + 8) * E_ + col) = make_float2(acc[t][u][2], acc[t][u][3]);
        }
    }
}

// ---------------- flash attention: FA2 repack, Q fragments register-resident ----------------
#define FQHI   0u
#define FQLO   32768u
#define FKV0   65536u
#define FTOT   196608u

__global__ __launch_bounds__(256, 1)
void flash_mma_kernel() {
    extern __shared__ char fs[];
    const uint32_t sb = smem_u32(fs);

    const int tid  = threadIdx.x;
    const int warp = tid >> 5, lane = tid & 31;
    const int qt = (S_/128 - 1) - blockIdx.x;
    const int h = blockIdx.y, b = blockIdx.z;
    const int q0 = qt * 128;
    const int kvh = h >> 2;
    const float scale2 = 0.08838834764831845f * 1.4426950408889634f;

    const int selAm = (lane >> 3) & 1;
    const int selAk = (lane >> 3) >> 1;
    const int selBn = (lane >> 4) & 1;
    const int selBk = (lane >> 3) & 1;
    const int rrow  = lane & 7;
    const int gr = lane >> 2, qq = lane & 3;
    const int wm = warp * 16;

    const size_t kvbase = (size_t)(b*KVH_ + kvh) * (S_/64);
    auto prefetch_kv = [&](int kt, int st) {
        size_t tb = (kvbase + kt) * 16384u;
        uint32_t sbuf = sb + FKV0 + (uint32_t)st * 65536u;
        #pragma unroll
        for (int j = 0; j < 4; j++) {
            uint32_t u = (uint32_t)(tid + j * 256) * 16u;
            cp16(sbuf + u,           (const char*)g_kb_hi + tb + u);
            cp16(sbuf + 16384u + u,  (const char*)g_kb_lo + tb + u);
            cp16(sbuf + 32768u + u,  (const char*)g_vb_hi + tb + u);
            cp16(sbuf + 49152u + u,  (const char*)g_vb_lo + tb + u);
        }
    };

    {
        const char* qh = (const char*)(g_qb_hi + (((size_t)(b*H_ + h) * (S_/128) + qt) << 14));
        const char* ql = (const char*)(g_qb_lo + (((size_t)(b*H_ + h) * (S_/128) + qt) << 14));
        #pragma unroll
        for (int j = 0; j < 8; j++) {
            uint32_t u = (uint32_t)(tid + j * 256) * 16u;
            cp16(sb + FQHI + u, qh + u);
            cp16(sb + FQLO + u, ql + u);
        }
        prefetch_kv(0, 0);
        asm volatile("cp.async.commit_group;" ::: "memory");
    }

    // wait for Q + KV0; then hoist Q fragments into registers (reused every kt)
    asm volatile("cp.async.wait_group 0;" ::: "memory");
    __syncthreads();

    uint32_t qfh[8][4], qfl[8][4];
    #pragma unroll
    for (int ks = 0; ks < 8; ks++) {
        int mbb = 2*warp + selAm;
        int kbb = 2*ks + selAk;
        uint32_t off = (uint32_t)((mbb * 16 + kbb) * 128 + rrow * 16);
        ldsm_x4(qfh[ks], sb + FQHI + off);
        ldsm_x4(qfl[ks], sb + FQLO + off);
    }

    float m1 = -1e30f, m2 = -1e30f, l1 = 0.f, l2 = 0.f;
    float acc[16][4];
    #pragma unroll
    for (int u = 0; u < 16; u++)
        #pragma unroll
        for (int j = 0; j < 4; j++) acc[u][j] = 0.f;

    const int r1 = wm + gr;
    const int r2 = r1 + 8;

    const int NK = 2 * qt + 2;
    for (int kt = 0; kt < NK; kt++) {
        const int k0 = kt * 64;
        if (kt > 0) {
            asm volatile("cp.async.wait_group 0;" ::: "memory");
            __syncthreads();   // all warps done reading stage (kt+1)&1 in iter kt-1
        }
        const uint32_t kvs = sb + FKV0 + (uint32_t)(kt & 1) * 65536u;

        if (kt + 1 < NK) {
            prefetch_kv(kt + 1, (kt + 1) & 1);
            asm volatile("cp.async.commit_group;" ::: "memory");
        }

        // ---- S = Q @ K^T (3-term), Q from registers ----
        float sacc[8][4];
        #pragma unroll
        for (int u = 0; u < 8; u++)
            #pragma unroll
            for (int j = 0; j < 4; j++) sacc[u][j] = 0.f;

        #pragma unroll
        for (int ks = 0; ks < 8; ks++) {
            uint32_t khi[4][4], klo[4][4];
            #pragma unroll
            for (int j = 0; j < 4; j++) {
                int nbb = 2*j + selBn;
                int kbb = 2*ks + selBk;
                uint32_t off = (uint32_t)((nbb * 16 + kbb) * 128 + rrow * 16);
                ldsm_x4(khi[j], kvs + off);
                ldsm_x4(klo[j], kvs + 16384u + off);
            }
            #pragma unroll
            for (int u = 0; u < 8; u++) {
                const uint32_t* kh = &khi[u >> 1][(u & 1) * 2];
                const uint32_t* kl = &klo[u >> 1][(u & 1) * 2];
                mma_f16(sacc[u], qfh[ks], kh);
                mma_f16(sacc[u], qfl[ks], kh);
                mma_f16(sacc[u], qfh[ks], kl);
            }
        }

        // ---- in-register softmax (base-2 domain) ----
        const bool needmask = (kt >= 2 * qt);
        float tm1 = -1e30f, tm2 = -1e30f;
        #pragma unroll
        for (int u = 0; u < 8; u++) {
            int c0 = u * 8 + qq * 2;
            float s0 = sacc[u][0] * scale2;
            float s1 = sacc[u][1] * scale2;
            float s2 = sacc[u][2] * scale2;
            float s3 = sacc[u][3] * scale2;
            if (needmask) {
                if (k0 + c0     > q0 + r1) s0 = -1e30f;
                if (k0 + c0 + 1 > q0 + r1) s1 = -1e30f;
                if (k0 + c0     > q0 + r2) s2 = -1e30f;
                if (k0 + c0 + 1 > q0 + r2) s3 = -1e30f;
            }
            sacc[u][0] = s0; sacc[u][1] = s1;
            sacc[u][2] = s2; sacc[u][3] = s3;
            tm1 = fmaxf(tm1, fmaxf(s0, s1));
            tm2 = fmaxf(tm2, fmaxf(s2, s3));
        }
        tm1 = fmaxf(tm1, __shfl_xor_sync(0xffffffffu, tm1, 1));
        tm1 = fmaxf(tm1, __shfl_xor_sync(0xffffffffu, tm1, 2));
        tm2 = fmaxf(tm2, __shfl_xor_sync(0xffffffffu, tm2, 1));
        tm2 = fmaxf(tm2, __shfl_xor_sync(0xffffffffu, tm2, 2));
        float mn1 = fmaxf(m1, tm1), mn2 = fmaxf(m2, tm2);
        float a1 = exp2f(m1 - mn1), a2 = exp2f(m2 - mn2);
        m1 = mn1; m2 = mn2;

        uint32_t pf[4][4];
        float ts1 = 0.f, ts2 = 0.f;
        #pragma unroll
        for (int kk = 0; kk < 4; kk++) {
            #pragma unroll
            for (int half = 0; half < 2; half++) {
                int u = 2*kk + half;
                float e0 = exp2f(sacc[u][0] - m1);
                float e1 = exp2f(sacc[u][1] - m1);
                float e2 = exp2f(sacc[u][2] - m2);
                float e3 = exp2f(sacc[u][3] - m2);
                ts1 += e0 + e1;
                ts2 += e2 + e3;
                pf[kk][half*2]     = pack_f16_pair(e0, e1);
                pf[kk][half*2 + 1] = pack_f16_pair(e2, e3);
            }
        }
        ts1 += __shfl_xor_sync(0xffffffffu, ts1, 1);
        ts1 += __shfl_xor_sync(0xffffffffu, ts1, 2);
        ts2 += __shfl_xor_sync(0xffffffffu, ts2, 1);
        ts2 += __shfl_xor_sync(0xffffffffu, ts2, 2);
        l1 = l1 * a1 + ts1;
        l2 = l2 * a2 + ts2;

        #pragma unroll
        for (int u = 0; u < 16; u++) {
            acc[u][0] *= a1; acc[u][1] *= a1;
            acc[u][2] *= a2; acc[u][3] *= a2;
        }

        // ---- O += P @ V (2-term), P from registers ----
        #pragma unroll
        for (int ks = 0; ks < 4; ks++) {
            #pragma unroll
            for (int nh = 0; nh < 2; nh++) {
                uint32_t vhi[4][4], vlo[4][4];
                #pragma unroll
                for (int j = 0; j < 4; j++) {
                    int nbb = nh*8 + 2*j + selBn;
                    int kbb = 2*ks + selBk;
                    uint32_t off = (uint32_t)((nbb * 8 + kbb) * 128 + rrow * 16);
                    ldsm_x4(vhi[j], kvs + 32768u + off);
                    ldsm_x4(vlo[j], kvs + 49152u + off);
                }
                #pragma unroll
                for (int uu = 0; uu < 8; uu++) {
                    int u = nh*8 + uu;
                    const uint32_t* vh = &vhi[uu >> 1][(uu & 1) * 2];
                    const uint32_t* vl = &vlo[uu >> 1][(uu & 1) * 2];
                    mma_f16(acc[u], pf[ks], vh);
                    mma_f16(acc[u], pf[ks], vl);
                }
            }
        }
    }

    // ---- epilogue: normalize + write blocked fp16 hi ----
    {
        const int KB = HD_ >> 3;
        float inv1 = 1.f / l1;
        float inv2 = 1.f / l2;
        int grow1 = b*S_ + q0 + r1;
        int grow2 = grow1 + 8;
        #pragma unroll
        for (int u = 0; u < 16; u++) {
            int col = h * D_ + u*8 + qq * 2;
            int kb = col >> 3, cw = col & 7;
            size_t o1 = (((size_t)(grow1 >> 3) * KB + kb) << 6) + (size_t)(grow1 & 7) * 8 + cw;
            size_t o2 = (((size_t)(grow2 >> 3) * KB + kb) << 6) + (size_t)(grow2 & 7) * 8 + cw;
            *(uint32_t*)(g_attn_hi + o1) = pack_f16_pair(acc[u][0]*inv1, acc[u][1]*inv1);
            *(uint32_t*)(g_attn_hi + o2) = pack_f16_pair(acc[u][2]*inv2, acc[u][3]*inv2);
        }
    }
}

// ---------------- launch ----------------
extern "C" void kernel_launch(void* const* d_in, const int* in_sizes, int n_in,
                              void* d_out, int out_size) {
    const float* hidden = (const float*)d_in[0];
    const int*   pos    = (const int*)  d_in[2];
    const float* Wq     = (const float*)d_in[3];
    const float* bq     = (const float*)d_in[4];
    const float* Wk     = (const float*)d_in[5];
    const float* bk     = (const float*)d_in[6];
    const float* Wv     = (const float*)d_in[7];
    const float* bv     = (const float*)d_in[8];
    const float* Wo     = (const float*)d_in[9];
    float* out = (float*)d_out;

    const size_t gsmem = 98304;
    cudaFuncSetAttribute(qkv_gemm_kernel, cudaFuncAttributeMaxDynamicSharedMemorySize, (int)gsmem);
    cudaFuncSetAttribute(o_gemm_kernel,   cudaFuncAttributeMaxDynamicSharedMemorySize, (int)gsmem);
    cudaFuncSetAttribute(flash_mma_kernel, cudaFuncAttributeMaxDynamicSharedMemorySize, (int)FTOT);

    prep_all_kernel<<<PREP_TOTAL, 256>>>(hidden, Wq, Wk, Wv, Wo);
    qkv_gemm_kernel<<<dim3(48, M_/128), 256, gsmem>>>(bq, bk, bv, pos);
    flash_mma_kernel<<<dim3(S_/128, H_, B_), 256, FTOT>>>();
    o_gemm_kernel<<<dim3(E_/128, M_/128), 256, gsmem>>>(out);
}

// round 17
// speedup vs baseline: 1.6656x; 1.0489x over previous
#include <cuda_runtime.h>
#include <cuda_fp16.h>
#include <math.h>
#include <stdint.h>

#define B_    2
#define S_    2048
#define E_    4096
#define H_    32
#define KVH_  8
#define D_    128
#define HD_   (H_*D_)      // 4096
#define KVHD_ (KVH_*D_)    // 1024
#define M_    (B_*S_)      // 4096

// ---------------- scratch (no allocations allowed) ----------------
__device__ float g_cos [S_*(D_/2)];
__device__ float g_sin [S_*(D_/2)];

__device__ __align__(16) __half g_hid_hi [(size_t)M_*E_];
__device__ __align__(16) __half g_wq_hi  [(size_t)HD_*E_];
__device__ __align__(16) __half g_wq_lo  [(size_t)HD_*E_];
__device__ __align__(16) __half g_wk_hi  [(size_t)KVHD_*E_];
__device__ __align__(16) __half g_wk_lo  [(size_t)KVHD_*E_];
__device__ __align__(16) __half g_wv_hi  [(size_t)KVHD_*E_];
__device__ __align__(16) __half g_wv_lo  [(size_t)KVHD_*E_];
__device__ __align__(16) __half g_wo_hi  [(size_t)E_*HD_];
__device__ __align__(16) __half g_wo_lo  [(size_t)E_*HD_];
__device__ __align__(16) __half g_attn_hi[(size_t)M_*HD_];

__device__ __align__(16) __half g_qb_hi[(size_t)B_*H_*S_*D_];
__device__ __align__(16) __half g_qb_lo[(size_t)B_*H_*S_*D_];
__device__ __align__(16) __half g_kb_hi[(size_t)B_*KVH_*S_*D_];
__device__ __align__(16) __half g_kb_lo[(size_t)B_*KVH_*S_*D_];
__device__ __align__(16) __half g_vb_hi[(size_t)B_*KVH_*S_*D_];   // V hi only (PV 1-term)

// ---------------- helpers ----------------
__device__ __forceinline__ uint32_t smem_u32(const void* p) {
    uint32_t a;
    asm("{ .reg .u64 t; cvta.to.shared.u64 t, %1; cvt.u32.u64 %0, t; }" : "=r"(a) : "l"(p));
    return a;
}
__device__ __forceinline__ void ldsm_x4(uint32_t* r, uint32_t a) {
    asm volatile("ldmatrix.sync.aligned.m8n8.x4.shared.b16 {%0,%1,%2,%3}, [%4];"
                 : "=r"(r[0]), "=r"(r[1]), "=r"(r[2]), "=r"(r[3]) : "r"(a));
}
__device__ __forceinline__ void mma_f16(float* c, const uint32_t* a, const uint32_t* b) {
    asm volatile("mma.sync.aligned.m16n8k16.row.col.f32.f16.f16.f32 "
                 "{%0,%1,%2,%3}, {%4,%5,%6,%7}, {%8,%9}, {%0,%1,%2,%3};"
                 : "+f"(c[0]), "+f"(c[1]), "+f"(c[2]), "+f"(c[3])
                 : "r"(a[0]), "r"(a[1]), "r"(a[2]), "r"(a[3]), "r"(b[0]), "r"(b[1]));
}
__device__ __forceinline__ void cp16(uint32_t saddr, const void* g) {
    asm volatile("cp.async.cg.shared.global [%0], [%1], 16;" :: "r"(saddr), "l"(g) : "memory");
}
__device__ __forceinline__ uint32_t pack_f16_split(float x0, float x1, uint32_t& lo_out) {
    __half h0 = __float2half_rn(x0);
    __half h1 = __float2half_rn(x1);
    __half l0 = __float2half_rn(x0 - __half2float(h0));
    __half l1 = __float2half_rn(x1 - __half2float(h1));
    __half2 hp = __halves2half2(h0, h1);
    __half2 lp = __halves2half2(l0, l1);
    lo_out = *reinterpret_cast<uint32_t*>(&lp);
    return *reinterpret_cast<uint32_t*>(&hp);
}
__device__ __forceinline__ uint32_t pack_f16_pair(float x0, float x1) {
    __half2 hp = __halves2half2(__float2half_rn(x0), __float2half_rn(x1));
    return *reinterpret_cast<uint32_t*>(&hp);
}

// ---------------- unified prep kernel ----------------
#define RT_B   ((S_*(D_/2))/256)
#define SP_B   ((M_*(E_>>3))/256)
#define WQ_B   ((HD_/32)*(E_/32))
#define WK_B   ((KVHD_/32)*(E_/32))
#define WV_B   WK_B
#define WO_B   ((E_/32)*(HD_/32))
#define PREP_TOTAL (RT_B + SP_B + WQ_B + WK_B + WV_B + WO_B)

__device__ __forceinline__ void do_wtrans(const float* __restrict__ W,
                                          __half* __restrict__ Thi, __half* __restrict__ Tlo,
                                          int Kdim, int Ndim, int seg, int tid,
                                          float (*tile)[33]) {
    int nTiles = Ndim / 32;
    int bx = seg % nTiles, by = seg / nTiles;
    int n0 = bx * 32, k0 = by * 32;
    int tx = tid & 31, ty = tid >> 5;
    #pragma unroll
    for (int dy = 0; dy < 32; dy += 8)
        tile[ty + dy][tx] = W[(size_t)(k0 + ty + dy) * Ndim + n0 + tx];
    __syncthreads();
    int KB = Kdim >> 3;
    #pragma unroll
    for (int dy = 0; dy < 32; dy += 8) {
        int n = n0 + ty + dy, k = k0 + tx;
        float x = tile[tx][ty + dy];
        __half h = __float2half_rn(x);
        __half l = __float2half_rn(x - __half2float(h));
        size_t off = (((size_t)(n >> 3) * KB + (k >> 3)) << 6) + (size_t)(n & 7) * 8 + (k & 7);
        Thi[off] = h;
        Tlo[off] = l;
    }
}

__global__ __launch_bounds__(256)
void prep_all_kernel(const float* __restrict__ hidden,
                     const float* __restrict__ Wq, const float* __restrict__ Wk,
                     const float* __restrict__ Wv, const float* __restrict__ Wo) {
    __shared__ float tile[32][33];
    const int tid = threadIdx.x;
    int blk = blockIdx.x;

    if (blk < RT_B) {
        int idx = blk * 256 + tid;
        int t = idx / (D_/2);
        int i = idx % (D_/2);
        double inv = exp(-((double)(2*i) / (double)D_) * log(10000.0));
        double ang = (double)t * inv;
        g_cos[idx] = (float)cos(ang);
        g_sin[idx] = (float)sin(ang);
        return;
    }
    blk -= RT_B;
    if (blk < SP_B) {
        int idx = blk * 256 + tid;
        const int KB = E_ >> 3;
        int row = idx / KB, kb = idx % KB;
        const float* src = hidden + (size_t)row * E_ + kb * 8;
        float4 v0 = *(const float4*)src;
        float4 v1 = *(const float4*)(src + 4);
        uint32_t hw[4];
        hw[0] = pack_f16_pair(v0.x, v0.y);
        hw[1] = pack_f16_pair(v0.z, v0.w);
        hw[2] = pack_f16_pair(v1.x, v1.y);
        hw[3] = pack_f16_pair(v1.z, v1.w);
        size_t off = (((size_t)(row >> 3) * KB + kb) << 6) + (size_t)(row & 7) * 8;
        *(uint4*)(g_hid_hi + off) = make_uint4(hw[0], hw[1], hw[2], hw[3]);
        return;
    }
    blk -= SP_B;
    if (blk < WQ_B) { do_wtrans(Wq, g_wq_hi, g_wq_lo, E_,  HD_, blk, tid, tile); return; }
    blk -= WQ_B;
    if (blk < WK_B) { do_wtrans(Wk, g_wk_hi, g_wk_lo, E_,  KVHD_, blk, tid, tile); return; }
    blk -= WK_B;
    if (blk < WV_B) { do_wtrans(Wv, g_wv_hi, g_wv_lo, E_,  KVHD_, blk, tid, tile); return; }
    blk -= WV_B;
    do_wtrans(Wo, g_wo_hi, g_wo_lo, HD_, E_, blk, tid, tile);
}

// ---------------- GEMM mainloop (2-stage, 96KB, 2 CTAs/SM, 1 sync/chunk) ----------------
#define GEMM_MAINLOOP(pAhi_, pBhi_, pBlo_, Kdim_)                                           \
    const int KB = (Kdim_) >> 3;                                                            \
    const int NC = (Kdim_) >> 6;                                                            \
    float acc[4][4][4];                                                                     \
    _Pragma("unroll") for (int t = 0; t < 4; t++)                                           \
        _Pragma("unroll") for (int u = 0; u < 4; u++)                                       \
            _Pragma("unroll") for (int j = 0; j < 4; j++) acc[t][u][j] = 0.f;               \
    auto prefetch = [&](int chunk, int st) {                                                \
        uint32_t sbuf = sbase + (uint32_t)st * 49152u;                                      \
        int kb0 = chunk << 3;                                                               \
        _Pragma("unroll") for (int j = 0; j < 4; j++) {                                     \
            int u = tid + j * 256;                                                          \
            int rb = u >> 6, kb = (u >> 3) & 7, w = u & 7;                                  \
            size_t gA = ((size_t)(mb0 + rb) * KB + (kb0 + kb)) * 128u + (size_t)w * 16u;    \
            size_t gB = ((size_t)(nb0 + rb) * KB + (kb0 + kb)) * 128u + (size_t)w * 16u;    \
            uint32_t so = (uint32_t)(((rb * 8 + kb) * 8 + w) * 16);                         \
            cp16(sbuf + so,          (const char*)(pAhi_) + gA);                            \
            cp16(sbuf + 16384u + so, (const char*)(pBhi_) + gB);                            \
            cp16(sbuf + 32768u + so, (const char*)(pBlo_) + gB);                            \
        }                                                                                   \
    };                                                                                      \
    const int wmb   = (warp >> 2) * 8;                                                      \
    const int wnb   = (warp & 3) * 4;                                                       \
    const int selAm = (lane >> 3) & 1;                                                      \
    const int selAk = (lane >> 3) >> 1;                                                     \
    const int selBn = (lane >> 4) & 1;                                                      \
    const int selBk = (lane >> 3) & 1;                                                      \
    const int rrow  = lane & 7;                                                             \
    prefetch(0, 0);                                                                         \
    asm volatile("cp.async.commit_group;" ::: "memory");                                    \
    for (int i = 0; i < NC; i++) {                                                          \
        asm volatile("cp.async.wait_group 0;" ::: "memory");                                \
        __syncthreads();                                                                    \
        if (i + 1 < NC) {                                                                   \
            prefetch(i + 1, (i + 1) & 1);                                                   \
            asm volatile("cp.async.commit_group;" ::: "memory");                            \
        }                                                                                   \
        uint32_t sbuf = sbase + (uint32_t)(i & 1) * 49152u;                                 \
        _Pragma("unroll") for (int ks = 0; ks < 4; ks++) {                                  \
            uint32_t ahi[4][4], bhi[2][4], blo[2][4];                                       \
            _Pragma("unroll") for (int t = 0; t < 4; t++) {                                 \
                int mbb = wmb + 2*t + selAm;                                                \
                int kbb = 2*ks + selAk;                                                     \
                uint32_t off = (uint32_t)((mbb * 8 + kbb) * 128 + rrow * 16);               \
                ldsm_x4(ahi[t], sbuf + off);                                                \
            }                                                                               \
            _Pragma("unroll") for (int u2 = 0; u2 < 2; u2++) {                              \
                int nbb = wnb + 2*u2 + selBn;                                               \
                int kbb = 2*ks + selBk;                                                     \
                uint32_t off = (uint32_t)((nbb * 8 + kbb) * 128 + rrow * 16);               \
                ldsm_x4(bhi[u2], sbuf + 16384u + off);                                      \
                ldsm_x4(blo[u2], sbuf + 32768u + off);                                      \
            }                                                                               \
            _Pragma("unroll") for (int t = 0; t < 4; t++)                                   \
                _Pragma("unroll") for (int u = 0; u < 4; u++) {                             \
                    const uint32_t* bh = &bhi[u >> 1][(u & 1) * 2];                         \
                    const uint32_t* bl = &blo[u >> 1][(u & 1) * 2];                         \
                    mma_f16(acc[t][u], ahi[t], bh);                                         \
                    mma_f16(acc[t][u], ahi[t], bl);                                         \
                }                                                                           \
        }                                                                                   \
    {

// ---------------- merged QKV projection kernel ----------------
__global__ __launch_bounds__(256, 2)
void qkv_gemm_kernel(const float* __restrict__ bq, const float* __restrict__ bk,
                     const float* __restrict__ bv, const int* __restrict__ pos) {
    extern __shared__ char smc[];
    const uint32_t sbase = smem_u32(smc);
    const int tid  = threadIdx.x;
    const int warp = tid >> 5, lane = tid & 31;
    const int mb0  = blockIdx.y * 16;
    const int bx   = blockIdx.x;

    const __half *pBh, *pBl;
    const float* bias;
    int nb0, mode, hh;
    if (bx < 32)      { pBh = g_wq_hi; pBl = g_wq_lo; bias = bq; nb0 = bx * 16;        mode = 1; hh = bx; }
    else if (bx < 40) { pBh = g_wk_hi; pBl = g_wk_lo; bias = bk; nb0 = (bx - 32) * 16; mode = 2; hh = bx - 32; }
    else              { pBh = g_wv_hi; pBl = g_wv_lo; bias = bv; nb0 = (bx - 40) * 16; mode = 3; hh = bx - 40; }

    GEMM_MAINLOOP(g_hid_hi, pBh, pBl, E_)
    }}   // close inner block + mainloop for

    const int gg = lane >> 2, qq = lane & 3;

    float* st = (float*)smc;
    __syncthreads();
    {
        const int lrow = (warp >> 2) * 64;
        const int lcol = (warp & 3) * 32;
        #pragma unroll
        for (int t = 0; t < 4; t++) {
            #pragma unroll
            for (int u = 0; u < 4; u++) {
                int r = lrow + t * 16 + gg;
                int c = lcol + u * 8 + qq * 2;
                float2 b2 = *(const float2*)(bias + nb0 * 8 + c);
                st[r * 132 + c]           = acc[t][u][0] + b2.x;
                st[r * 132 + c + 1]       = acc[t][u][1] + b2.y;
                st[(r + 8) * 132 + c]     = acc[t][u][2] + b2.x;
                st[(r + 8) * 132 + c + 1] = acc[t][u][3] + b2.y;
            }
        }
    }
    __syncthreads();

    if (mode == 1 || mode == 2) {
        __half* oHi = (mode == 1) ? g_qb_hi : g_kb_hi;
        __half* oLo = (mode == 1) ? g_qb_lo : g_kb_lo;
        #pragma unroll
        for (int j = 0; j < 4; j++) {
            int idx = tid + j * 256;
            int kbl = idx & 7;
            int r   = idx >> 3;
            int token = blockIdx.y * 128 + r;
            int b = token >> 11;
            int s = token & (S_ - 1);
            int p = pos[b * S_ + s];
            int i0 = kbl * 8;
            float y1[8], y2[8];
            #pragma unroll
            for (int jj = 0; jj < 8; jj++) {
                float x1 = st[r * 132 + i0 + jj];
                float x2 = st[r * 132 + 64 + i0 + jj];
                float c  = g_cos[p * 64 + i0 + jj];
                float sn = g_sin[p * 64 + i0 + jj];
                y1[jj] = x1 * c - x2 * sn;
                y2[jj] = x2 * c + x1 * sn;
            }
            uint32_t h1[4], l1[4], h2[4], l2[4];
            #pragma unroll
            for (int jj = 0; jj < 4; jj++) {
                h1[jj] = pack_f16_split(y1[2*jj], y1[2*jj+1], l1[jj]);
                h2[jj] = pack_f16_split(y2[2*jj], y2[2*jj+1], l2[jj]);
            }
            size_t dbase;
            if (mode == 1) {
                int qt = s >> 7, sbw = (s >> 3) & 15;
                dbase = ((((size_t)(b * H_ + hh) * (S_/128) + qt) * 16 + sbw) * 16);
            } else {
                int kt = s >> 6, sbw = (s >> 3) & 7;
                dbase = ((((size_t)(b * KVH_ + hh) * (S_/64) + kt) * 8 + sbw) * 16);
            }
            int rr = s & 7;
            size_t o1 = (dbase + kbl)     * 64 + (size_t)rr * 8;
            size_t o2 = (dbase + kbl + 8) * 64 + (size_t)rr * 8;
            *(uint4*)(oHi + o1) = make_uint4(h1[0], h1[1], h1[2], h1[3]);
            *(uint4*)(oLo + o1) = make_uint4(l1[0], l1[1], l1[2], l1[3]);
            *(uint4*)(oHi + o2) = make_uint4(h2[0], h2[1], h2[2], h2[3]);
            *(uint4*)(oLo + o2) = make_uint4(l2[0], l2[1], l2[2], l2[3]);
        }
    } else {
        // V: hi-only (PV is 1-term)
        const int token0 = blockIdx.y * 128;
        const int b = token0 >> 11;
        const int sbase0 = token0 & (S_ - 1);
        #pragma unroll
        for (int j = 0; j < 8; j++) {
            int idx = tid + j * 256;
            int dr  = idx & 7;
            int sbw = (idx >> 3) & 7;
            int db  = (idx >> 6) & 15;
            int ktl = idx >> 10;
            int d = db * 8 + dr;
            int sl = ktl * 64 + sbw * 8;
            uint32_t hw[4];
            #pragma unroll
            for (int jj = 0; jj < 4; jj++) {
                float x0 = st[(sl + 2*jj)     * 132 + d];
                float x1 = st[(sl + 2*jj + 1) * 132 + d];
                hw[jj] = pack_f16_pair(x0, x1);
            }
            int s = sbase0 + sl;
            int kt = s >> 6;
            size_t off = (((((size_t)(b * KVH_ + hh) * (S_/64) + kt) * 16 + db) * 8 + sbw) * 64)
                       + (size_t)dr * 8;
            *(uint4*)(g_vb_hi + off) = make_uint4(hw[0], hw[1], hw[2], hw[3]);
        }
    }
}

// ---------------- O-projection kernel ----------------
__global__ __launch_bounds__(256, 2)
void o_gemm_kernel(float* __restrict__ C) {
    extern __shared__ char smc[];
    const uint32_t sbase = smem_u32(smc);
    const int tid  = threadIdx.x;
    const int warp = tid >> 5, lane = tid & 31;
    const int mb0  = blockIdx.y * 16;
    const int nb0  = blockIdx.x * 16;

    GEMM_MAINLOOP(g_attn_hi, g_wo_hi, g_wo_lo, HD_)
    }}

    const int mrow = mb0 * 8 + (warp >> 2) * 64;
    const int ncol = nb0 * 8 + (warp & 3) * 32;
    const int gg = lane >> 2, qq = lane & 3;
    #pragma unroll
    for (int t = 0; t < 4; t++) {
        #pragma unroll
        for (int u = 0; u < 4; u++) {
            int row = mrow + t * 16 + gg;
            int col = ncol + u * 8 + qq * 2;
            *(float2*)(C + (size_t)row * E_ + col)       = make_float2(acc[t][u][0], acc[t][u][1]);
            *(float2*)(C + (size_t)(row + 8) * E_ + col) = make_float2(acc[t][u][2], acc[t][u][3]);
        }
    }
}

// ---------------- flash attention: FA2 repack, Q in regs, PV 1-term ----------------
// smem: Q hi 32K | Q lo 32K | KV stage0 48K | KV stage1 48K = 160K
// KV stage layout: K hi @0, K lo @16K, V hi @32K
#define FQHI   0u
#define FQLO   32768u
#define FKV0   65536u
#define FKVSZ  49152u
#define FTOT   163840u

__global__ __launch_bounds__(256, 1)
void flash_mma_kernel() {
    extern __shared__ char fs[];
    const uint32_t sb = smem_u32(fs);

    const int tid  = threadIdx.x;
    const int warp = tid >> 5, lane = tid & 31;
    const int qt = (S_/128 - 1) - blockIdx.x;
    const int h = blockIdx.y, b = blockIdx.z;
    const int q0 = qt * 128;
    const int kvh = h >> 2;
    const float scale2 = 0.08838834764831845f * 1.4426950408889634f;

    const int selAm = (lane >> 3) & 1;
    const int selAk = (lane >> 3) >> 1;
    const int selBn = (lane >> 4) & 1;
    const int selBk = (lane >> 3) & 1;
    const int rrow  = lane & 7;
    const int gr = lane >> 2, qq = lane & 3;
    const int wm = warp * 16;

    const size_t kvbase = (size_t)(b*KVH_ + kvh) * (S_/64);
    auto prefetch_kv = [&](int kt, int st) {
        size_t tb = (kvbase + kt) * 16384u;   // byte offset of each 16KB tile
        uint32_t sbuf = sb + FKV0 + (uint32_t)st * FKVSZ;
        #pragma unroll
        for (int j = 0; j < 4; j++) {
            uint32_t u = (uint32_t)(tid + j * 256) * 16u;
            cp16(sbuf + u,           (const char*)g_kb_hi + tb + u);
            cp16(sbuf + 16384u + u,  (const char*)g_kb_lo + tb + u);
            cp16(sbuf + 32768u + u,  (const char*)g_vb_hi + tb + u);
        }
    };

    {
        const char* qh = (const char*)(g_qb_hi + (((size_t)(b*H_ + h) * (S_/128) + qt) << 14));
        const char* ql = (const char*)(g_qb_lo + (((size_t)(b*H_ + h) * (S_/128) + qt) << 14));
        #pragma unroll
        for (int j = 0; j < 8; j++) {
            uint32_t u = (uint32_t)(tid + j * 256) * 16u;
            cp16(sb + FQHI + u, qh + u);
            cp16(sb + FQLO + u, ql + u);
        }
        prefetch_kv(0, 0);
        asm volatile("cp.async.commit_group;" ::: "memory");
    }

    asm volatile("cp.async.wait_group 0;" ::: "memory");
    __syncthreads();

    uint32_t qfh[8][4], qfl[8][4];
    #pragma unroll
    for (int ks = 0; ks < 8; ks++) {
        int mbb = 2*warp + selAm;
        int kbb = 2*ks + selAk;
        uint32_t off = (uint32_t)((mbb * 16 + kbb) * 128 + rrow * 16);
        ldsm_x4(qfh[ks], sb + FQHI + off);
        ldsm_x4(qfl[ks], sb + FQLO + off);
    }

    float m1 = -1e30f, m2 = -1e30f, l1 = 0.f, l2 = 0.f;
    float acc[16][4];
    #pragma unroll
    for (int u = 0; u < 16; u++)
        #pragma unroll
        for (int j = 0; j < 4; j++) acc[u][j] = 0.f;

    const int r1 = wm + gr;
    const int r2 = r1 + 8;

    const int NK = 2 * qt + 2;
    for (int kt = 0; kt < NK; kt++) {
        const int k0 = kt * 64;
        if (kt > 0) {
            asm volatile("cp.async.wait_group 0;" ::: "memory");
            __syncthreads();
        }
        const uint32_t kvs = sb + FKV0 + (uint32_t)(kt & 1) * FKVSZ;

        if (kt + 1 < NK) {
            prefetch_kv(kt + 1, (kt + 1) & 1);
            asm volatile("cp.async.commit_group;" ::: "memory");
        }

        // ---- S = Q @ K^T (3-term), Q from registers ----
        float sacc[8][4];
        #pragma unroll
        for (int u = 0; u < 8; u++)
            #pragma unroll
            for (int j = 0; j < 4; j++) sacc[u][j] = 0.f;

        #pragma unroll
        for (int ks = 0; ks < 8; ks++) {
            uint32_t khi[4][4], klo[4][4];
            #pragma unroll
            for (int j = 0; j < 4; j++) {
                int nbb = 2*j + selBn;
                int kbb = 2*ks + selBk;
                uint32_t off = (uint32_t)((nbb * 16 + kbb) * 128 + rrow * 16);
                ldsm_x4(khi[j], kvs + off);
                ldsm_x4(klo[j], kvs + 16384u + off);
            }
            #pragma unroll
            for (int u = 0; u < 8; u++) {
                const uint32_t* kh = &khi[u >> 1][(u & 1) * 2];
                const uint32_t* kl = &klo[u >> 1][(u & 1) * 2];
                mma_f16(sacc[u], qfh[ks], kh);
                mma_f16(sacc[u], qfl[ks], kh);
                mma_f16(sacc[u], qfh[ks], kl);
            }
        }

        // ---- in-register softmax (base-2 domain) ----
        const bool needmask = (kt >= 2 * qt);
        float tm1 = -1e30f, tm2 = -1e30f;
        #pragma unroll
        for (int u = 0; u < 8; u++) {
            int c0 = u * 8 + qq * 2;
            float s0 = sacc[u][0] * scale2;
            float s1 = sacc[u][1] * scale2;
            float s2 = sacc[u][2] * scale2;
            float s3 = sacc[u][3] * scale2;
            if (needmask) {
                if (k0 + c0     > q0 + r1) s0 = -1e30f;
                if (k0 + c0 + 1 > q0 + r1) s1 = -1e30f;
                if (k0 + c0     > q0 + r2) s2 = -1e30f;
                if (k0 + c0 + 1 > q0 + r2) s3 = -1e30f;
            }
            sacc[u][0] = s0; sacc[u][1] = s1;
            sacc[u][2] = s2; sacc[u][3] = s3;
            tm1 = fmaxf(tm1, fmaxf(s0, s1));
            tm2 = fmaxf(tm2, fmaxf(s2, s3));
        }
        tm1 = fmaxf(tm1, __shfl_xor_sync(0xffffffffu, tm1, 1));
        tm1 = fmaxf(tm1, __shfl_xor_sync(0xffffffffu, tm1, 2));
        tm2 = fmaxf(tm2, __shfl_xor_sync(0xffffffffu, tm2, 1));
        tm2 = fmaxf(tm2, __shfl_xor_sync(0xffffffffu, tm2, 2));
        float mn1 = fmaxf(m1, tm1), mn2 = fmaxf(m2, tm2);
        float a1 = exp2f(m1 - mn1), a2 = exp2f(m2 - mn2);
        m1 = mn1; m2 = mn2;

        uint32_t pf[4][4];
        float ts1 = 0.f, ts2 = 0.f;
        #pragma unroll
        for (int kk = 0; kk < 4; kk++) {
            #pragma unroll
            for (int half = 0; half < 2; half++) {
                int u = 2*kk + half;
                float e0 = exp2f(sacc[u][0] - m1);
                float e1 = exp2f(sacc[u][1] - m1);
                float e2 = exp2f(sacc[u][2] - m2);
                float e3 = exp2f(sacc[u][3] - m2);
                ts1 += e0 + e1;
                ts2 += e2 + e3;
                pf[kk][half*2]     = pack_f16_pair(e0, e1);
                pf[kk][half*2 + 1] = pack_f16_pair(e2, e3);
            }
        }
        ts1 += __shfl_xor_sync(0xffffffffu, ts1, 1);
        ts1 += __shfl_xor_sync(0xffffffffu, ts1, 2);
        ts2 += __shfl_xor_sync(0xffffffffu, ts2, 1);
        ts2 += __shfl_xor_sync(0xffffffffu, ts2, 2);
        l1 = l1 * a1 + ts1;
        l2 = l2 * a2 + ts2;

        #pragma unroll
        for (int u = 0; u < 16; u++) {
            acc[u][0] *= a1; acc[u][1] *= a1;
            acc[u][2] *= a2; acc[u][3] *= a2;
        }

        // ---- O += P @ V (1-term, V hi only), P from registers ----
        #pragma unroll
        for (int ks = 0; ks < 4; ks++) {
            #pragma unroll
            for (int nh = 0; nh < 2; nh++) {
                uint32_t vhi[4][4];
                #pragma unroll
                for (int j = 0; j < 4; j++) {
                    int nbb = nh*8 + 2*j + selBn;
                    int kbb = 2*ks + selBk;
                    uint32_t off = (uint32_t)((nbb * 8 + kbb) * 128 + rrow * 16);
                    ldsm_x4(vhi[j], kvs + 32768u + off);
                }
                #pragma unroll
                for (int uu = 0; uu < 8; uu++) {
                    int u = nh*8 + uu;
                    const uint32_t* vh = &vhi[uu >> 1][(uu & 1) * 2];
                    mma_f16(acc[u], pf[ks], vh);
                }
            }
        }
    }

    // ---- epilogue: normalize + write blocked fp16 hi ----
    {
        const int KB = HD_ >> 3;
        float inv1 = 1.f / l1;
        float inv2 = 1.f / l2;
        int grow1 = b*S_ + q0 + r1;
        int grow2 = grow1 + 8;
        #pragma unroll
        for (int u = 0; u < 16; u++) {
            int col = h * D_ + u*8 + qq * 2;
            int kb = col >> 3, cw = col & 7;
            size_t o1 = (((size_t)(grow1 >> 3) * KB + kb) << 6) + (size_t)(grow1 & 7) * 8 + cw;
            size_t o2 = (((size_t)(grow2 >> 3) * KB + kb) << 6) + (size_t)(grow2 & 7) * 8 + cw;
            *(uint32_t*)(g_attn_hi + o1) = pack_f16_pair(acc[u][0]*inv1, acc[u][1]*inv1);
            *(uint32_t*)(g_attn_hi + o2) = pack_f16_pair(acc[u][2]*inv2, acc[u][3]*inv2);
        }
    }
}

// ---------------- launch ----------------
extern "C" void kernel_launch(void* const* d_in, const int* in_sizes, int n_in,
                              void* d_out, int out_size) {
    const float* hidden = (const float*)d_in[0];
    const int*   pos    = (const int*)  d_in[2];
    const float* Wq     = (const float*)d_in[3];
    const float* bq     = (const float*)d_in[4];
    const float* Wk     = (const float*)d_in[5];
    const float* bk     = (const float*)d_in[6];
    const float* Wv     = (const float*)d_in[7];
    const float* bv     = (const float*)d_in[8];
    const float* Wo     = (const float*)d_in[9];
    float* out = (float*)d_out;

    const size_t gsmem = 98304;
    cudaFuncSetAttribute(qkv_gemm_kernel, cudaFuncAttributeMaxDynamicSharedMemorySize, (int)gsmem);
    cudaFuncSetAttribute(o_gemm_kernel,   cudaFuncAttributeMaxDynamicSharedMemorySize, (int)gsmem);
    cudaFuncSetAttribute(flash_mma_kernel, cudaFuncAttributeMaxDynamicSharedMemorySize, (int)FTOT);

    prep_all_kernel<<<PREP_TOTAL, 256>>>(hidden, Wq, Wk, Wv, Wo);
    qkv_gemm_kernel<<<dim3(48, M_/128), 256, gsmem>>>(bq, bk, bv, pos);
    flash_mma_kernel<<<dim3(S_/128, H_, B_), 256, FTOT>>>();
    o_gemm_kernel<<<dim3(E_/128, M_/128), 256, gsmem>>>(out);
}